// round 6
// baseline (speedup 1.0000x reference)
#include <cuda_runtime.h>
#include <cuda_bf16.h>
#include <math.h>
#include <stdint.h>

#define NHEAD 16
#define HS    64
#define CEMB  1024
#define BB    4
#define TT    2048
#define MTOT  (BB*TT)          // 8192

// ---------------- device scratch (module-load allocated) -------------------
__device__ __align__(16) float g_q[(size_t)BB*NHEAD*TT*HS];
__device__ __align__(16) float g_att[(size_t)MTOT*CEMB];
__device__ __align__(16) float g_xr[(size_t)MTOT*CEMB];        // tf32-rounded x
__device__ __align__(16) float g_wr[(size_t)4*CEMB*CEMB];      // rounded Wq,Wk,Wv,Wp
__device__ __align__(16) float2 g_rope[(size_t)TT*32];          // (cos,sin)
__device__ __align__(16) __nv_bfloat16 g_khi[(size_t)BB*NHEAD*TT*HS];
__device__ __align__(16) __nv_bfloat16 g_klo[(size_t)BB*NHEAD*TT*HS];
__device__ __align__(16) __nv_bfloat16 g_vthi[(size_t)BB*NHEAD*TT*HS]; // [bh][d][t]
__device__ __align__(16) __nv_bfloat16 g_vtlo[(size_t)BB*NHEAD*TT*HS];

// ---------------- helpers ---------------------------------------------------
__device__ __forceinline__ float tf32r(float x) {
    unsigned u;
    asm("cvt.rna.tf32.f32 %0, %1;" : "=r"(u) : "f"(x));
    return __uint_as_float(u);
}

__device__ __forceinline__ void mma_tf32(float c[4], const unsigned a[4],
                                         const unsigned b[2]) {
    asm volatile(
        "mma.sync.aligned.m16n8k8.row.col.f32.tf32.tf32.f32 "
        "{%0,%1,%2,%3}, {%4,%5,%6,%7}, {%8,%9}, {%0,%1,%2,%3};\n"
        : "+f"(c[0]), "+f"(c[1]), "+f"(c[2]), "+f"(c[3])
        : "r"(a[0]), "r"(a[1]), "r"(a[2]), "r"(a[3]),
          "r"(b[0]), "r"(b[1]));
}

__device__ __forceinline__ void mma_bf16(float c[4], const unsigned a[4],
                                         unsigned b0, unsigned b1) {
    asm volatile(
        "mma.sync.aligned.m16n8k16.row.col.f32.bf16.bf16.f32 "
        "{%0,%1,%2,%3}, {%4,%5,%6,%7}, {%8,%9}, {%0,%1,%2,%3};\n"
        : "+f"(c[0]), "+f"(c[1]), "+f"(c[2]), "+f"(c[3])
        : "r"(a[0]), "r"(a[1]), "r"(a[2]), "r"(a[3]),
          "r"(b0), "r"(b1));
}

__device__ __forceinline__ unsigned pk(__nv_bfloat16 x, __nv_bfloat16 y) {
    unsigned short a = *(unsigned short*)&x, b = *(unsigned short*)&y;
    return (unsigned)a | ((unsigned)b << 16);
}
__device__ __forceinline__ void split2(float a, float b,
                                       unsigned &hi, unsigned &lo) {
    __nv_bfloat16 ah = __float2bfloat16(a);
    __nv_bfloat16 bh = __float2bfloat16(b);
    __nv_bfloat16 al = __float2bfloat16(a - __bfloat162float(ah));
    __nv_bfloat16 bl = __float2bfloat16(b - __bfloat162float(bh));
    hi = pk(ah, bh);
    lo = pk(al, bl);
}

__device__ __forceinline__ uint32_t smem_u32(const void* p) {
    uint32_t a;
    asm("{ .reg .u64 t; cvta.to.shared.u64 t, %1; cvt.u32.u64 %0, t; }"
        : "=r"(a) : "l"(p));
    return a;
}
__device__ __forceinline__ void cpa16(uint32_t dst, const void* src) {
    asm volatile("cp.async.cg.shared.global [%0], [%1], 16;\n"
                 :: "r"(dst), "l"(src));
}
#define CP_COMMIT() asm volatile("cp.async.commit_group;\n" ::: "memory")
#define CP_WAIT(n)  asm volatile("cp.async.wait_group %0;\n" :: "n"(n) : "memory")

// ---------------------------------------------------------------------------
// Prep kernels: tf32-round x / W, RoPE table
// ---------------------------------------------------------------------------
__global__ void __launch_bounds__(256) prep_round_x(const float* __restrict__ x)
{
    int i = blockIdx.x * 256 + threadIdx.x;
    float4 v = ((const float4*)x)[i];
    ((float4*)g_xr)[i] = make_float4(tf32r(v.x), tf32r(v.y),
                                     tf32r(v.z), tf32r(v.w));
}

__global__ void __launch_bounds__(256) prep_round_w(
    const float* __restrict__ Wq, const float* __restrict__ Wk,
    const float* __restrict__ Wv, const float* __restrict__ Wp)
{
    const int z = blockIdx.y;
    const float* W = (z == 0) ? Wq : ((z == 1) ? Wk : ((z == 2) ? Wv : Wp));
    int i = blockIdx.x * 256 + threadIdx.x;
    float4 v = ((const float4*)W)[i];
    ((float4*)(g_wr + (size_t)z * CEMB * CEMB))[i] =
        make_float4(tf32r(v.x), tf32r(v.y), tf32r(v.z), tf32r(v.w));
}

__global__ void __launch_bounds__(256) prep_rope()
{
    int idx = blockIdx.x * 256 + threadIdx.x;     // 0 .. 65535
    int t = idx >> 5, p = idx & 31;
    const float L2T = 13.287712379549449f / 64.0f;
    float inv = exp2f(-(float)(2 * p) * L2T);
    float sv, cv;
    sincosf((float)t * inv, &sv, &cv);
    g_rope[idx] = make_float2(cv, sv);
}

// ---------------------------------------------------------------------------
// tf32 MMA GEMM, cp.async 3-stage. 128x128 tile, BK=16, 256 threads,
// 8 warps (4x2, 32x64 per warp).
// Smem: A [m][k] stride 20 floats (3 stages), B [k][n] stride 132 (3 stages).
// ---------------------------------------------------------------------------
#define ASTR 20
#define BSTR 132
#define ABYTES (128 * ASTR * 4)        // 10240
#define BBYTES (16 * BSTR * 4)         // 8448
#define BOFF   (3 * ABYTES)            // 30720
#define GM_SMEM (3 * ABYTES + 3 * BBYTES)  // 56064

// Full mainloop producing acc[2][8][4]; A = rows of Ag, B = rows of Bg.
__device__ __forceinline__ void gemm_main(
    const float* __restrict__ Ag, const float* __restrict__ Bg,
    int m0, int n0, char* smp, float acc[2][8][4])
{
    const int tid  = threadIdx.x;
    const int warp = tid >> 5;
    const int lane = tid & 31;
    const int wm = warp >> 1;
    const int wn = warp & 1;
    const uint32_t sb = smem_u32(smp);

#pragma unroll
    for (int mt = 0; mt < 2; mt++)
#pragma unroll
        for (int nt = 0; nt < 8; nt++)
#pragma unroll
            for (int r = 0; r < 4; r++) acc[mt][nt][r] = 0.0f;

    // copy slot geometry (2 16B segs per thread for A and for B)
    const int ar0 = (tid * 2) >> 2, ak0 = ((tid * 2) & 3) * 4;
    const int ar1 = (tid * 2 + 1) >> 2, ak1 = ((tid * 2 + 1) & 3) * 4;
    const int br0 = (tid * 2) >> 5, bn0 = ((tid * 2) & 31) * 4;
    const int br1 = (tid * 2 + 1) >> 5, bn1 = ((tid * 2 + 1) & 31) * 4;

#define GM_ISSUE(CK, S) do {                                                   \
    const int kb = (CK) * 16;                                                  \
    uint32_t ab = sb + (S) * ABYTES;                                           \
    uint32_t bb = sb + BOFF + (S) * BBYTES;                                    \
    cpa16(ab + (ar0 * ASTR + ak0) * 4,                                         \
          Ag + (size_t)(m0 + ar0) * CEMB + kb + ak0);                          \
    cpa16(ab + (ar1 * ASTR + ak1) * 4,                                         \
          Ag + (size_t)(m0 + ar1) * CEMB + kb + ak1);                          \
    cpa16(bb + (br0 * BSTR + bn0) * 4,                                         \
          Bg + (size_t)(kb + br0) * CEMB + n0 + bn0);                          \
    cpa16(bb + (br1 * BSTR + bn1) * 4,                                         \
          Bg + (size_t)(kb + br1) * CEMB + n0 + bn1);                          \
    CP_COMMIT();                                                               \
} while (0)

    GM_ISSUE(0, 0);
    GM_ISSUE(1, 1);

    const int mrow = wm * 32 + (lane >> 2);
    const int ncol = wn * 64 + (lane >> 2);

    for (int ck = 0; ck < 64; ck++) {
        if (ck + 2 < 64) {
            GM_ISSUE(ck + 2, (ck + 2) % 3);
            CP_WAIT(2);
        } else if (ck + 1 < 64) {
            CP_WAIT(1);
        } else {
            CP_WAIT(0);
        }
        __syncthreads();

        const int s = ck % 3;
        const float* As = (const float*)(smp + s * ABYTES);
        const float* Bs = (const float*)(smp + BOFF + s * BBYTES);

#pragma unroll
        for (int ks = 0; ks < 16; ks += 8) {
            const int kr = ks + (lane & 3);
            unsigned af[2][4], bf[8][2];
#pragma unroll
            for (int mt = 0; mt < 2; mt++) {
                af[mt][0] = __float_as_uint(As[(mrow + mt * 16    ) * ASTR + kr]);
                af[mt][1] = __float_as_uint(As[(mrow + mt * 16 + 8) * ASTR + kr]);
                af[mt][2] = __float_as_uint(As[(mrow + mt * 16    ) * ASTR + kr + 4]);
                af[mt][3] = __float_as_uint(As[(mrow + mt * 16 + 8) * ASTR + kr + 4]);
            }
#pragma unroll
            for (int nt = 0; nt < 8; nt++) {
                bf[nt][0] = __float_as_uint(Bs[kr * BSTR + ncol + nt * 8]);
                bf[nt][1] = __float_as_uint(Bs[(kr + 4) * BSTR + ncol + nt * 8]);
            }
#pragma unroll
            for (int mt = 0; mt < 2; mt++)
#pragma unroll
                for (int nt = 0; nt < 8; nt++)
                    mma_tf32(acc[mt][nt], af[mt], bf[nt]);
        }
        __syncthreads();
    }
#undef GM_ISSUE
}

// ---------------------------------------------------------------------------
// QKV: mode 0=Q(+RoPE)->fp32 g_q, 1=K(+RoPE)->bf16 planes, 2=V->trans planes
// ---------------------------------------------------------------------------
__global__ void __launch_bounds__(256) qkv_gemm()
{
    extern __shared__ char smp[];
    const int mode = blockIdx.z;
    const int m0 = blockIdx.y * 128;
    const int n0 = blockIdx.x * 128;

    float acc[2][8][4];
    gemm_main(g_xr, g_wr + (size_t)mode * CEMB * CEMB, m0, n0, smp, acc);

    const int warp = threadIdx.x >> 5;
    const int lane = threadIdx.x & 31;
    const int wm = warp >> 1;
    const int wn = warp & 1;

#pragma unroll
    for (int mt = 0; mt < 2; mt++) {
        const int row_base = m0 + wm * 32 + mt * 16 + (lane >> 2);
#pragma unroll
        for (int nt = 0; nt < 8; nt++) {
            const int col = n0 + wn * 64 + nt * 8 + (lane & 3) * 2;
            const int h = col >> 6;
            const int d = col & 63;
#pragma unroll
            for (int half = 0; half < 2; half++) {
                const int row = row_base + half * 8;
                const int b = row >> 11;
                const int t = row & 2047;
                float x0 = acc[mt][nt][half * 2];
                float x1 = acc[mt][nt][half * 2 + 1];
                float o0 = x0, o1 = x1;
                if (mode < 2) {
                    float2 cs = g_rope[t * 32 + (d >> 1)];
                    o0 = x0 * cs.x - x1 * cs.y;
                    o1 = x0 * cs.y + x1 * cs.x;
                }
                const int bh = b * NHEAD + h;
                if (mode == 0) {
                    size_t base = ((size_t)bh * TT + t) * HS + d;
                    *(float2*)(g_q + base) = make_float2(o0, o1);
                } else if (mode == 1) {
                    size_t base = ((size_t)bh * TT + t) * HS + d;
                    unsigned hi, lo;
                    split2(o0, o1, hi, lo);
                    *(unsigned*)(g_khi + base) = hi;
                    *(unsigned*)(g_klo + base) = lo;
                } else {
                    size_t tb = ((size_t)bh * HS + d) * TT + t;
                    __nv_bfloat16 h0 = __float2bfloat16(o0);
                    __nv_bfloat16 h1 = __float2bfloat16(o1);
                    g_vthi[tb]      = h0;
                    g_vthi[tb + TT] = h1;
                    g_vtlo[tb]      = __float2bfloat16(o0 - __bfloat162float(h0));
                    g_vtlo[tb + TT] = __float2bfloat16(o1 - __bfloat162float(h1));
                }
            }
        }
    }
}

// ---------------------------------------------------------------------------
// Output projection: g_att (tf32-rounded) @ Wp + bp -> fp32 out
// ---------------------------------------------------------------------------
__global__ void __launch_bounds__(256) proj_gemm(
    const float* __restrict__ bp, float* __restrict__ out)
{
    extern __shared__ char smp[];
    const int m0 = blockIdx.y * 128;
    const int n0 = blockIdx.x * 128;

    float acc[2][8][4];
    gemm_main(g_att, g_wr + (size_t)3 * CEMB * CEMB, m0, n0, smp, acc);

    const int warp = threadIdx.x >> 5;
    const int lane = threadIdx.x & 31;
    const int wm = warp >> 1;
    const int wn = warp & 1;

#pragma unroll
    for (int mt = 0; mt < 2; mt++) {
        const int row_base = m0 + wm * 32 + mt * 16 + (lane >> 2);
#pragma unroll
        for (int nt = 0; nt < 8; nt++) {
            const int col = n0 + wn * 64 + nt * 8 + (lane & 3) * 2;
            const float b0 = bp[col];
            const float b1 = bp[col + 1];
#pragma unroll
            for (int half = 0; half < 2; half++) {
                const int row = row_base + half * 8;
                *(float2*)(out + (size_t)row * CEMB + col) =
                    make_float2(acc[mt][nt][half * 2]     + b0,
                                acc[mt][nt][half * 2 + 1] + b1);
            }
        }
    }
}

// ---------------------------------------------------------------------------
// Flash attention, bf16x3 mma.sync (validated round 4). Writes g_att
// tf32-rounded fp32 (rounding moved here from proj staging).
// ---------------------------------------------------------------------------
#define KVS 72

__global__ void __launch_bounds__(128) flash_bf16()
{
    __shared__ __nv_bfloat16 KhiS[64][KVS];
    __shared__ __nv_bfloat16 KloS[64][KVS];
    __shared__ __nv_bfloat16 VhiS[64][KVS];   // [d][j]
    __shared__ __nv_bfloat16 VloS[64][KVS];

    const int tid  = threadIdx.x;
    const int warp = tid >> 5;
    const int lane = tid & 31;
    const int qt   = gridDim.x - 1 - blockIdx.x;
    const int q0   = qt * 64;
    const int bh   = blockIdx.y;

    const float* Q = g_q + (size_t)bh * TT * HS;
    const __nv_bfloat16* Khi = g_khi + (size_t)bh * TT * HS;
    const __nv_bfloat16* Klo = g_klo + (size_t)bh * TT * HS;
    const __nv_bfloat16* Vhi = g_vthi + (size_t)bh * HS * TT;
    const __nv_bfloat16* Vlo = g_vtlo + (size_t)bh * HS * TT;

    const int lr = lane >> 2;
    const int lc = lane & 3;
    const int lrow = warp * 16 + lr;
    const int grow_a = q0 + lrow;
    const int grow_b = grow_a + 8;

    unsigned qh[4][4], ql[4][4];
#pragma unroll
    for (int ks = 0; ks < 4; ks++) {
        const int kd = ks * 16 + lc * 2;
        const float* qa = Q + (size_t)grow_a * HS;
        const float* qb = Q + (size_t)grow_b * HS;
        float2 v0 = *(const float2*)(qa + kd);
        float2 v1 = *(const float2*)(qb + kd);
        float2 v2 = *(const float2*)(qa + kd + 8);
        float2 v3 = *(const float2*)(qb + kd + 8);
        split2(v0.x * 0.125f, v0.y * 0.125f, qh[ks][0], ql[ks][0]);
        split2(v1.x * 0.125f, v1.y * 0.125f, qh[ks][1], ql[ks][1]);
        split2(v2.x * 0.125f, v2.y * 0.125f, qh[ks][2], ql[ks][2]);
        split2(v3.x * 0.125f, v3.y * 0.125f, qh[ks][3], ql[ks][3]);
    }

    float o[8][4];
#pragma unroll
    for (int nt = 0; nt < 8; nt++)
#pragma unroll
        for (int r = 0; r < 4; r++) o[nt][r] = 0.0f;
    float m_a = -1e30f, m_b = -1e30f, l_a = 0.0f, l_b = 0.0f;

    for (int kt = 0; kt <= qt; kt++) {
        const int k0 = kt * 64;
        __syncthreads();
#pragma unroll
        for (int a = 0; a < 8; a++) {
            int s = a * 128 + tid;
            int j = s >> 4, dq = (s & 15) * 4;
            *(uint2*)&KhiS[j][dq] =
                *(const uint2*)(Khi + (size_t)(k0 + j) * HS + dq);
            *(uint2*)&KloS[j][dq] =
                *(const uint2*)(Klo + (size_t)(k0 + j) * HS + dq);
            *(uint2*)&VhiS[j][dq] =
                *(const uint2*)(Vhi + (size_t)j * TT + k0 + dq);
            *(uint2*)&VloS[j][dq] =
                *(const uint2*)(Vlo + (size_t)j * TT + k0 + dq);
        }
        __syncthreads();

        float p[8][4];
#pragma unroll
        for (int nt = 0; nt < 8; nt++)
#pragma unroll
            for (int r = 0; r < 4; r++) p[nt][r] = 0.0f;

#pragma unroll
        for (int ks = 0; ks < 4; ks++) {
            const int kd = ks * 16 + lc * 2;
#pragma unroll
            for (int nt = 0; nt < 8; nt++) {
                const int j = nt * 8 + lr;
                unsigned bh0 = *(const unsigned*)&KhiS[j][kd];
                unsigned bh1 = *(const unsigned*)&KhiS[j][kd + 8];
                unsigned bl0 = *(const unsigned*)&KloS[j][kd];
                unsigned bl1 = *(const unsigned*)&KloS[j][kd + 8];
                mma_bf16(p[nt], qh[ks], bh0, bh1);
                mma_bf16(p[nt], qh[ks], bl0, bl1);
                mma_bf16(p[nt], ql[ks], bh0, bh1);
            }
        }

        if (kt == qt) {
#pragma unroll
            for (int nt = 0; nt < 8; nt++) {
                const int c = k0 + nt * 8 + lc * 2;
                if (c     > grow_a) p[nt][0] = -1e30f;
                if (c + 1 > grow_a) p[nt][1] = -1e30f;
                if (c     > grow_b) p[nt][2] = -1e30f;
                if (c + 1 > grow_b) p[nt][3] = -1e30f;
            }
        }

        float ma = -1e30f, mb2 = -1e30f;
#pragma unroll
        for (int nt = 0; nt < 8; nt++) {
            ma  = fmaxf(ma,  fmaxf(p[nt][0], p[nt][1]));
            mb2 = fmaxf(mb2, fmaxf(p[nt][2], p[nt][3]));
        }
        ma  = fmaxf(ma,  __shfl_xor_sync(0xffffffffu, ma, 1));
        ma  = fmaxf(ma,  __shfl_xor_sync(0xffffffffu, ma, 2));
        mb2 = fmaxf(mb2, __shfl_xor_sync(0xffffffffu, mb2, 1));
        mb2 = fmaxf(mb2, __shfl_xor_sync(0xffffffffu, mb2, 2));

        const float mna = fmaxf(m_a, ma);
        const float mnb = fmaxf(m_b, mb2);
        const float ca  = __expf(m_a - mna);
        const float cbx = __expf(m_b - mnb);

        float sa = 0.0f, sb = 0.0f;
#pragma unroll
        for (int nt = 0; nt < 8; nt++) {
            p[nt][0] = __expf(p[nt][0] - mna);
            p[nt][1] = __expf(p[nt][1] - mna);
            p[nt][2] = __expf(p[nt][2] - mnb);
            p[nt][3] = __expf(p[nt][3] - mnb);
            sa += p[nt][0] + p[nt][1];
            sb += p[nt][2] + p[nt][3];
        }
        sa += __shfl_xor_sync(0xffffffffu, sa, 1);
        sa += __shfl_xor_sync(0xffffffffu, sa, 2);
        sb += __shfl_xor_sync(0xffffffffu, sb, 1);
        sb += __shfl_xor_sync(0xffffffffu, sb, 2);
        l_a = l_a * ca + sa;   m_a = mna;
        l_b = l_b * cbx + sb;  m_b = mnb;

#pragma unroll
        for (int nt = 0; nt < 8; nt++) {
            o[nt][0] *= ca;  o[nt][1] *= ca;
            o[nt][2] *= cbx; o[nt][3] *= cbx;
        }

        unsigned pah[4][4], pal[4][4];
#pragma unroll
        for (int g = 0; g < 4; g++) {
            split2(p[2*g][0],   p[2*g][1],   pah[g][0], pal[g][0]);
            split2(p[2*g][2],   p[2*g][3],   pah[g][1], pal[g][1]);
            split2(p[2*g+1][0], p[2*g+1][1], pah[g][2], pal[g][2]);
            split2(p[2*g+1][2], p[2*g+1][3], pah[g][3], pal[g][3]);
        }

#pragma unroll
        for (int g = 0; g < 4; g++) {
            const int j0 = g * 16 + lc * 2;
#pragma unroll
            for (int nt = 0; nt < 8; nt++) {
                const int dcol = nt * 8 + lr;
                unsigned bh0 = *(const unsigned*)&VhiS[dcol][j0];
                unsigned bh1 = *(const unsigned*)&VhiS[dcol][j0 + 8];
                unsigned bl0 = *(const unsigned*)&VloS[dcol][j0];
                unsigned bl1 = *(const unsigned*)&VloS[dcol][j0 + 8];
                mma_bf16(o[nt], pah[g], bh0, bh1);
                mma_bf16(o[nt], pah[g], bl0, bl1);
                mma_bf16(o[nt], pal[g], bh0, bh1);
            }
        }
    }

    // epilogue: normalize, tf32-round (for proj), write fp32 att
    const float rla = 1.0f / l_a;
    const float rlb = 1.0f / l_b;
    const int b = bh >> 4;
    const int h = bh & 15;
    float* oa = g_att + ((size_t)b * TT + grow_a) * CEMB + h * HS;
    float* ob = g_att + ((size_t)b * TT + grow_b) * CEMB + h * HS;
#pragma unroll
    for (int nt = 0; nt < 8; nt++) {
        const int col = nt * 8 + lc * 2;
        *(float2*)(oa + col) = make_float2(tf32r(o[nt][0] * rla),
                                           tf32r(o[nt][1] * rla));
        *(float2*)(ob + col) = make_float2(tf32r(o[nt][2] * rlb),
                                           tf32r(o[nt][3] * rlb));
    }
}

// ---------------------------------------------------------------------------
extern "C" void kernel_launch(void* const* d_in, const int* in_sizes, int n_in,
                              void* d_out, int out_size)
{
    (void)in_sizes; (void)n_in; (void)out_size;
    const float* x  = (const float*)d_in[0];
    const float* Wq = (const float*)d_in[1];
    const float* Wk = (const float*)d_in[2];
    const float* Wv = (const float*)d_in[3];
    const float* Wp = (const float*)d_in[4];
    const float* bp = (const float*)d_in[5];
    float* out = (float*)d_out;

    cudaFuncSetAttribute(qkv_gemm,
        cudaFuncAttributeMaxDynamicSharedMemorySize, GM_SMEM);
    cudaFuncSetAttribute(proj_gemm,
        cudaFuncAttributeMaxDynamicSharedMemorySize, GM_SMEM);

    prep_round_x<<<MTOT * CEMB / 4 / 256, 256>>>(x);
    prep_round_w<<<dim3(CEMB * CEMB / 4 / 256, 4), 256>>>(Wq, Wk, Wv, Wp);
    prep_rope<<<TT * 32 / 256, 256>>>();

    qkv_gemm<<<dim3(CEMB / 128, MTOT / 128, 3), 256, GM_SMEM>>>();

    flash_bf16<<<dim3(TT / 64, BB * NHEAD), 128>>>();

    proj_gemm<<<dim3(CEMB / 128, MTOT / 128), 256, GM_SMEM>>>(bp, out);
}

// round 7
// speedup vs baseline: 1.0177x; 1.0177x over previous
#include <cuda_runtime.h>
#include <cuda_bf16.h>
#include <math.h>
#include <stdint.h>

#define NHEAD 16
#define HS    64
#define CEMB  1024
#define BB    4
#define TT    2048
#define MTOT  (BB*TT)          // 8192

// ---------------- device scratch (module-load allocated) -------------------
__device__ __align__(16) float g_q[(size_t)BB*NHEAD*TT*HS];
__device__ __align__(16) float2 g_rope[(size_t)TT*32];
__device__ __align__(16) __nv_bfloat16 g_khi[(size_t)BB*NHEAD*TT*HS];
__device__ __align__(16) __nv_bfloat16 g_klo[(size_t)BB*NHEAD*TT*HS];
__device__ __align__(16) __nv_bfloat16 g_vthi[(size_t)BB*NHEAD*TT*HS]; // [bh][d][t]
__device__ __align__(16) __nv_bfloat16 g_vtlo[(size_t)BB*NHEAD*TT*HS];
__device__ __align__(16) __nv_bfloat16 g_xhi[(size_t)MTOT*CEMB];
__device__ __align__(16) __nv_bfloat16 g_xlo[(size_t)MTOT*CEMB];
__device__ __align__(16) __nv_bfloat16 g_wthi[(size_t)4*CEMB*CEMB];   // [mat][n][k]
__device__ __align__(16) __nv_bfloat16 g_wtlo[(size_t)4*CEMB*CEMB];
__device__ __align__(16) __nv_bfloat16 g_atthi[(size_t)MTOT*CEMB];
__device__ __align__(16) __nv_bfloat16 g_attlo[(size_t)MTOT*CEMB];

// ---------------- helpers ---------------------------------------------------
__device__ __forceinline__ void mma_bf16(float c[4], const unsigned a[4],
                                         unsigned b0, unsigned b1) {
    asm volatile(
        "mma.sync.aligned.m16n8k16.row.col.f32.bf16.bf16.f32 "
        "{%0,%1,%2,%3}, {%4,%5,%6,%7}, {%8,%9}, {%0,%1,%2,%3};\n"
        : "+f"(c[0]), "+f"(c[1]), "+f"(c[2]), "+f"(c[3])
        : "r"(a[0]), "r"(a[1]), "r"(a[2]), "r"(a[3]),
          "r"(b0), "r"(b1));
}

__device__ __forceinline__ void ldsm4(unsigned r[4], uint32_t addr) {
    asm volatile(
        "ldmatrix.sync.aligned.m8n8.x4.shared.b16 {%0,%1,%2,%3}, [%4];"
        : "=r"(r[0]), "=r"(r[1]), "=r"(r[2]), "=r"(r[3]) : "r"(addr));
}

__device__ __forceinline__ unsigned pk(__nv_bfloat16 x, __nv_bfloat16 y) {
    unsigned short a = *(unsigned short*)&x, b = *(unsigned short*)&y;
    return (unsigned)a | ((unsigned)b << 16);
}
__device__ __forceinline__ void split2(float a, float b,
                                       unsigned &hi, unsigned &lo) {
    __nv_bfloat16 ah = __float2bfloat16(a);
    __nv_bfloat16 bh = __float2bfloat16(b);
    __nv_bfloat16 al = __float2bfloat16(a - __bfloat162float(ah));
    __nv_bfloat16 bl = __float2bfloat16(b - __bfloat162float(bh));
    hi = pk(ah, bh);
    lo = pk(al, bl);
}

__device__ __forceinline__ uint32_t smem_u32(const void* p) {
    uint32_t a;
    asm("{ .reg .u64 t; cvta.to.shared.u64 t, %1; cvt.u32.u64 %0, t; }"
        : "=r"(a) : "l"(p));
    return a;
}
__device__ __forceinline__ void cpa16(uint32_t dst, const void* src) {
    asm volatile("cp.async.cg.shared.global [%0], [%1], 16;\n"
                 :: "r"(dst), "l"(src));
}
#define CP_COMMIT() asm volatile("cp.async.commit_group;\n" ::: "memory")
#define CP_WAIT(n)  asm volatile("cp.async.wait_group %0;\n" :: "n"(n) : "memory")

// ---------------------------------------------------------------------------
// Prep: split x into bf16 planes; split+transpose W into [n][k] planes; RoPE.
// ---------------------------------------------------------------------------
__global__ void __launch_bounds__(256) split_x(const float* __restrict__ x)
{
    int i = blockIdx.x * 256 + threadIdx.x;
    float4 v = ((const float4*)x)[i];
    unsigned h0, l0, h1, l1;
    split2(v.x, v.y, h0, l0);
    split2(v.z, v.w, h1, l1);
    ((uint2*)g_xhi)[i] = make_uint2(h0, h1);
    ((uint2*)g_xlo)[i] = make_uint2(l0, l1);
}

__global__ void __launch_bounds__(256) split_transW(
    const float* __restrict__ Wq, const float* __restrict__ Wk,
    const float* __restrict__ Wv, const float* __restrict__ Wp)
{
    __shared__ float tile[32][33];
    const int z = blockIdx.z;
    const float* W = (z == 0) ? Wq : ((z == 1) ? Wk : ((z == 2) ? Wv : Wp));
    __nv_bfloat16* outh = g_wthi + (size_t)z * CEMB * CEMB;
    __nv_bfloat16* outl = g_wtlo + (size_t)z * CEMB * CEMB;

    const int tx = threadIdx.x & 31;
    const int ty = threadIdx.x >> 5;
    const int k0 = blockIdx.y * 32;
    const int nn0 = blockIdx.x * 32;

#pragma unroll
    for (int j = 0; j < 4; j++)
        tile[ty + 8 * j][tx] = W[(size_t)(k0 + ty + 8 * j) * CEMB + nn0 + tx];
    __syncthreads();
#pragma unroll
    for (int j = 0; j < 4; j++) {
        float v = tile[tx][ty + 8 * j];
        __nv_bfloat16 h = __float2bfloat16(v);
        size_t o = (size_t)(nn0 + ty + 8 * j) * CEMB + k0 + tx;
        outh[o] = h;
        outl[o] = __float2bfloat16(v - __bfloat162float(h));
    }
}

__global__ void __launch_bounds__(256) prep_rope()
{
    int idx = blockIdx.x * 256 + threadIdx.x;
    int t = idx >> 5, p = idx & 31;
    const float L2T = 13.287712379549449f / 64.0f;
    float inv = exp2f(-(float)(2 * p) * L2T);
    float sv, cv;
    sincosf((float)t * inv, &sv, &cv);
    g_rope[idx] = make_float2(cv, sv);
}

// ---------------------------------------------------------------------------
// bf16x3 LDSM GEMM: 128x128 tile, BK=32, 2-stage cp.async, 256 threads,
// 8 warps (4x2 of 32x64). Planes [row][k] padded to 40 bf16 (80B) rows.
// Stage layout (bytes): Ahi 0, Alo 10240, Bhi 20480, Blo 30720; stage=40960.
// ---------------------------------------------------------------------------
#define PL_B   10240
#define STG_B  40960
#define GM_SMEM (2 * STG_B)    // 81920

__device__ __forceinline__ void gemm_main_bf16(
    const __nv_bfloat16* __restrict__ Ahg, const __nv_bfloat16* __restrict__ Alg,
    const __nv_bfloat16* __restrict__ Bhg, const __nv_bfloat16* __restrict__ Blg,
    int m0, int n0, char* smp, float acc[2][8][4])
{
    const int tid  = threadIdx.x;
    const int warp = tid >> 5;
    const int lane = tid & 31;
    const int wm = warp >> 1;
    const int wn = warp & 1;
    const uint32_t sb = smem_u32(smp);

#pragma unroll
    for (int mt = 0; mt < 2; mt++)
#pragma unroll
        for (int nt = 0; nt < 8; nt++)
#pragma unroll
            for (int r = 0; r < 4; r++) acc[mt][nt][r] = 0.0f;

    // staging slots: 2048 16B segs / 256 thr = 8 per thread
    const __nv_bfloat16* sp[8];
    uint32_t doff[8];
#pragma unroll
    for (int i = 0; i < 8; i++) {
        int g = i * 256 + tid;
        int pl = g >> 9;             // 0..3
        int r  = (g >> 2) & 127;
        int sg = g & 3;
        const __nv_bfloat16* base =
            (pl == 0) ? Ahg : ((pl == 1) ? Alg : ((pl == 2) ? Bhg : Blg));
        int rbase = (pl < 2) ? m0 : n0;
        sp[i]   = base + (size_t)(rbase + r) * CEMB + sg * 8;
        doff[i] = (uint32_t)(pl * PL_B + r * 80 + sg * 16);
    }

#define GM_ISSUE(CK, S) do {                                  \
    const int kb_ = (CK) * 32;                                \
    uint32_t st_ = sb + (S) * STG_B;                          \
    _Pragma("unroll")                                         \
    for (int i = 0; i < 8; i++)                               \
        cpa16(st_ + doff[i], sp[i] + kb_);                    \
    CP_COMMIT();                                              \
} while (0)

    GM_ISSUE(0, 0);

    // ldmatrix lane addressing
    const int a_row = lane & 15;
    const int a_kh  = lane >> 4;
    const uint32_t aoff = (uint32_t)((wm * 32 + a_row) * 80 + a_kh * 16);
    const int b_n  = ((lane >> 4) << 3) + (lane & 7);
    const int b_kh = (lane >> 3) & 1;
    const uint32_t boff = (uint32_t)(2 * PL_B + (wn * 64 + b_n) * 80 + b_kh * 16);

    for (int ck = 0; ck < 32; ck++) {
        if (ck + 1 < 32) {
            GM_ISSUE(ck + 1, (ck + 1) & 1);
            CP_WAIT(1);
        } else {
            CP_WAIT(0);
        }
        __syncthreads();

        const uint32_t st = sb + (ck & 1) * STG_B;
#pragma unroll
        for (int kk = 0; kk < 2; kk++) {
            unsigned Ah[2][4], Al[2][4];
#pragma unroll
            for (int mt = 0; mt < 2; mt++) {
                ldsm4(Ah[mt], st + aoff + mt * 1280 + kk * 32);
                ldsm4(Al[mt], st + PL_B + aoff + mt * 1280 + kk * 32);
            }
#pragma unroll
            for (int ntp = 0; ntp < 4; ntp++) {
                unsigned Bh[4], Bl[4];
                ldsm4(Bh, st + boff + ntp * 1280 + kk * 32);
                ldsm4(Bl, st + PL_B + boff + ntp * 1280 + kk * 32);
#pragma unroll
                for (int mt = 0; mt < 2; mt++) {
                    mma_bf16(acc[mt][ntp * 2 + 0], Ah[mt], Bh[0], Bh[1]);
                    mma_bf16(acc[mt][ntp * 2 + 0], Ah[mt], Bl[0], Bl[1]);
                    mma_bf16(acc[mt][ntp * 2 + 0], Al[mt], Bh[0], Bh[1]);
                    mma_bf16(acc[mt][ntp * 2 + 1], Ah[mt], Bh[2], Bh[3]);
                    mma_bf16(acc[mt][ntp * 2 + 1], Ah[mt], Bl[2], Bl[3]);
                    mma_bf16(acc[mt][ntp * 2 + 1], Al[mt], Bh[2], Bh[3]);
                }
            }
        }
        __syncthreads();
    }
#undef GM_ISSUE
}

// ---------------------------------------------------------------------------
// QKV: mode 0=Q(+RoPE)->fp32 g_q, 1=K(+RoPE)->bf16 planes, 2=V->trans planes
// ---------------------------------------------------------------------------
__global__ void __launch_bounds__(256, 2) qkv_gemm()
{
    extern __shared__ char smp[];
    const int mode = blockIdx.z;
    const int m0 = blockIdx.y * 128;
    const int n0 = blockIdx.x * 128;

    float acc[2][8][4];
    gemm_main_bf16(g_xhi, g_xlo,
                   g_wthi + (size_t)mode * CEMB * CEMB,
                   g_wtlo + (size_t)mode * CEMB * CEMB,
                   m0, n0, smp, acc);

    const int warp = threadIdx.x >> 5;
    const int lane = threadIdx.x & 31;
    const int wm = warp >> 1;
    const int wn = warp & 1;

#pragma unroll
    for (int mt = 0; mt < 2; mt++) {
        const int row_base = m0 + wm * 32 + mt * 16 + (lane >> 2);
#pragma unroll
        for (int nt = 0; nt < 8; nt++) {
            const int col = n0 + wn * 64 + nt * 8 + (lane & 3) * 2;
            const int h = col >> 6;
            const int d = col & 63;
#pragma unroll
            for (int half = 0; half < 2; half++) {
                const int row = row_base + half * 8;
                const int b = row >> 11;
                const int t = row & 2047;
                float x0 = acc[mt][nt][half * 2];
                float x1 = acc[mt][nt][half * 2 + 1];
                float o0 = x0, o1 = x1;
                if (mode < 2) {
                    float2 cs = g_rope[t * 32 + (d >> 1)];
                    o0 = x0 * cs.x - x1 * cs.y;
                    o1 = x0 * cs.y + x1 * cs.x;
                }
                const int bh = b * NHEAD + h;
                if (mode == 0) {
                    size_t base = ((size_t)bh * TT + t) * HS + d;
                    *(float2*)(g_q + base) = make_float2(o0, o1);
                } else if (mode == 1) {
                    size_t base = ((size_t)bh * TT + t) * HS + d;
                    unsigned hi, lo;
                    split2(o0, o1, hi, lo);
                    *(unsigned*)(g_khi + base) = hi;
                    *(unsigned*)(g_klo + base) = lo;
                } else {
                    size_t tb = ((size_t)bh * HS + d) * TT + t;
                    __nv_bfloat16 h0 = __float2bfloat16(o0);
                    __nv_bfloat16 h1 = __float2bfloat16(o1);
                    g_vthi[tb]      = h0;
                    g_vthi[tb + TT] = h1;
                    g_vtlo[tb]      = __float2bfloat16(o0 - __bfloat162float(h0));
                    g_vtlo[tb + TT] = __float2bfloat16(o1 - __bfloat162float(h1));
                }
            }
        }
    }
}

// ---------------------------------------------------------------------------
// Output projection: att planes @ WpT planes + bias -> fp32 out
// ---------------------------------------------------------------------------
__global__ void __launch_bounds__(256, 2) proj_gemm(
    const float* __restrict__ bp, float* __restrict__ out)
{
    extern __shared__ char smp[];
    const int m0 = blockIdx.y * 128;
    const int n0 = blockIdx.x * 128;

    float acc[2][8][4];
    gemm_main_bf16(g_atthi, g_attlo,
                   g_wthi + (size_t)3 * CEMB * CEMB,
                   g_wtlo + (size_t)3 * CEMB * CEMB,
                   m0, n0, smp, acc);

    const int warp = threadIdx.x >> 5;
    const int lane = threadIdx.x & 31;
    const int wm = warp >> 1;
    const int wn = warp & 1;

#pragma unroll
    for (int mt = 0; mt < 2; mt++) {
        const int row_base = m0 + wm * 32 + mt * 16 + (lane >> 2);
#pragma unroll
        for (int nt = 0; nt < 8; nt++) {
            const int col = n0 + wn * 64 + nt * 8 + (lane & 3) * 2;
            const float b0 = bp[col];
            const float b1 = bp[col + 1];
#pragma unroll
            for (int half = 0; half < 2; half++) {
                const int row = row_base + half * 8;
                *(float2*)(out + (size_t)row * CEMB + col) =
                    make_float2(acc[mt][nt][half * 2]     + b0,
                                acc[mt][nt][half * 2 + 1] + b1);
            }
        }
    }
}

// ---------------------------------------------------------------------------
// Flash attention, bf16x3 mma.sync (validated round 4). Writes att planes.
// ---------------------------------------------------------------------------
#define KVS 72

__global__ void __launch_bounds__(128) flash_bf16()
{
    __shared__ __nv_bfloat16 KhiS[64][KVS];
    __shared__ __nv_bfloat16 KloS[64][KVS];
    __shared__ __nv_bfloat16 VhiS[64][KVS];   // [d][j]
    __shared__ __nv_bfloat16 VloS[64][KVS];

    const int tid  = threadIdx.x;
    const int warp = tid >> 5;
    const int lane = tid & 31;
    const int qt   = gridDim.x - 1 - blockIdx.x;
    const int q0   = qt * 64;
    const int bh   = blockIdx.y;

    const float* Q = g_q + (size_t)bh * TT * HS;
    const __nv_bfloat16* Khi = g_khi + (size_t)bh * TT * HS;
    const __nv_bfloat16* Klo = g_klo + (size_t)bh * TT * HS;
    const __nv_bfloat16* Vhi = g_vthi + (size_t)bh * HS * TT;
    const __nv_bfloat16* Vlo = g_vtlo + (size_t)bh * HS * TT;

    const int lr = lane >> 2;
    const int lc = lane & 3;
    const int lrow = warp * 16 + lr;
    const int grow_a = q0 + lrow;
    const int grow_b = grow_a + 8;

    unsigned qh[4][4], ql[4][4];
#pragma unroll
    for (int ks = 0; ks < 4; ks++) {
        const int kd = ks * 16 + lc * 2;
        const float* qa = Q + (size_t)grow_a * HS;
        const float* qb = Q + (size_t)grow_b * HS;
        float2 v0 = *(const float2*)(qa + kd);
        float2 v1 = *(const float2*)(qb + kd);
        float2 v2 = *(const float2*)(qa + kd + 8);
        float2 v3 = *(const float2*)(qb + kd + 8);
        split2(v0.x * 0.125f, v0.y * 0.125f, qh[ks][0], ql[ks][0]);
        split2(v1.x * 0.125f, v1.y * 0.125f, qh[ks][1], ql[ks][1]);
        split2(v2.x * 0.125f, v2.y * 0.125f, qh[ks][2], ql[ks][2]);
        split2(v3.x * 0.125f, v3.y * 0.125f, qh[ks][3], ql[ks][3]);
    }

    float o[8][4];
#pragma unroll
    for (int nt = 0; nt < 8; nt++)
#pragma unroll
        for (int r = 0; r < 4; r++) o[nt][r] = 0.0f;
    float m_a = -1e30f, m_b = -1e30f, l_a = 0.0f, l_b = 0.0f;

    for (int kt = 0; kt <= qt; kt++) {
        const int k0 = kt * 64;
        __syncthreads();
#pragma unroll
        for (int a = 0; a < 8; a++) {
            int s = a * 128 + tid;
            int j = s >> 4, dq = (s & 15) * 4;
            *(uint2*)&KhiS[j][dq] =
                *(const uint2*)(Khi + (size_t)(k0 + j) * HS + dq);
            *(uint2*)&KloS[j][dq] =
                *(const uint2*)(Klo + (size_t)(k0 + j) * HS + dq);
            *(uint2*)&VhiS[j][dq] =
                *(const uint2*)(Vhi + (size_t)j * TT + k0 + dq);
            *(uint2*)&VloS[j][dq] =
                *(const uint2*)(Vlo + (size_t)j * TT + k0 + dq);
        }
        __syncthreads();

        float p[8][4];
#pragma unroll
        for (int nt = 0; nt < 8; nt++)
#pragma unroll
            for (int r = 0; r < 4; r++) p[nt][r] = 0.0f;

#pragma unroll
        for (int ks = 0; ks < 4; ks++) {
            const int kd = ks * 16 + lc * 2;
#pragma unroll
            for (int nt = 0; nt < 8; nt++) {
                const int j = nt * 8 + lr;
                unsigned bh0 = *(const unsigned*)&KhiS[j][kd];
                unsigned bh1 = *(const unsigned*)&KhiS[j][kd + 8];
                unsigned bl0 = *(const unsigned*)&KloS[j][kd];
                unsigned bl1 = *(const unsigned*)&KloS[j][kd + 8];
                mma_bf16(p[nt], qh[ks], bh0, bh1);
                mma_bf16(p[nt], qh[ks], bl0, bl1);
                mma_bf16(p[nt], ql[ks], bh0, bh1);
            }
        }

        if (kt == qt) {
#pragma unroll
            for (int nt = 0; nt < 8; nt++) {
                const int c = k0 + nt * 8 + lc * 2;
                if (c     > grow_a) p[nt][0] = -1e30f;
                if (c + 1 > grow_a) p[nt][1] = -1e30f;
                if (c     > grow_b) p[nt][2] = -1e30f;
                if (c + 1 > grow_b) p[nt][3] = -1e30f;
            }
        }

        float ma = -1e30f, mb2 = -1e30f;
#pragma unroll
        for (int nt = 0; nt < 8; nt++) {
            ma  = fmaxf(ma,  fmaxf(p[nt][0], p[nt][1]));
            mb2 = fmaxf(mb2, fmaxf(p[nt][2], p[nt][3]));
        }
        ma  = fmaxf(ma,  __shfl_xor_sync(0xffffffffu, ma, 1));
        ma  = fmaxf(ma,  __shfl_xor_sync(0xffffffffu, ma, 2));
        mb2 = fmaxf(mb2, __shfl_xor_sync(0xffffffffu, mb2, 1));
        mb2 = fmaxf(mb2, __shfl_xor_sync(0xffffffffu, mb2, 2));

        const float mna = fmaxf(m_a, ma);
        const float mnb = fmaxf(m_b, mb2);
        const float ca  = __expf(m_a - mna);
        const float cbx = __expf(m_b - mnb);

        float sa = 0.0f, sb = 0.0f;
#pragma unroll
        for (int nt = 0; nt < 8; nt++) {
            p[nt][0] = __expf(p[nt][0] - mna);
            p[nt][1] = __expf(p[nt][1] - mna);
            p[nt][2] = __expf(p[nt][2] - mnb);
            p[nt][3] = __expf(p[nt][3] - mnb);
            sa += p[nt][0] + p[nt][1];
            sb += p[nt][2] + p[nt][3];
        }
        sa += __shfl_xor_sync(0xffffffffu, sa, 1);
        sa += __shfl_xor_sync(0xffffffffu, sa, 2);
        sb += __shfl_xor_sync(0xffffffffu, sb, 1);
        sb += __shfl_xor_sync(0xffffffffu, sb, 2);
        l_a = l_a * ca + sa;   m_a = mna;
        l_b = l_b * cbx + sb;  m_b = mnb;

#pragma unroll
        for (int nt = 0; nt < 8; nt++) {
            o[nt][0] *= ca;  o[nt][1] *= ca;
            o[nt][2] *= cbx; o[nt][3] *= cbx;
        }

        unsigned pah[4][4], pal[4][4];
#pragma unroll
        for (int g = 0; g < 4; g++) {
            split2(p[2*g][0],   p[2*g][1],   pah[g][0], pal[g][0]);
            split2(p[2*g][2],   p[2*g][3],   pah[g][1], pal[g][1]);
            split2(p[2*g+1][0], p[2*g+1][1], pah[g][2], pal[g][2]);
            split2(p[2*g+1][2], p[2*g+1][3], pah[g][3], pal[g][3]);
        }

#pragma unroll
        for (int g = 0; g < 4; g++) {
            const int j0 = g * 16 + lc * 2;
#pragma unroll
            for (int nt = 0; nt < 8; nt++) {
                const int dcol = nt * 8 + lr;
                unsigned bh0 = *(const unsigned*)&VhiS[dcol][j0];
                unsigned bh1 = *(const unsigned*)&VhiS[dcol][j0 + 8];
                unsigned bl0 = *(const unsigned*)&VloS[dcol][j0];
                unsigned bl1 = *(const unsigned*)&VloS[dcol][j0 + 8];
                mma_bf16(o[nt], pah[g], bh0, bh1);
                mma_bf16(o[nt], pah[g], bl0, bl1);
                mma_bf16(o[nt], pal[g], bh0, bh1);
            }
        }
    }

    // epilogue: normalize and write bf16 hi/lo att planes
    const float rla = 1.0f / l_a;
    const float rlb = 1.0f / l_b;
    const int b = bh >> 4;
    const int h = bh & 15;
    size_t oa = ((size_t)b * TT + grow_a) * CEMB + h * HS;
    size_t ob = ((size_t)b * TT + grow_b) * CEMB + h * HS;
#pragma unroll
    for (int nt = 0; nt < 8; nt++) {
        const int col = nt * 8 + lc * 2;
        unsigned hi, lo;
        split2(o[nt][0] * rla, o[nt][1] * rla, hi, lo);
        *(unsigned*)(g_atthi + oa + col) = hi;
        *(unsigned*)(g_attlo + oa + col) = lo;
        split2(o[nt][2] * rlb, o[nt][3] * rlb, hi, lo);
        *(unsigned*)(g_atthi + ob + col) = hi;
        *(unsigned*)(g_attlo + ob + col) = lo;
    }
}

// ---------------------------------------------------------------------------
extern "C" void kernel_launch(void* const* d_in, const int* in_sizes, int n_in,
                              void* d_out, int out_size)
{
    (void)in_sizes; (void)n_in; (void)out_size;
    const float* x  = (const float*)d_in[0];
    const float* Wq = (const float*)d_in[1];
    const float* Wk = (const float*)d_in[2];
    const float* Wv = (const float*)d_in[3];
    const float* Wp = (const float*)d_in[4];
    const float* bp = (const float*)d_in[5];
    float* out = (float*)d_out;

    cudaFuncSetAttribute(qkv_gemm,
        cudaFuncAttributeMaxDynamicSharedMemorySize, GM_SMEM);
    cudaFuncSetAttribute(proj_gemm,
        cudaFuncAttributeMaxDynamicSharedMemorySize, GM_SMEM);

    split_x<<<MTOT * CEMB / 4 / 256, 256>>>(x);
    split_transW<<<dim3(CEMB / 32, CEMB / 32, 4), 256>>>(Wq, Wk, Wv, Wp);
    prep_rope<<<TT * 32 / 256, 256>>>();

    qkv_gemm<<<dim3(CEMB / 128, MTOT / 128, 3), 256, GM_SMEM>>>();

    flash_bf16<<<dim3(TT / 64, BB * NHEAD), 128>>>();

    proj_gemm<<<dim3(CEMB / 128, MTOT / 128), 256, GM_SMEM>>>(bp, out);
}

// round 8
// speedup vs baseline: 1.2247x; 1.2034x over previous
#include <cuda_runtime.h>
#include <cuda_bf16.h>
#include <cuda_fp16.h>
#include <math.h>
#include <stdint.h>

#define NHEAD 16
#define HS    64
#define CEMB  1024
#define BB    4
#define TT    2048
#define MTOT  (BB*TT)          // 8192

// ---------------- device scratch (module-load allocated) -------------------
__device__ __align__(16) float g_q[(size_t)BB*NHEAD*TT*HS];
__device__ __align__(16) float2 g_rope[(size_t)TT*32];
__device__ __align__(16) __nv_bfloat16 g_khi[(size_t)BB*NHEAD*TT*HS];
__device__ __align__(16) __nv_bfloat16 g_klo[(size_t)BB*NHEAD*TT*HS];
__device__ __align__(16) __nv_bfloat16 g_vthi[(size_t)BB*NHEAD*TT*HS]; // [bh][d][t]
__device__ __align__(16) __nv_bfloat16 g_vtlo[(size_t)BB*NHEAD*TT*HS];
__device__ __align__(16) __half g_xh[(size_t)MTOT*CEMB];      // x hi plane (fp16)
__device__ __align__(16) __half g_xl[(size_t)MTOT*CEMB];      // x lo plane
__device__ __align__(16) __half g_wt[(size_t)4*CEMB*CEMB];    // [mat][n][k] fp16
__device__ __align__(16) __half g_atth[(size_t)MTOT*CEMB];    // att hi plane
__device__ __align__(16) __half g_attl[(size_t)MTOT*CEMB];    // att lo plane

// ---------------- helpers ---------------------------------------------------
__device__ __forceinline__ void mma_bf16(float c[4], const unsigned a[4],
                                         unsigned b0, unsigned b1) {
    asm volatile(
        "mma.sync.aligned.m16n8k16.row.col.f32.bf16.bf16.f32 "
        "{%0,%1,%2,%3}, {%4,%5,%6,%7}, {%8,%9}, {%0,%1,%2,%3};\n"
        : "+f"(c[0]), "+f"(c[1]), "+f"(c[2]), "+f"(c[3])
        : "r"(a[0]), "r"(a[1]), "r"(a[2]), "r"(a[3]),
          "r"(b0), "r"(b1));
}

__device__ __forceinline__ void mma_fp16(float c[4], const unsigned a[4],
                                         unsigned b0, unsigned b1) {
    asm volatile(
        "mma.sync.aligned.m16n8k16.row.col.f32.f16.f16.f32 "
        "{%0,%1,%2,%3}, {%4,%5,%6,%7}, {%8,%9}, {%0,%1,%2,%3};\n"
        : "+f"(c[0]), "+f"(c[1]), "+f"(c[2]), "+f"(c[3])
        : "r"(a[0]), "r"(a[1]), "r"(a[2]), "r"(a[3]),
          "r"(b0), "r"(b1));
}

__device__ __forceinline__ void ldsm4(unsigned r[4], uint32_t addr) {
    asm volatile(
        "ldmatrix.sync.aligned.m8n8.x4.shared.b16 {%0,%1,%2,%3}, [%4];"
        : "=r"(r[0]), "=r"(r[1]), "=r"(r[2]), "=r"(r[3]) : "r"(addr));
}

__device__ __forceinline__ unsigned pk(__nv_bfloat16 x, __nv_bfloat16 y) {
    unsigned short a = *(unsigned short*)&x, b = *(unsigned short*)&y;
    return (unsigned)a | ((unsigned)b << 16);
}
__device__ __forceinline__ void split2(float a, float b,
                                       unsigned &hi, unsigned &lo) {
    __nv_bfloat16 ah = __float2bfloat16(a);
    __nv_bfloat16 bh = __float2bfloat16(b);
    __nv_bfloat16 al = __float2bfloat16(a - __bfloat162float(ah));
    __nv_bfloat16 bl = __float2bfloat16(b - __bfloat162float(bh));
    hi = pk(ah, bh);
    lo = pk(al, bl);
}

__device__ __forceinline__ unsigned pkh(__half x, __half y) {
    unsigned short a = *(unsigned short*)&x, b = *(unsigned short*)&y;
    return (unsigned)a | ((unsigned)b << 16);
}
// fp16 split: a = h + l with h = fp16(a), l = fp16(a - h)
__device__ __forceinline__ void split2h(float a, float b,
                                        unsigned &hi, unsigned &lo) {
    __half ah = __float2half_rn(a);
    __half bh = __float2half_rn(b);
    __half al = __float2half_rn(a - __half2float(ah));
    __half bl = __float2half_rn(b - __half2float(bh));
    hi = pkh(ah, bh);
    lo = pkh(al, bl);
}

__device__ __forceinline__ uint32_t smem_u32(const void* p) {
    uint32_t a;
    asm("{ .reg .u64 t; cvta.to.shared.u64 t, %1; cvt.u32.u64 %0, t; }"
        : "=r"(a) : "l"(p));
    return a;
}
__device__ __forceinline__ void cpa16(uint32_t dst, const void* src) {
    asm volatile("cp.async.cg.shared.global [%0], [%1], 16;\n"
                 :: "r"(dst), "l"(src));
}
#define CP_COMMIT() asm volatile("cp.async.commit_group;\n" ::: "memory")
#define CP_WAIT(n)  asm volatile("cp.async.wait_group %0;\n" :: "n"(n) : "memory")

// ---------------------------------------------------------------------------
// Prep: split x into fp16 hi/lo planes; transpose+round W to fp16 [n][k]; RoPE.
// ---------------------------------------------------------------------------
__global__ void __launch_bounds__(256) split_x(const float* __restrict__ x)
{
    int i = blockIdx.x * 256 + threadIdx.x;
    float4 v = ((const float4*)x)[i];
    unsigned h0, l0, h1, l1;
    split2h(v.x, v.y, h0, l0);
    split2h(v.z, v.w, h1, l1);
    ((uint2*)g_xh)[i] = make_uint2(h0, h1);
    ((uint2*)g_xl)[i] = make_uint2(l0, l1);
}

__global__ void __launch_bounds__(256) split_transW(
    const float* __restrict__ Wq, const float* __restrict__ Wk,
    const float* __restrict__ Wv, const float* __restrict__ Wp)
{
    __shared__ float tile[32][33];
    const int z = blockIdx.z;
    const float* W = (z == 0) ? Wq : ((z == 1) ? Wk : ((z == 2) ? Wv : Wp));
    __half* outh = g_wt + (size_t)z * CEMB * CEMB;

    const int tx = threadIdx.x & 31;
    const int ty = threadIdx.x >> 5;
    const int k0 = blockIdx.y * 32;
    const int nn0 = blockIdx.x * 32;

#pragma unroll
    for (int j = 0; j < 4; j++)
        tile[ty + 8 * j][tx] = W[(size_t)(k0 + ty + 8 * j) * CEMB + nn0 + tx];
    __syncthreads();
#pragma unroll
    for (int j = 0; j < 4; j++) {
        float v = tile[tx][ty + 8 * j];
        outh[(size_t)(nn0 + ty + 8 * j) * CEMB + k0 + tx] = __float2half_rn(v);
    }
}

__global__ void __launch_bounds__(256) prep_rope()
{
    int idx = blockIdx.x * 256 + threadIdx.x;
    int t = idx >> 5, p = idx & 31;
    const float L2T = 13.287712379549449f / 64.0f;
    float inv = exp2f(-(float)(2 * p) * L2T);
    float sv, cv;
    sincosf((float)t * inv, &sv, &cv);
    g_rope[idx] = make_float2(cv, sv);
}

// ---------------------------------------------------------------------------
// fp16x2 LDSM GEMM: 128x128 tile, BK=32, 2-stage cp.async, 256 threads,
// 8 warps (4x2 of 32x64). Planes [row][k] padded to 40 halves (80B) rows.
// Stage (bytes): Ah 0, Al 10240, B 20480; stage=30720.
// ---------------------------------------------------------------------------
#define PL_B   10240
#define STG_B  30720
#define GM_SMEM (2 * STG_B)    // 61440

__device__ __forceinline__ void gemm_main_fp16(
    const __half* __restrict__ Ahg, const __half* __restrict__ Alg,
    const __half* __restrict__ Bg,
    int m0, int n0, char* smp, float acc[2][8][4])
{
    const int tid  = threadIdx.x;
    const int warp = tid >> 5;
    const int lane = tid & 31;
    const int wm = warp >> 1;
    const int wn = warp & 1;
    const uint32_t sb = smem_u32(smp);

#pragma unroll
    for (int mt = 0; mt < 2; mt++)
#pragma unroll
        for (int nt = 0; nt < 8; nt++)
#pragma unroll
            for (int r = 0; r < 4; r++) acc[mt][nt][r] = 0.0f;

    // staging slots: 3 planes * 128 rows * 4 segs = 1536 / 256 thr = 6 each
    const __half* sp[6];
    uint32_t doff[6];
#pragma unroll
    for (int i = 0; i < 6; i++) {
        int g = i * 256 + tid;
        int pl = g >> 9;             // 0..2
        int r  = (g >> 2) & 127;
        int sg = g & 3;
        const __half* base = (pl == 0) ? Ahg : ((pl == 1) ? Alg : Bg);
        int rbase = (pl < 2) ? m0 : n0;
        sp[i]   = base + (size_t)(rbase + r) * CEMB + sg * 8;
        doff[i] = (uint32_t)(pl * PL_B + r * 80 + sg * 16);
    }

#define GM_ISSUE(CK, S) do {                                  \
    const int kb_ = (CK) * 32;                                \
    uint32_t st_ = sb + (S) * STG_B;                          \
    _Pragma("unroll")                                         \
    for (int i = 0; i < 6; i++)                               \
        cpa16(st_ + doff[i], sp[i] + kb_);                    \
    CP_COMMIT();                                              \
} while (0)

    GM_ISSUE(0, 0);

    // ldmatrix lane addressing (validated round 7)
    const int a_row = lane & 15;
    const int a_kh  = lane >> 4;
    const uint32_t aoff = (uint32_t)((wm * 32 + a_row) * 80 + a_kh * 16);
    const int b_n  = ((lane >> 4) << 3) + (lane & 7);
    const int b_kh = (lane >> 3) & 1;
    const uint32_t boff = (uint32_t)(2 * PL_B + (wn * 64 + b_n) * 80 + b_kh * 16);

    for (int ck = 0; ck < 32; ck++) {
        if (ck + 1 < 32) {
            GM_ISSUE(ck + 1, (ck + 1) & 1);
            CP_WAIT(1);
        } else {
            CP_WAIT(0);
        }
        __syncthreads();

        const uint32_t st = sb + (ck & 1) * STG_B;
#pragma unroll
        for (int kk = 0; kk < 2; kk++) {
            unsigned Ah[2][4], Al[2][4];
#pragma unroll
            for (int mt = 0; mt < 2; mt++) {
                ldsm4(Ah[mt], st + aoff + mt * 1280 + kk * 32);
                ldsm4(Al[mt], st + PL_B + aoff + mt * 1280 + kk * 32);
            }
#pragma unroll
            for (int ntp = 0; ntp < 4; ntp++) {
                unsigned Bh[4];
                ldsm4(Bh, st + boff + ntp * 1280 + kk * 32);
#pragma unroll
                for (int mt = 0; mt < 2; mt++) {
                    mma_fp16(acc[mt][ntp * 2 + 0], Ah[mt], Bh[0], Bh[1]);
                    mma_fp16(acc[mt][ntp * 2 + 0], Al[mt], Bh[0], Bh[1]);
                    mma_fp16(acc[mt][ntp * 2 + 1], Ah[mt], Bh[2], Bh[3]);
                    mma_fp16(acc[mt][ntp * 2 + 1], Al[mt], Bh[2], Bh[3]);
                }
            }
        }
        __syncthreads();
    }
#undef GM_ISSUE
}

// ---------------------------------------------------------------------------
// QKV: mode 0=Q(+RoPE)->fp32 g_q, 1=K(+RoPE)->bf16 planes, 2=V->trans planes
// ---------------------------------------------------------------------------
__global__ void __launch_bounds__(256, 2) qkv_gemm()
{
    extern __shared__ char smp[];
    const int mode = blockIdx.z;
    const int m0 = blockIdx.y * 128;
    const int n0 = blockIdx.x * 128;

    float acc[2][8][4];
    gemm_main_fp16(g_xh, g_xl, g_wt + (size_t)mode * CEMB * CEMB,
                   m0, n0, smp, acc);

    const int warp = threadIdx.x >> 5;
    const int lane = threadIdx.x & 31;
    const int wm = warp >> 1;
    const int wn = warp & 1;

#pragma unroll
    for (int mt = 0; mt < 2; mt++) {
        const int row_base = m0 + wm * 32 + mt * 16 + (lane >> 2);
#pragma unroll
        for (int nt = 0; nt < 8; nt++) {
            const int col = n0 + wn * 64 + nt * 8 + (lane & 3) * 2;
            const int h = col >> 6;
            const int d = col & 63;
#pragma unroll
            for (int half = 0; half < 2; half++) {
                const int row = row_base + half * 8;
                const int b = row >> 11;
                const int t = row & 2047;
                float x0 = acc[mt][nt][half * 2];
                float x1 = acc[mt][nt][half * 2 + 1];
                float o0 = x0, o1 = x1;
                if (mode < 2) {
                    float2 cs = g_rope[t * 32 + (d >> 1)];
                    o0 = x0 * cs.x - x1 * cs.y;
                    o1 = x0 * cs.y + x1 * cs.x;
                }
                const int bh = b * NHEAD + h;
                if (mode == 0) {
                    size_t base = ((size_t)bh * TT + t) * HS + d;
                    *(float2*)(g_q + base) = make_float2(o0, o1);
                } else if (mode == 1) {
                    size_t base = ((size_t)bh * TT + t) * HS + d;
                    unsigned hi, lo;
                    split2(o0, o1, hi, lo);
                    *(unsigned*)(g_khi + base) = hi;
                    *(unsigned*)(g_klo + base) = lo;
                } else {
                    size_t tb = ((size_t)bh * HS + d) * TT + t;
                    __nv_bfloat16 h0 = __float2bfloat16(o0);
                    __nv_bfloat16 h1 = __float2bfloat16(o1);
                    g_vthi[tb]      = h0;
                    g_vthi[tb + TT] = h1;
                    g_vtlo[tb]      = __float2bfloat16(o0 - __bfloat162float(h0));
                    g_vtlo[tb + TT] = __float2bfloat16(o1 - __bfloat162float(h1));
                }
            }
        }
    }
}

// ---------------------------------------------------------------------------
// Output projection: att fp16 planes @ WpT fp16 + bias -> fp32 out
// ---------------------------------------------------------------------------
__global__ void __launch_bounds__(256, 2) proj_gemm(
    const float* __restrict__ bp, float* __restrict__ out)
{
    extern __shared__ char smp[];
    const int m0 = blockIdx.y * 128;
    const int n0 = blockIdx.x * 128;

    float acc[2][8][4];
    gemm_main_fp16(g_atth, g_attl, g_wt + (size_t)3 * CEMB * CEMB,
                   m0, n0, smp, acc);

    const int warp = threadIdx.x >> 5;
    const int lane = threadIdx.x & 31;
    const int wm = warp >> 1;
    const int wn = warp & 1;

#pragma unroll
    for (int mt = 0; mt < 2; mt++) {
        const int row_base = m0 + wm * 32 + mt * 16 + (lane >> 2);
#pragma unroll
        for (int nt = 0; nt < 8; nt++) {
            const int col = n0 + wn * 64 + nt * 8 + (lane & 3) * 2;
            const float b0 = bp[col];
            const float b1 = bp[col + 1];
#pragma unroll
            for (int half = 0; half < 2; half++) {
                const int row = row_base + half * 8;
                *(float2*)(out + (size_t)row * CEMB + col) =
                    make_float2(acc[mt][nt][half * 2]     + b0,
                                acc[mt][nt][half * 2 + 1] + b1);
            }
        }
    }
}

// ---------------------------------------------------------------------------
// Flash attention, bf16x3 mma.sync (validated). Writes att fp16 hi/lo planes.
// ---------------------------------------------------------------------------
#define KVS 72

__global__ void __launch_bounds__(128) flash_bf16()
{
    __shared__ __nv_bfloat16 KhiS[64][KVS];
    __shared__ __nv_bfloat16 KloS[64][KVS];
    __shared__ __nv_bfloat16 VhiS[64][KVS];   // [d][j]
    __shared__ __nv_bfloat16 VloS[64][KVS];

    const int tid  = threadIdx.x;
    const int warp = tid >> 5;
    const int lane = tid & 31;
    const int qt   = gridDim.x - 1 - blockIdx.x;
    const int q0   = qt * 64;
    const int bh   = blockIdx.y;

    const float* Q = g_q + (size_t)bh * TT * HS;
    const __nv_bfloat16* Khi = g_khi + (size_t)bh * TT * HS;
    const __nv_bfloat16* Klo = g_klo + (size_t)bh * TT * HS;
    const __nv_bfloat16* Vhi = g_vthi + (size_t)bh * HS * TT;
    const __nv_bfloat16* Vlo = g_vtlo + (size_t)bh * HS * TT;

    const int lr = lane >> 2;
    const int lc = lane & 3;
    const int lrow = warp * 16 + lr;
    const int grow_a = q0 + lrow;
    const int grow_b = grow_a + 8;

    unsigned qh[4][4], ql[4][4];
#pragma unroll
    for (int ks = 0; ks < 4; ks++) {
        const int kd = ks * 16 + lc * 2;
        const float* qa = Q + (size_t)grow_a * HS;
        const float* qb = Q + (size_t)grow_b * HS;
        float2 v0 = *(const float2*)(qa + kd);
        float2 v1 = *(const float2*)(qb + kd);
        float2 v2 = *(const float2*)(qa + kd + 8);
        float2 v3 = *(const float2*)(qb + kd + 8);
        split2(v0.x * 0.125f, v0.y * 0.125f, qh[ks][0], ql[ks][0]);
        split2(v1.x * 0.125f, v1.y * 0.125f, qh[ks][1], ql[ks][1]);
        split2(v2.x * 0.125f, v2.y * 0.125f, qh[ks][2], ql[ks][2]);
        split2(v3.x * 0.125f, v3.y * 0.125f, qh[ks][3], ql[ks][3]);
    }

    float o[8][4];
#pragma unroll
    for (int nt = 0; nt < 8; nt++)
#pragma unroll
        for (int r = 0; r < 4; r++) o[nt][r] = 0.0f;
    float m_a = -1e30f, m_b = -1e30f, l_a = 0.0f, l_b = 0.0f;

    for (int kt = 0; kt <= qt; kt++) {
        const int k0 = kt * 64;
        __syncthreads();
#pragma unroll
        for (int a = 0; a < 8; a++) {
            int s = a * 128 + tid;
            int j = s >> 4, dq = (s & 15) * 4;
            *(uint2*)&KhiS[j][dq] =
                *(const uint2*)(Khi + (size_t)(k0 + j) * HS + dq);
            *(uint2*)&KloS[j][dq] =
                *(const uint2*)(Klo + (size_t)(k0 + j) * HS + dq);
            *(uint2*)&VhiS[j][dq] =
                *(const uint2*)(Vhi + (size_t)j * TT + k0 + dq);
            *(uint2*)&VloS[j][dq] =
                *(const uint2*)(Vlo + (size_t)j * TT + k0 + dq);
        }
        __syncthreads();

        float p[8][4];
#pragma unroll
        for (int nt = 0; nt < 8; nt++)
#pragma unroll
            for (int r = 0; r < 4; r++) p[nt][r] = 0.0f;

#pragma unroll
        for (int ks = 0; ks < 4; ks++) {
            const int kd = ks * 16 + lc * 2;
#pragma unroll
            for (int nt = 0; nt < 8; nt++) {
                const int j = nt * 8 + lr;
                unsigned bh0 = *(const unsigned*)&KhiS[j][kd];
                unsigned bh1 = *(const unsigned*)&KhiS[j][kd + 8];
                unsigned bl0 = *(const unsigned*)&KloS[j][kd];
                unsigned bl1 = *(const unsigned*)&KloS[j][kd + 8];
                mma_bf16(p[nt], qh[ks], bh0, bh1);
                mma_bf16(p[nt], qh[ks], bl0, bl1);
                mma_bf16(p[nt], ql[ks], bh0, bh1);
            }
        }

        if (kt == qt) {
#pragma unroll
            for (int nt = 0; nt < 8; nt++) {
                const int c = k0 + nt * 8 + lc * 2;
                if (c     > grow_a) p[nt][0] = -1e30f;
                if (c + 1 > grow_a) p[nt][1] = -1e30f;
                if (c     > grow_b) p[nt][2] = -1e30f;
                if (c + 1 > grow_b) p[nt][3] = -1e30f;
            }
        }

        float ma = -1e30f, mb2 = -1e30f;
#pragma unroll
        for (int nt = 0; nt < 8; nt++) {
            ma  = fmaxf(ma,  fmaxf(p[nt][0], p[nt][1]));
            mb2 = fmaxf(mb2, fmaxf(p[nt][2], p[nt][3]));
        }
        ma  = fmaxf(ma,  __shfl_xor_sync(0xffffffffu, ma, 1));
        ma  = fmaxf(ma,  __shfl_xor_sync(0xffffffffu, ma, 2));
        mb2 = fmaxf(mb2, __shfl_xor_sync(0xffffffffu, mb2, 1));
        mb2 = fmaxf(mb2, __shfl_xor_sync(0xffffffffu, mb2, 2));

        const float mna = fmaxf(m_a, ma);
        const float mnb = fmaxf(m_b, mb2);
        const float ca  = __expf(m_a - mna);
        const float cbx = __expf(m_b - mnb);

        float sa = 0.0f, sb = 0.0f;
#pragma unroll
        for (int nt = 0; nt < 8; nt++) {
            p[nt][0] = __expf(p[nt][0] - mna);
            p[nt][1] = __expf(p[nt][1] - mna);
            p[nt][2] = __expf(p[nt][2] - mnb);
            p[nt][3] = __expf(p[nt][3] - mnb);
            sa += p[nt][0] + p[nt][1];
            sb += p[nt][2] + p[nt][3];
        }
        sa += __shfl_xor_sync(0xffffffffu, sa, 1);
        sa += __shfl_xor_sync(0xffffffffu, sa, 2);
        sb += __shfl_xor_sync(0xffffffffu, sb, 1);
        sb += __shfl_xor_sync(0xffffffffu, sb, 2);
        l_a = l_a * ca + sa;   m_a = mna;
        l_b = l_b * cbx + sb;  m_b = mnb;

#pragma unroll
        for (int nt = 0; nt < 8; nt++) {
            o[nt][0] *= ca;  o[nt][1] *= ca;
            o[nt][2] *= cbx; o[nt][3] *= cbx;
        }

        unsigned pah[4][4], pal[4][4];
#pragma unroll
        for (int g = 0; g < 4; g++) {
            split2(p[2*g][0],   p[2*g][1],   pah[g][0], pal[g][0]);
            split2(p[2*g][2],   p[2*g][3],   pah[g][1], pal[g][1]);
            split2(p[2*g+1][0], p[2*g+1][1], pah[g][2], pal[g][2]);
            split2(p[2*g+1][2], p[2*g+1][3], pah[g][3], pal[g][3]);
        }

#pragma unroll
        for (int g = 0; g < 4; g++) {
            const int j0 = g * 16 + lc * 2;
#pragma unroll
            for (int nt = 0; nt < 8; nt++) {
                const int dcol = nt * 8 + lr;
                unsigned bh0 = *(const unsigned*)&VhiS[dcol][j0];
                unsigned bh1 = *(const unsigned*)&VhiS[dcol][j0 + 8];
                unsigned bl0 = *(const unsigned*)&VloS[dcol][j0];
                unsigned bl1 = *(const unsigned*)&VloS[dcol][j0 + 8];
                mma_bf16(o[nt], pah[g], bh0, bh1);
                mma_bf16(o[nt], pah[g], bl0, bl1);
                mma_bf16(o[nt], pal[g], bh0, bh1);
            }
        }
    }

    // epilogue: normalize, write fp16 hi/lo att planes (A operand of proj)
    const float rla = 1.0f / l_a;
    const float rlb = 1.0f / l_b;
    const int b = bh >> 4;
    const int h = bh & 15;
    size_t oa = ((size_t)b * TT + grow_a) * CEMB + h * HS;
    size_t ob = ((size_t)b * TT + grow_b) * CEMB + h * HS;
#pragma unroll
    for (int nt = 0; nt < 8; nt++) {
        const int col = nt * 8 + lc * 2;
        unsigned hi, lo;
        split2h(o[nt][0] * rla, o[nt][1] * rla, hi, lo);
        *(unsigned*)(g_atth + oa + col) = hi;
        *(unsigned*)(g_attl + oa + col) = lo;
        split2h(o[nt][2] * rlb, o[nt][3] * rlb, hi, lo);
        *(unsigned*)(g_atth + ob + col) = hi;
        *(unsigned*)(g_attl + ob + col) = lo;
    }
}

// ---------------------------------------------------------------------------
extern "C" void kernel_launch(void* const* d_in, const int* in_sizes, int n_in,
                              void* d_out, int out_size)
{
    (void)in_sizes; (void)n_in; (void)out_size;
    const float* x  = (const float*)d_in[0];
    const float* Wq = (const float*)d_in[1];
    const float* Wk = (const float*)d_in[2];
    const float* Wv = (const float*)d_in[3];
    const float* Wp = (const float*)d_in[4];
    const float* bp = (const float*)d_in[5];
    float* out = (float*)d_out;

    cudaFuncSetAttribute(qkv_gemm,
        cudaFuncAttributeMaxDynamicSharedMemorySize, GM_SMEM);
    cudaFuncSetAttribute(proj_gemm,
        cudaFuncAttributeMaxDynamicSharedMemorySize, GM_SMEM);

    split_x<<<MTOT * CEMB / 4 / 256, 256>>>(x);
    split_transW<<<dim3(CEMB / 32, CEMB / 32, 4), 256>>>(Wq, Wk, Wv, Wp);
    prep_rope<<<TT * 32 / 256, 256>>>();

    qkv_gemm<<<dim3(CEMB / 128, MTOT / 128, 3), 256, GM_SMEM>>>();

    flash_bf16<<<dim3(TT / 64, BB * NHEAD), 128>>>();

    proj_gemm<<<dim3(CEMB / 128, MTOT / 128), 256, GM_SMEM>>>(bp, out);
}

// round 9
// speedup vs baseline: 1.2955x; 1.0578x over previous
#include <cuda_runtime.h>
#include <cuda_bf16.h>
#include <cuda_fp16.h>
#include <math.h>
#include <stdint.h>

#define NHEAD 16
#define HS    64
#define CEMB  1024
#define BB    4
#define TT    2048
#define MTOT  (BB*TT)          // 8192

// ---------------- device scratch (module-load allocated) -------------------
__device__ __align__(16) float g_q[(size_t)BB*NHEAD*TT*HS];
__device__ __align__(16) float2 g_rope[(size_t)TT*32];
__device__ __align__(16) __half g_kh[(size_t)BB*NHEAD*TT*HS];   // K fp16 [bh][t][d]
__device__ __align__(16) __half g_vt[(size_t)BB*NHEAD*TT*HS];   // V fp16 [bh][d][t]
__device__ __align__(16) __half g_xh[(size_t)MTOT*CEMB];        // x hi plane
__device__ __align__(16) __half g_xl[(size_t)MTOT*CEMB];        // x lo plane
__device__ __align__(16) __half g_wt[(size_t)4*CEMB*CEMB];      // [mat][n][k]
__device__ __align__(16) __half g_atth[(size_t)MTOT*CEMB];      // att hi plane
__device__ __align__(16) __half g_attl[(size_t)MTOT*CEMB];      // att lo plane

// ---------------- helpers ---------------------------------------------------
__device__ __forceinline__ void mma_fp16(float c[4], const unsigned a[4],
                                         unsigned b0, unsigned b1) {
    asm volatile(
        "mma.sync.aligned.m16n8k16.row.col.f32.f16.f16.f32 "
        "{%0,%1,%2,%3}, {%4,%5,%6,%7}, {%8,%9}, {%0,%1,%2,%3};\n"
        : "+f"(c[0]), "+f"(c[1]), "+f"(c[2]), "+f"(c[3])
        : "r"(a[0]), "r"(a[1]), "r"(a[2]), "r"(a[3]),
          "r"(b0), "r"(b1));
}

__device__ __forceinline__ void ldsm4(unsigned r[4], uint32_t addr) {
    asm volatile(
        "ldmatrix.sync.aligned.m8n8.x4.shared.b16 {%0,%1,%2,%3}, [%4];"
        : "=r"(r[0]), "=r"(r[1]), "=r"(r[2]), "=r"(r[3]) : "r"(addr));
}

__device__ __forceinline__ unsigned pkh(__half x, __half y) {
    unsigned short a = *(unsigned short*)&x, b = *(unsigned short*)&y;
    return (unsigned)a | ((unsigned)b << 16);
}
// fp16 split: a = h + l with h = fp16(a), l = fp16(a - h)
__device__ __forceinline__ void split2h(float a, float b,
                                        unsigned &hi, unsigned &lo) {
    __half ah = __float2half_rn(a);
    __half bh = __float2half_rn(b);
    __half al = __float2half_rn(a - __half2float(ah));
    __half bl = __float2half_rn(b - __half2float(bh));
    hi = pkh(ah, bh);
    lo = pkh(al, bl);
}

__device__ __forceinline__ uint32_t smem_u32(const void* p) {
    uint32_t a;
    asm("{ .reg .u64 t; cvta.to.shared.u64 t, %1; cvt.u32.u64 %0, t; }"
        : "=r"(a) : "l"(p));
    return a;
}
__device__ __forceinline__ void cpa16(uint32_t dst, const void* src) {
    asm volatile("cp.async.cg.shared.global [%0], [%1], 16;\n"
                 :: "r"(dst), "l"(src));
}
#define CP_COMMIT() asm volatile("cp.async.commit_group;\n" ::: "memory")
#define CP_WAIT(n)  asm volatile("cp.async.wait_group %0;\n" :: "n"(n) : "memory")

// ---------------------------------------------------------------------------
// Prep: split x into fp16 hi/lo planes; transpose+round W to fp16 [n][k]; RoPE.
// ---------------------------------------------------------------------------
__global__ void __launch_bounds__(256) split_x(const float* __restrict__ x)
{
    int i = blockIdx.x * 256 + threadIdx.x;
    float4 v = ((const float4*)x)[i];
    unsigned h0, l0, h1, l1;
    split2h(v.x, v.y, h0, l0);
    split2h(v.z, v.w, h1, l1);
    ((uint2*)g_xh)[i] = make_uint2(h0, h1);
    ((uint2*)g_xl)[i] = make_uint2(l0, l1);
}

__global__ void __launch_bounds__(256) split_transW(
    const float* __restrict__ Wq, const float* __restrict__ Wk,
    const float* __restrict__ Wv, const float* __restrict__ Wp)
{
    __shared__ float tile[32][33];
    const int z = blockIdx.z;
    const float* W = (z == 0) ? Wq : ((z == 1) ? Wk : ((z == 2) ? Wv : Wp));
    __half* outh = g_wt + (size_t)z * CEMB * CEMB;

    const int tx = threadIdx.x & 31;
    const int ty = threadIdx.x >> 5;
    const int k0 = blockIdx.y * 32;
    const int nn0 = blockIdx.x * 32;

#pragma unroll
    for (int j = 0; j < 4; j++)
        tile[ty + 8 * j][tx] = W[(size_t)(k0 + ty + 8 * j) * CEMB + nn0 + tx];
    __syncthreads();
#pragma unroll
    for (int j = 0; j < 4; j++) {
        float v = tile[tx][ty + 8 * j];
        outh[(size_t)(nn0 + ty + 8 * j) * CEMB + k0 + tx] = __float2half_rn(v);
    }
}

__global__ void __launch_bounds__(256) prep_rope()
{
    int idx = blockIdx.x * 256 + threadIdx.x;
    int t = idx >> 5, p = idx & 31;
    const float L2T = 13.287712379549449f / 64.0f;
    float inv = exp2f(-(float)(2 * p) * L2T);
    float sv, cv;
    sincosf((float)t * inv, &sv, &cv);
    g_rope[idx] = make_float2(cv, sv);
}

// ---------------------------------------------------------------------------
// fp16x2 LDSM GEMM (validated round 8): 128x128 tile, BK=32, 2-stage cp.async.
// ---------------------------------------------------------------------------
#define PL_B   10240
#define STG_B  30720
#define GM_SMEM (2 * STG_B)    // 61440

__device__ __forceinline__ void gemm_main_fp16(
    const __half* __restrict__ Ahg, const __half* __restrict__ Alg,
    const __half* __restrict__ Bg,
    int m0, int n0, char* smp, float acc[2][8][4])
{
    const int tid  = threadIdx.x;
    const int warp = tid >> 5;
    const int lane = tid & 31;
    const int wm = warp >> 1;
    const int wn = warp & 1;
    const uint32_t sb = smem_u32(smp);

#pragma unroll
    for (int mt = 0; mt < 2; mt++)
#pragma unroll
        for (int nt = 0; nt < 8; nt++)
#pragma unroll
            for (int r = 0; r < 4; r++) acc[mt][nt][r] = 0.0f;

    const __half* sp[6];
    uint32_t doff[6];
#pragma unroll
    for (int i = 0; i < 6; i++) {
        int g = i * 256 + tid;
        int pl = g >> 9;
        int r  = (g >> 2) & 127;
        int sg = g & 3;
        const __half* base = (pl == 0) ? Ahg : ((pl == 1) ? Alg : Bg);
        int rbase = (pl < 2) ? m0 : n0;
        sp[i]   = base + (size_t)(rbase + r) * CEMB + sg * 8;
        doff[i] = (uint32_t)(pl * PL_B + r * 80 + sg * 16);
    }

#define GM_ISSUE(CK, S) do {                                  \
    const int kb_ = (CK) * 32;                                \
    uint32_t st_ = sb + (S) * STG_B;                          \
    _Pragma("unroll")                                         \
    for (int i = 0; i < 6; i++)                               \
        cpa16(st_ + doff[i], sp[i] + kb_);                    \
    CP_COMMIT();                                              \
} while (0)

    GM_ISSUE(0, 0);

    const int a_row = lane & 15;
    const int a_kh  = lane >> 4;
    const uint32_t aoff = (uint32_t)((wm * 32 + a_row) * 80 + a_kh * 16);
    const int b_n  = ((lane >> 4) << 3) + (lane & 7);
    const int b_kh = (lane >> 3) & 1;
    const uint32_t boff = (uint32_t)(2 * PL_B + (wn * 64 + b_n) * 80 + b_kh * 16);

    for (int ck = 0; ck < 32; ck++) {
        if (ck + 1 < 32) {
            GM_ISSUE(ck + 1, (ck + 1) & 1);
            CP_WAIT(1);
        } else {
            CP_WAIT(0);
        }
        __syncthreads();

        const uint32_t st = sb + (ck & 1) * STG_B;
#pragma unroll
        for (int kk = 0; kk < 2; kk++) {
            unsigned Ah[2][4], Al[2][4];
#pragma unroll
            for (int mt = 0; mt < 2; mt++) {
                ldsm4(Ah[mt], st + aoff + mt * 1280 + kk * 32);
                ldsm4(Al[mt], st + PL_B + aoff + mt * 1280 + kk * 32);
            }
#pragma unroll
            for (int ntp = 0; ntp < 4; ntp++) {
                unsigned Bh[4];
                ldsm4(Bh, st + boff + ntp * 1280 + kk * 32);
#pragma unroll
                for (int mt = 0; mt < 2; mt++) {
                    mma_fp16(acc[mt][ntp * 2 + 0], Ah[mt], Bh[0], Bh[1]);
                    mma_fp16(acc[mt][ntp * 2 + 0], Al[mt], Bh[0], Bh[1]);
                    mma_fp16(acc[mt][ntp * 2 + 1], Ah[mt], Bh[2], Bh[3]);
                    mma_fp16(acc[mt][ntp * 2 + 1], Al[mt], Bh[2], Bh[3]);
                }
            }
        }
        __syncthreads();
    }
#undef GM_ISSUE
}

// ---------------------------------------------------------------------------
// QKV: mode 0=Q(+RoPE)->fp32 g_q, 1=K(+RoPE)->fp16 g_kh, 2=V->fp16 g_vt trans
// ---------------------------------------------------------------------------
__global__ void __launch_bounds__(256, 2) qkv_gemm()
{
    extern __shared__ char smp[];
    const int mode = blockIdx.z;
    const int m0 = blockIdx.y * 128;
    const int n0 = blockIdx.x * 128;

    float acc[2][8][4];
    gemm_main_fp16(g_xh, g_xl, g_wt + (size_t)mode * CEMB * CEMB,
                   m0, n0, smp, acc);

    const int warp = threadIdx.x >> 5;
    const int lane = threadIdx.x & 31;
    const int wm = warp >> 1;
    const int wn = warp & 1;

#pragma unroll
    for (int mt = 0; mt < 2; mt++) {
        const int row_base = m0 + wm * 32 + mt * 16 + (lane >> 2);
#pragma unroll
        for (int nt = 0; nt < 8; nt++) {
            const int col = n0 + wn * 64 + nt * 8 + (lane & 3) * 2;
            const int h = col >> 6;
            const int d = col & 63;
#pragma unroll
            for (int half = 0; half < 2; half++) {
                const int row = row_base + half * 8;
                const int b = row >> 11;
                const int t = row & 2047;
                float x0 = acc[mt][nt][half * 2];
                float x1 = acc[mt][nt][half * 2 + 1];
                float o0 = x0, o1 = x1;
                if (mode < 2) {
                    float2 cs = g_rope[t * 32 + (d >> 1)];
                    o0 = x0 * cs.x - x1 * cs.y;
                    o1 = x0 * cs.y + x1 * cs.x;
                }
                const int bh = b * NHEAD + h;
                if (mode == 0) {
                    size_t base = ((size_t)bh * TT + t) * HS + d;
                    *(float2*)(g_q + base) = make_float2(o0, o1);
                } else if (mode == 1) {
                    size_t base = ((size_t)bh * TT + t) * HS + d;
                    *(unsigned*)(g_kh + base) =
                        pkh(__float2half_rn(o0), __float2half_rn(o1));
                } else {
                    size_t tb = ((size_t)bh * HS + d) * TT + t;
                    g_vt[tb]      = __float2half_rn(o0);
                    g_vt[tb + TT] = __float2half_rn(o1);
                }
            }
        }
    }
}

// ---------------------------------------------------------------------------
// Output projection: att fp16 planes @ WpT fp16 + bias -> fp32 out
// ---------------------------------------------------------------------------
__global__ void __launch_bounds__(256, 2) proj_gemm(
    const float* __restrict__ bp, float* __restrict__ out)
{
    extern __shared__ char smp[];
    const int m0 = blockIdx.y * 128;
    const int n0 = blockIdx.x * 128;

    float acc[2][8][4];
    gemm_main_fp16(g_atth, g_attl, g_wt + (size_t)3 * CEMB * CEMB,
                   m0, n0, smp, acc);

    const int warp = threadIdx.x >> 5;
    const int lane = threadIdx.x & 31;
    const int wm = warp >> 1;
    const int wn = warp & 1;

#pragma unroll
    for (int mt = 0; mt < 2; mt++) {
        const int row_base = m0 + wm * 32 + mt * 16 + (lane >> 2);
#pragma unroll
        for (int nt = 0; nt < 8; nt++) {
            const int col = n0 + wn * 64 + nt * 8 + (lane & 3) * 2;
            const float b0 = bp[col];
            const float b1 = bp[col + 1];
#pragma unroll
            for (int half = 0; half < 2; half++) {
                const int row = row_base + half * 8;
                *(float2*)(out + (size_t)row * CEMB + col) =
                    make_float2(acc[mt][nt][half * 2]     + b0,
                                acc[mt][nt][half * 2 + 1] + b1);
            }
        }
    }
}

// ---------------------------------------------------------------------------
// Flash attention, fp16x2: BM=128 (8 warps x m16), BN=64, D=64.
// QK: Q split fp16 (hi/lo) x K fp16 single -> 2 MMAs.
// PV: P split fp16 (hi/lo) x V fp16 single -> 2 MMAs.
// Smem: K [j][d] fp16 stride 72, V [d][j] fp16 stride 72 (single planes).
// ---------------------------------------------------------------------------
#define KVS 72

__global__ void __launch_bounds__(256) flash_fp16()
{
    __shared__ __half KS[64][KVS];
    __shared__ __half VS[64][KVS];   // [d][j]

    const int tid  = threadIdx.x;
    const int warp = tid >> 5;
    const int lane = tid & 31;
    const int qt   = gridDim.x - 1 - blockIdx.x;   // big tiles first
    const int q0   = qt * 128;
    const int bh   = blockIdx.y;

    const float* Q = g_q + (size_t)bh * TT * HS;
    const __half* K = g_kh + (size_t)bh * TT * HS;
    const __half* V = g_vt + (size_t)bh * HS * TT;

    const int lr = lane >> 2;
    const int lc = lane & 3;
    const int lrow = warp * 16 + lr;     // 0..127
    const int grow_a = q0 + lrow;
    const int grow_b = grow_a + 8;

    // Q fragments: scaled, split fp16 hi/lo
    unsigned qh[4][4], ql[4][4];
#pragma unroll
    for (int ks = 0; ks < 4; ks++) {
        const int kd = ks * 16 + lc * 2;
        const float* qa = Q + (size_t)grow_a * HS;
        const float* qb = Q + (size_t)grow_b * HS;
        float2 v0 = *(const float2*)(qa + kd);
        float2 v1 = *(const float2*)(qb + kd);
        float2 v2 = *(const float2*)(qa + kd + 8);
        float2 v3 = *(const float2*)(qb + kd + 8);
        split2h(v0.x * 0.125f, v0.y * 0.125f, qh[ks][0], ql[ks][0]);
        split2h(v1.x * 0.125f, v1.y * 0.125f, qh[ks][1], ql[ks][1]);
        split2h(v2.x * 0.125f, v2.y * 0.125f, qh[ks][2], ql[ks][2]);
        split2h(v3.x * 0.125f, v3.y * 0.125f, qh[ks][3], ql[ks][3]);
    }

    float o[8][4];
#pragma unroll
    for (int nt = 0; nt < 8; nt++)
#pragma unroll
        for (int r = 0; r < 4; r++) o[nt][r] = 0.0f;
    float m_a = -1e30f, m_b = -1e30f, l_a = 0.0f, l_b = 0.0f;

    const int nkt = 2 * qt + 2;
    for (int kt = 0; kt < nkt; kt++) {
        const int k0 = kt * 64;
        __syncthreads();
        // stage K and V tiles: 512 uint4 slots per tensor / 256 thr = 2 each
#pragma unroll
        for (int a = 0; a < 2; a++) {
            int s = a * 256 + tid;
            int j = s >> 3, dq = (s & 7) * 8;
            *(uint4*)&KS[j][dq] = *(const uint4*)(K + (size_t)(k0 + j) * HS + dq);
            *(uint4*)&VS[j][dq] = *(const uint4*)(V + (size_t)j * TT + k0 + dq);
        }
        __syncthreads();

        // S = Q K^T (fp16x2)
        float p[8][4];
#pragma unroll
        for (int nt = 0; nt < 8; nt++)
#pragma unroll
            for (int r = 0; r < 4; r++) p[nt][r] = 0.0f;

#pragma unroll
        for (int ks = 0; ks < 4; ks++) {
            const int kd = ks * 16 + lc * 2;
#pragma unroll
            for (int nt = 0; nt < 8; nt++) {
                const int j = nt * 8 + lr;
                unsigned b0 = *(const unsigned*)&KS[j][kd];
                unsigned b1 = *(const unsigned*)&KS[j][kd + 8];
                mma_fp16(p[nt], qh[ks], b0, b1);
                mma_fp16(p[nt], ql[ks], b0, b1);
            }
        }

        // causal mask (last two tiles intersect the diagonal band)
        if (kt + 2 >= nkt) {
#pragma unroll
            for (int nt = 0; nt < 8; nt++) {
                const int c = k0 + nt * 8 + lc * 2;
                if (c     > grow_a) p[nt][0] = -1e30f;
                if (c + 1 > grow_a) p[nt][1] = -1e30f;
                if (c     > grow_b) p[nt][2] = -1e30f;
                if (c + 1 > grow_b) p[nt][3] = -1e30f;
            }
        }

        // online softmax
        float ma = -1e30f, mb2 = -1e30f;
#pragma unroll
        for (int nt = 0; nt < 8; nt++) {
            ma  = fmaxf(ma,  fmaxf(p[nt][0], p[nt][1]));
            mb2 = fmaxf(mb2, fmaxf(p[nt][2], p[nt][3]));
        }
        ma  = fmaxf(ma,  __shfl_xor_sync(0xffffffffu, ma, 1));
        ma  = fmaxf(ma,  __shfl_xor_sync(0xffffffffu, ma, 2));
        mb2 = fmaxf(mb2, __shfl_xor_sync(0xffffffffu, mb2, 1));
        mb2 = fmaxf(mb2, __shfl_xor_sync(0xffffffffu, mb2, 2));

        const float mna = fmaxf(m_a, ma);
        const float mnb = fmaxf(m_b, mb2);
        const float ca  = __expf(m_a - mna);
        const float cbx = __expf(m_b - mnb);

        float sa = 0.0f, sb = 0.0f;
#pragma unroll
        for (int nt = 0; nt < 8; nt++) {
            p[nt][0] = __expf(p[nt][0] - mna);
            p[nt][1] = __expf(p[nt][1] - mna);
            p[nt][2] = __expf(p[nt][2] - mnb);
            p[nt][3] = __expf(p[nt][3] - mnb);
            sa += p[nt][0] + p[nt][1];
            sb += p[nt][2] + p[nt][3];
        }
        sa += __shfl_xor_sync(0xffffffffu, sa, 1);
        sa += __shfl_xor_sync(0xffffffffu, sa, 2);
        sb += __shfl_xor_sync(0xffffffffu, sb, 1);
        sb += __shfl_xor_sync(0xffffffffu, sb, 2);
        l_a = l_a * ca + sa;   m_a = mna;
        l_b = l_b * cbx + sb;  m_b = mnb;

#pragma unroll
        for (int nt = 0; nt < 8; nt++) {
            o[nt][0] *= ca;  o[nt][1] *= ca;
            o[nt][2] *= cbx; o[nt][3] *= cbx;
        }

        // P fragments: fp16 split (C-frag cols == A-frag k-pairs)
        unsigned pah[4][4], pal[4][4];
#pragma unroll
        for (int g = 0; g < 4; g++) {
            split2h(p[2*g][0],   p[2*g][1],   pah[g][0], pal[g][0]);
            split2h(p[2*g][2],   p[2*g][3],   pah[g][1], pal[g][1]);
            split2h(p[2*g+1][0], p[2*g+1][1], pah[g][2], pal[g][2]);
            split2h(p[2*g+1][2], p[2*g+1][3], pah[g][3], pal[g][3]);
        }

        // O += P V (fp16x2)
#pragma unroll
        for (int g = 0; g < 4; g++) {
            const int j0 = g * 16 + lc * 2;
#pragma unroll
            for (int nt = 0; nt < 8; nt++) {
                const int dcol = nt * 8 + lr;
                unsigned b0 = *(const unsigned*)&VS[dcol][j0];
                unsigned b1 = *(const unsigned*)&VS[dcol][j0 + 8];
                mma_fp16(o[nt], pah[g], b0, b1);
                mma_fp16(o[nt], pal[g], b0, b1);
            }
        }
    }

    // epilogue: normalize, write fp16 hi/lo att planes
    const float rla = 1.0f / l_a;
    const float rlb = 1.0f / l_b;
    const int b = bh >> 4;
    const int h = bh & 15;
    size_t oa = ((size_t)b * TT + grow_a) * CEMB + h * HS;
    size_t ob = ((size_t)b * TT + grow_b) * CEMB + h * HS;
#pragma unroll
    for (int nt = 0; nt < 8; nt++) {
        const int col = nt * 8 + lc * 2;
        unsigned hi, lo;
        split2h(o[nt][0] * rla, o[nt][1] * rla, hi, lo);
        *(unsigned*)(g_atth + oa + col) = hi;
        *(unsigned*)(g_attl + oa + col) = lo;
        split2h(o[nt][2] * rlb, o[nt][3] * rlb, hi, lo);
        *(unsigned*)(g_atth + ob + col) = hi;
        *(unsigned*)(g_attl + ob + col) = lo;
    }
}

// ---------------------------------------------------------------------------
extern "C" void kernel_launch(void* const* d_in, const int* in_sizes, int n_in,
                              void* d_out, int out_size)
{
    (void)in_sizes; (void)n_in; (void)out_size;
    const float* x  = (const float*)d_in[0];
    const float* Wq = (const float*)d_in[1];
    const float* Wk = (const float*)d_in[2];
    const float* Wv = (const float*)d_in[3];
    const float* Wp = (const float*)d_in[4];
    const float* bp = (const float*)d_in[5];
    float* out = (float*)d_out;

    cudaFuncSetAttribute(qkv_gemm,
        cudaFuncAttributeMaxDynamicSharedMemorySize, GM_SMEM);
    cudaFuncSetAttribute(proj_gemm,
        cudaFuncAttributeMaxDynamicSharedMemorySize, GM_SMEM);

    split_x<<<MTOT * CEMB / 4 / 256, 256>>>(x);
    split_transW<<<dim3(CEMB / 32, CEMB / 32, 4), 256>>>(Wq, Wk, Wv, Wp);
    prep_rope<<<TT * 32 / 256, 256>>>();

    qkv_gemm<<<dim3(CEMB / 128, MTOT / 128, 3), 256, GM_SMEM>>>();

    flash_fp16<<<dim3(TT / 128, BB * NHEAD), 256>>>();

    proj_gemm<<<dim3(CEMB / 128, MTOT / 128), 256, GM_SMEM>>>(bp, out);
}

// round 10
// speedup vs baseline: 1.5367x; 1.1861x over previous
#include <cuda_runtime.h>
#include <cuda_bf16.h>
#include <cuda_fp16.h>
#include <math.h>
#include <stdint.h>

#define NHEAD 16
#define HS    64
#define CEMB  1024
#define BB    4
#define TT    2048
#define MTOT  (BB*TT)          // 8192

// ---------------- device scratch (module-load allocated) -------------------
__device__ __align__(16) float g_q[(size_t)BB*NHEAD*TT*HS];
__device__ __align__(16) float2 g_rope[(size_t)TT*32];
__device__ __align__(16) __half g_kh[(size_t)BB*NHEAD*TT*HS];   // K fp16 [bh][t][d]
__device__ __align__(16) __half g_vt[(size_t)BB*NHEAD*TT*HS];   // V fp16 [bh][d][t]
__device__ __align__(16) __half g_xh[(size_t)MTOT*CEMB];        // x fp16 (single)
__device__ __align__(16) __half g_wt[(size_t)4*CEMB*CEMB];      // [mat][n][k]
__device__ __align__(16) __half g_atth[(size_t)MTOT*CEMB];      // att hi plane
__device__ __align__(16) __half g_attl[(size_t)MTOT*CEMB];      // att lo plane

// ---------------- helpers ---------------------------------------------------
__device__ __forceinline__ void mma_fp16(float c[4], const unsigned a[4],
                                         unsigned b0, unsigned b1) {
    asm volatile(
        "mma.sync.aligned.m16n8k16.row.col.f32.f16.f16.f32 "
        "{%0,%1,%2,%3}, {%4,%5,%6,%7}, {%8,%9}, {%0,%1,%2,%3};\n"
        : "+f"(c[0]), "+f"(c[1]), "+f"(c[2]), "+f"(c[3])
        : "r"(a[0]), "r"(a[1]), "r"(a[2]), "r"(a[3]),
          "r"(b0), "r"(b1));
}

__device__ __forceinline__ void ldsm4(unsigned r[4], uint32_t addr) {
    asm volatile(
        "ldmatrix.sync.aligned.m8n8.x4.shared.b16 {%0,%1,%2,%3}, [%4];"
        : "=r"(r[0]), "=r"(r[1]), "=r"(r[2]), "=r"(r[3]) : "r"(addr));
}

__device__ __forceinline__ unsigned pkh(__half x, __half y) {
    unsigned short a = *(unsigned short*)&x, b = *(unsigned short*)&y;
    return (unsigned)a | ((unsigned)b << 16);
}
__device__ __forceinline__ void split2h(float a, float b,
                                        unsigned &hi, unsigned &lo) {
    __half ah = __float2half_rn(a);
    __half bh = __float2half_rn(b);
    __half al = __float2half_rn(a - __half2float(ah));
    __half bl = __float2half_rn(b - __half2float(bh));
    hi = pkh(ah, bh);
    lo = pkh(al, bl);
}

__device__ __forceinline__ uint32_t smem_u32(const void* p) {
    uint32_t a;
    asm("{ .reg .u64 t; cvta.to.shared.u64 t, %1; cvt.u32.u64 %0, t; }"
        : "=r"(a) : "l"(p));
    return a;
}
__device__ __forceinline__ void cpa16(uint32_t dst, const void* src) {
    asm volatile("cp.async.cg.shared.global [%0], [%1], 16;\n"
                 :: "r"(dst), "l"(src));
}
#define CP_COMMIT() asm volatile("cp.async.commit_group;\n" ::: "memory")
#define CP_WAIT(n)  asm volatile("cp.async.wait_group %0;\n" :: "n"(n) : "memory")

// ---------------------------------------------------------------------------
// Prep kernels
// ---------------------------------------------------------------------------
__global__ void __launch_bounds__(256) round_x(const float* __restrict__ x)
{
    int i = blockIdx.x * 256 + threadIdx.x;
    float4 v = ((const float4*)x)[i];
    ((uint2*)g_xh)[i] = make_uint2(
        pkh(__float2half_rn(v.x), __float2half_rn(v.y)),
        pkh(__float2half_rn(v.z), __float2half_rn(v.w)));
}

__global__ void __launch_bounds__(256) split_transW(
    const float* __restrict__ Wq, const float* __restrict__ Wk,
    const float* __restrict__ Wv, const float* __restrict__ Wp)
{
    __shared__ float tile[32][33];
    const int z = blockIdx.z;
    const float* W = (z == 0) ? Wq : ((z == 1) ? Wk : ((z == 2) ? Wv : Wp));
    __half* outh = g_wt + (size_t)z * CEMB * CEMB;

    const int tx = threadIdx.x & 31;
    const int ty = threadIdx.x >> 5;
    const int k0 = blockIdx.y * 32;
    const int nn0 = blockIdx.x * 32;

#pragma unroll
    for (int j = 0; j < 4; j++)
        tile[ty + 8 * j][tx] = W[(size_t)(k0 + ty + 8 * j) * CEMB + nn0 + tx];
    __syncthreads();
#pragma unroll
    for (int j = 0; j < 4; j++) {
        float v = tile[tx][ty + 8 * j];
        outh[(size_t)(nn0 + ty + 8 * j) * CEMB + k0 + tx] = __float2half_rn(v);
    }
}

__global__ void __launch_bounds__(256) prep_rope()
{
    int idx = blockIdx.x * 256 + threadIdx.x;
    int t = idx >> 5, p = idx & 31;
    const float L2T = 13.287712379549449f / 64.0f;
    float inv = exp2f(-(float)(2 * p) * L2T);
    float sv, cv;
    sincosf((float)t * inv, &sv, &cv);
    g_rope[idx] = make_float2(cv, sv);
}

// ---------------------------------------------------------------------------
// fp16 x1 LDSM GEMM (for QKV): 128x128, BK=32, 2-stage. Planes: A 0, B 10240.
// ---------------------------------------------------------------------------
#define PL_B    10240
#define STG1_B  20480
#define GM1_SMEM (2 * STG1_B)  // 40960

__device__ __forceinline__ void gemm_main_x1(
    const __half* __restrict__ Ag, const __half* __restrict__ Bg,
    int m0, int n0, char* smp, float acc[2][8][4])
{
    const int tid  = threadIdx.x;
    const int warp = tid >> 5;
    const int lane = tid & 31;
    const int wm = warp >> 1;
    const int wn = warp & 1;
    const uint32_t sb = smem_u32(smp);

#pragma unroll
    for (int mt = 0; mt < 2; mt++)
#pragma unroll
        for (int nt = 0; nt < 8; nt++)
#pragma unroll
            for (int r = 0; r < 4; r++) acc[mt][nt][r] = 0.0f;

    // staging: 2 planes * 512 segs = 1024 / 256 thr = 4 per thread
    const __half* sp[4];
    uint32_t doff[4];
#pragma unroll
    for (int i = 0; i < 4; i++) {
        int g = i * 256 + tid;
        int pl = g >> 9;             // 0..1
        int r  = (g >> 2) & 127;
        int sg = g & 3;
        const __half* base = pl ? Bg : Ag;
        int rbase = pl ? n0 : m0;
        sp[i]   = base + (size_t)(rbase + r) * CEMB + sg * 8;
        doff[i] = (uint32_t)(pl * PL_B + r * 80 + sg * 16);
    }

#define GM1_ISSUE(CK, S) do {                                 \
    const int kb_ = (CK) * 32;                                \
    uint32_t st_ = sb + (S) * STG1_B;                         \
    _Pragma("unroll")                                         \
    for (int i = 0; i < 4; i++)                               \
        cpa16(st_ + doff[i], sp[i] + kb_);                    \
    CP_COMMIT();                                              \
} while (0)

    GM1_ISSUE(0, 0);

    const int a_row = lane & 15;
    const int a_kh  = lane >> 4;
    const uint32_t aoff = (uint32_t)((wm * 32 + a_row) * 80 + a_kh * 16);
    const int b_n  = ((lane >> 4) << 3) + (lane & 7);
    const int b_kh = (lane >> 3) & 1;
    const uint32_t boff = (uint32_t)(PL_B + (wn * 64 + b_n) * 80 + b_kh * 16);

    for (int ck = 0; ck < 32; ck++) {
        if (ck + 1 < 32) {
            GM1_ISSUE(ck + 1, (ck + 1) & 1);
            CP_WAIT(1);
        } else {
            CP_WAIT(0);
        }
        __syncthreads();

        const uint32_t st = sb + (ck & 1) * STG1_B;
#pragma unroll
        for (int kk = 0; kk < 2; kk++) {
            unsigned Ah[2][4];
#pragma unroll
            for (int mt = 0; mt < 2; mt++)
                ldsm4(Ah[mt], st + aoff + mt * 1280 + kk * 32);
#pragma unroll
            for (int ntp = 0; ntp < 4; ntp++) {
                unsigned Bh[4];
                ldsm4(Bh, st + boff + ntp * 1280 + kk * 32);
#pragma unroll
                for (int mt = 0; mt < 2; mt++) {
                    mma_fp16(acc[mt][ntp * 2 + 0], Ah[mt], Bh[0], Bh[1]);
                    mma_fp16(acc[mt][ntp * 2 + 1], Ah[mt], Bh[2], Bh[3]);
                }
            }
        }
        __syncthreads();
    }
#undef GM1_ISSUE
}

// ---------------------------------------------------------------------------
// fp16 x2 LDSM GEMM (for proj; validated round 8): planes Ah, Al, B.
// ---------------------------------------------------------------------------
#define STG2_B  30720
#define GM2_SMEM (2 * STG2_B)  // 61440

__device__ __forceinline__ void gemm_main_x2(
    const __half* __restrict__ Ahg, const __half* __restrict__ Alg,
    const __half* __restrict__ Bg,
    int m0, int n0, char* smp, float acc[2][8][4])
{
    const int tid  = threadIdx.x;
    const int warp = tid >> 5;
    const int lane = tid & 31;
    const int wm = warp >> 1;
    const int wn = warp & 1;
    const uint32_t sb = smem_u32(smp);

#pragma unroll
    for (int mt = 0; mt < 2; mt++)
#pragma unroll
        for (int nt = 0; nt < 8; nt++)
#pragma unroll
            for (int r = 0; r < 4; r++) acc[mt][nt][r] = 0.0f;

    const __half* sp[6];
    uint32_t doff[6];
#pragma unroll
    for (int i = 0; i < 6; i++) {
        int g = i * 256 + tid;
        int pl = g >> 9;
        int r  = (g >> 2) & 127;
        int sg = g & 3;
        const __half* base = (pl == 0) ? Ahg : ((pl == 1) ? Alg : Bg);
        int rbase = (pl < 2) ? m0 : n0;
        sp[i]   = base + (size_t)(rbase + r) * CEMB + sg * 8;
        doff[i] = (uint32_t)(pl * PL_B + r * 80 + sg * 16);
    }

#define GM2_ISSUE(CK, S) do {                                 \
    const int kb_ = (CK) * 32;                                \
    uint32_t st_ = sb + (S) * STG2_B;                         \
    _Pragma("unroll")                                         \
    for (int i = 0; i < 6; i++)                               \
        cpa16(st_ + doff[i], sp[i] + kb_);                    \
    CP_COMMIT();                                              \
} while (0)

    GM2_ISSUE(0, 0);

    const int a_row = lane & 15;
    const int a_kh  = lane >> 4;
    const uint32_t aoff = (uint32_t)((wm * 32 + a_row) * 80 + a_kh * 16);
    const int b_n  = ((lane >> 4) << 3) + (lane & 7);
    const int b_kh = (lane >> 3) & 1;
    const uint32_t boff = (uint32_t)(2 * PL_B + (wn * 64 + b_n) * 80 + b_kh * 16);

    for (int ck = 0; ck < 32; ck++) {
        if (ck + 1 < 32) {
            GM2_ISSUE(ck + 1, (ck + 1) & 1);
            CP_WAIT(1);
        } else {
            CP_WAIT(0);
        }
        __syncthreads();

        const uint32_t st = sb + (ck & 1) * STG2_B;
#pragma unroll
        for (int kk = 0; kk < 2; kk++) {
            unsigned Ah[2][4], Al[2][4];
#pragma unroll
            for (int mt = 0; mt < 2; mt++) {
                ldsm4(Ah[mt], st + aoff + mt * 1280 + kk * 32);
                ldsm4(Al[mt], st + PL_B + aoff + mt * 1280 + kk * 32);
            }
#pragma unroll
            for (int ntp = 0; ntp < 4; ntp++) {
                unsigned Bh[4];
                ldsm4(Bh, st + boff + ntp * 1280 + kk * 32);
#pragma unroll
                for (int mt = 0; mt < 2; mt++) {
                    mma_fp16(acc[mt][ntp * 2 + 0], Ah[mt], Bh[0], Bh[1]);
                    mma_fp16(acc[mt][ntp * 2 + 0], Al[mt], Bh[0], Bh[1]);
                    mma_fp16(acc[mt][ntp * 2 + 1], Ah[mt], Bh[2], Bh[3]);
                    mma_fp16(acc[mt][ntp * 2 + 1], Al[mt], Bh[2], Bh[3]);
                }
            }
        }
        __syncthreads();
    }
#undef GM2_ISSUE
}

// ---------------------------------------------------------------------------
// QKV (x1): mode 0=Q(+RoPE)->fp32 g_q, 1=K(+RoPE)->fp16 g_kh, 2=V->g_vt trans
// ---------------------------------------------------------------------------
__global__ void __launch_bounds__(256, 2) qkv_gemm()
{
    extern __shared__ char smp[];
    const int mode = blockIdx.z;
    const int m0 = blockIdx.y * 128;
    const int n0 = blockIdx.x * 128;

    float acc[2][8][4];
    gemm_main_x1(g_xh, g_wt + (size_t)mode * CEMB * CEMB, m0, n0, smp, acc);

    const int warp = threadIdx.x >> 5;
    const int lane = threadIdx.x & 31;
    const int wm = warp >> 1;
    const int wn = warp & 1;

#pragma unroll
    for (int mt = 0; mt < 2; mt++) {
        const int row_base = m0 + wm * 32 + mt * 16 + (lane >> 2);
#pragma unroll
        for (int nt = 0; nt < 8; nt++) {
            const int col = n0 + wn * 64 + nt * 8 + (lane & 3) * 2;
            const int h = col >> 6;
            const int d = col & 63;
#pragma unroll
            for (int half = 0; half < 2; half++) {
                const int row = row_base + half * 8;
                const int b = row >> 11;
                const int t = row & 2047;
                float x0 = acc[mt][nt][half * 2];
                float x1 = acc[mt][nt][half * 2 + 1];
                float o0 = x0, o1 = x1;
                if (mode < 2) {
                    float2 cs = g_rope[t * 32 + (d >> 1)];
                    o0 = x0 * cs.x - x1 * cs.y;
                    o1 = x0 * cs.y + x1 * cs.x;
                }
                const int bh = b * NHEAD + h;
                if (mode == 0) {
                    size_t base = ((size_t)bh * TT + t) * HS + d;
                    *(float2*)(g_q + base) = make_float2(o0, o1);
                } else if (mode == 1) {
                    size_t base = ((size_t)bh * TT + t) * HS + d;
                    *(unsigned*)(g_kh + base) =
                        pkh(__float2half_rn(o0), __float2half_rn(o1));
                } else {
                    size_t tb = ((size_t)bh * HS + d) * TT + t;
                    g_vt[tb]      = __float2half_rn(o0);
                    g_vt[tb + TT] = __float2half_rn(o1);
                }
            }
        }
    }
}

// ---------------------------------------------------------------------------
// Output projection (x2): att fp16 planes @ WpT fp16 + bias -> fp32 out
// ---------------------------------------------------------------------------
__global__ void __launch_bounds__(256, 2) proj_gemm(
    const float* __restrict__ bp, float* __restrict__ out)
{
    extern __shared__ char smp[];
    const int m0 = blockIdx.y * 128;
    const int n0 = blockIdx.x * 128;

    float acc[2][8][4];
    gemm_main_x2(g_atth, g_attl, g_wt + (size_t)3 * CEMB * CEMB,
                 m0, n0, smp, acc);

    const int warp = threadIdx.x >> 5;
    const int lane = threadIdx.x & 31;
    const int wm = warp >> 1;
    const int wn = warp & 1;

#pragma unroll
    for (int mt = 0; mt < 2; mt++) {
        const int row_base = m0 + wm * 32 + mt * 16 + (lane >> 2);
#pragma unroll
        for (int nt = 0; nt < 8; nt++) {
            const int col = n0 + wn * 64 + nt * 8 + (lane & 3) * 2;
            const float b0 = bp[col];
            const float b1 = bp[col + 1];
#pragma unroll
            for (int half = 0; half < 2; half++) {
                const int row = row_base + half * 8;
                *(float2*)(out + (size_t)row * CEMB + col) =
                    make_float2(acc[mt][nt][half * 2]     + b0,
                                acc[mt][nt][half * 2 + 1] + b1);
            }
        }
    }
}

// ---------------------------------------------------------------------------
// Flash attention, fp16x2 (validated round 9): BM=128 (8 warps), BN=64.
// ---------------------------------------------------------------------------
#define KVS 72

__global__ void __launch_bounds__(256) flash_fp16()
{
    __shared__ __half KS[64][KVS];
    __shared__ __half VS[64][KVS];   // [d][j]

    const int tid  = threadIdx.x;
    const int warp = tid >> 5;
    const int lane = tid & 31;
    const int qt   = gridDim.x - 1 - blockIdx.x;
    const int q0   = qt * 128;
    const int bh   = blockIdx.y;

    const float* Q = g_q + (size_t)bh * TT * HS;
    const __half* K = g_kh + (size_t)bh * TT * HS;
    const __half* V = g_vt + (size_t)bh * HS * TT;

    const int lr = lane >> 2;
    const int lc = lane & 3;
    const int lrow = warp * 16 + lr;
    const int grow_a = q0 + lrow;
    const int grow_b = grow_a + 8;

    unsigned qh[4][4], ql[4][4];
#pragma unroll
    for (int ks = 0; ks < 4; ks++) {
        const int kd = ks * 16 + lc * 2;
        const float* qa = Q + (size_t)grow_a * HS;
        const float* qb = Q + (size_t)grow_b * HS;
        float2 v0 = *(const float2*)(qa + kd);
        float2 v1 = *(const float2*)(qb + kd);
        float2 v2 = *(const float2*)(qa + kd + 8);
        float2 v3 = *(const float2*)(qb + kd + 8);
        split2h(v0.x * 0.125f, v0.y * 0.125f, qh[ks][0], ql[ks][0]);
        split2h(v1.x * 0.125f, v1.y * 0.125f, qh[ks][1], ql[ks][1]);
        split2h(v2.x * 0.125f, v2.y * 0.125f, qh[ks][2], ql[ks][2]);
        split2h(v3.x * 0.125f, v3.y * 0.125f, qh[ks][3], ql[ks][3]);
    }

    float o[8][4];
#pragma unroll
    for (int nt = 0; nt < 8; nt++)
#pragma unroll
        for (int r = 0; r < 4; r++) o[nt][r] = 0.0f;
    float m_a = -1e30f, m_b = -1e30f, l_a = 0.0f, l_b = 0.0f;

    const int nkt = 2 * qt + 2;
    for (int kt = 0; kt < nkt; kt++) {
        const int k0 = kt * 64;
        __syncthreads();
#pragma unroll
        for (int a = 0; a < 2; a++) {
            int s = a * 256 + tid;
            int j = s >> 3, dq = (s & 7) * 8;
            *(uint4*)&KS[j][dq] = *(const uint4*)(K + (size_t)(k0 + j) * HS + dq);
            *(uint4*)&VS[j][dq] = *(const uint4*)(V + (size_t)j * TT + k0 + dq);
        }
        __syncthreads();

        float p[8][4];
#pragma unroll
        for (int nt = 0; nt < 8; nt++)
#pragma unroll
            for (int r = 0; r < 4; r++) p[nt][r] = 0.0f;

#pragma unroll
        for (int ks = 0; ks < 4; ks++) {
            const int kd = ks * 16 + lc * 2;
#pragma unroll
            for (int nt = 0; nt < 8; nt++) {
                const int j = nt * 8 + lr;
                unsigned b0 = *(const unsigned*)&KS[j][kd];
                unsigned b1 = *(const unsigned*)&KS[j][kd + 8];
                mma_fp16(p[nt], qh[ks], b0, b1);
                mma_fp16(p[nt], ql[ks], b0, b1);
            }
        }

        if (kt + 2 >= nkt) {
#pragma unroll
            for (int nt = 0; nt < 8; nt++) {
                const int c = k0 + nt * 8 + lc * 2;
                if (c     > grow_a) p[nt][0] = -1e30f;
                if (c + 1 > grow_a) p[nt][1] = -1e30f;
                if (c     > grow_b) p[nt][2] = -1e30f;
                if (c + 1 > grow_b) p[nt][3] = -1e30f;
            }
        }

        float ma = -1e30f, mb2 = -1e30f;
#pragma unroll
        for (int nt = 0; nt < 8; nt++) {
            ma  = fmaxf(ma,  fmaxf(p[nt][0], p[nt][1]));
            mb2 = fmaxf(mb2, fmaxf(p[nt][2], p[nt][3]));
        }
        ma  = fmaxf(ma,  __shfl_xor_sync(0xffffffffu, ma, 1));
        ma  = fmaxf(ma,  __shfl_xor_sync(0xffffffffu, ma, 2));
        mb2 = fmaxf(mb2, __shfl_xor_sync(0xffffffffu, mb2, 1));
        mb2 = fmaxf(mb2, __shfl_xor_sync(0xffffffffu, mb2, 2));

        const float mna = fmaxf(m_a, ma);
        const float mnb = fmaxf(m_b, mb2);
        const float ca  = __expf(m_a - mna);
        const float cbx = __expf(m_b - mnb);

        float sa = 0.0f, sb = 0.0f;
#pragma unroll
        for (int nt = 0; nt < 8; nt++) {
            p[nt][0] = __expf(p[nt][0] - mna);
            p[nt][1] = __expf(p[nt][1] - mna);
            p[nt][2] = __expf(p[nt][2] - mnb);
            p[nt][3] = __expf(p[nt][3] - mnb);
            sa += p[nt][0] + p[nt][1];
            sb += p[nt][2] + p[nt][3];
        }
        sa += __shfl_xor_sync(0xffffffffu, sa, 1);
        sa += __shfl_xor_sync(0xffffffffu, sa, 2);
        sb += __shfl_xor_sync(0xffffffffu, sb, 1);
        sb += __shfl_xor_sync(0xffffffffu, sb, 2);
        l_a = l_a * ca + sa;   m_a = mna;
        l_b = l_b * cbx + sb;  m_b = mnb;

#pragma unroll
        for (int nt = 0; nt < 8; nt++) {
            o[nt][0] *= ca;  o[nt][1] *= ca;
            o[nt][2] *= cbx; o[nt][3] *= cbx;
        }

        unsigned pah[4][4], pal[4][4];
#pragma unroll
        for (int g = 0; g < 4; g++) {
            split2h(p[2*g][0],   p[2*g][1],   pah[g][0], pal[g][0]);
            split2h(p[2*g][2],   p[2*g][3],   pah[g][1], pal[g][1]);
            split2h(p[2*g+1][0], p[2*g+1][1], pah[g][2], pal[g][2]);
            split2h(p[2*g+1][2], p[2*g+1][3], pah[g][3], pal[g][3]);
        }

#pragma unroll
        for (int g = 0; g < 4; g++) {
            const int j0 = g * 16 + lc * 2;
#pragma unroll
            for (int nt = 0; nt < 8; nt++) {
                const int dcol = nt * 8 + lr;
                unsigned b0 = *(const unsigned*)&VS[dcol][j0];
                unsigned b1 = *(const unsigned*)&VS[dcol][j0 + 8];
                mma_fp16(o[nt], pah[g], b0, b1);
                mma_fp16(o[nt], pal[g], b0, b1);
            }
        }
    }

    const float rla = 1.0f / l_a;
    const float rlb = 1.0f / l_b;
    const int b = bh >> 4;
    const int h = bh & 15;
    size_t oa = ((size_t)b * TT + grow_a) * CEMB + h * HS;
    size_t ob = ((size_t)b * TT + grow_b) * CEMB + h * HS;
#pragma unroll
    for (int nt = 0; nt < 8; nt++) {
        const int col = nt * 8 + lc * 2;
        unsigned hi, lo;
        split2h(o[nt][0] * rla, o[nt][1] * rla, hi, lo);
        *(unsigned*)(g_atth + oa + col) = hi;
        *(unsigned*)(g_attl + oa + col) = lo;
        split2h(o[nt][2] * rlb, o[nt][3] * rlb, hi, lo);
        *(unsigned*)(g_atth + ob + col) = hi;
        *(unsigned*)(g_attl + ob + col) = lo;
    }
}

// ---------------------------------------------------------------------------
extern "C" void kernel_launch(void* const* d_in, const int* in_sizes, int n_in,
                              void* d_out, int out_size)
{
    (void)in_sizes; (void)n_in; (void)out_size;
    const float* x  = (const float*)d_in[0];
    const float* Wq = (const float*)d_in[1];
    const float* Wk = (const float*)d_in[2];
    const float* Wv = (const float*)d_in[3];
    const float* Wp = (const float*)d_in[4];
    const float* bp = (const float*)d_in[5];
    float* out = (float*)d_out;

    cudaFuncSetAttribute(qkv_gemm,
        cudaFuncAttributeMaxDynamicSharedMemorySize, GM1_SMEM);
    cudaFuncSetAttribute(proj_gemm,
        cudaFuncAttributeMaxDynamicSharedMemorySize, GM2_SMEM);

    round_x<<<MTOT * CEMB / 4 / 256, 256>>>(x);
    split_transW<<<dim3(CEMB / 32, CEMB / 32, 4), 256>>>(Wq, Wk, Wv, Wp);
    prep_rope<<<TT * 32 / 256, 256>>>();

    qkv_gemm<<<dim3(CEMB / 128, MTOT / 128, 3), 256, GM1_SMEM>>>();

    flash_fp16<<<dim3(TT / 128, BB * NHEAD), 256>>>();

    proj_gemm<<<dim3(CEMB / 128, MTOT / 128), 256, GM2_SMEM>>>(bp, out);
}

// round 11
// speedup vs baseline: 2.1208x; 1.3801x over previous
#include <cuda_runtime.h>
#include <cuda_bf16.h>
#include <cuda_fp16.h>
#include <math.h>
#include <stdint.h>

#define NHEAD 16
#define HS    64
#define CEMB  1024
#define BB    4
#define TT    2048
#define MTOT  (BB*TT)          // 8192

// ---------------- device scratch (module-load allocated) -------------------
__device__ __align__(16) float g_q[(size_t)BB*NHEAD*TT*HS];
__device__ __align__(16) float2 g_rope[(size_t)TT*32];
__device__ __align__(16) __half g_kh[(size_t)BB*NHEAD*TT*HS];   // K fp16 [bh][t][d]
__device__ __align__(16) __half g_vt[(size_t)BB*NHEAD*TT*HS];   // V fp16 [bh][d][t]
__device__ __align__(16) __half g_xh[(size_t)MTOT*CEMB];        // x fp16
__device__ __align__(16) __half g_wt[(size_t)4*CEMB*CEMB];      // [mat][n][k]
__device__ __align__(16) __half g_atth[(size_t)MTOT*CEMB];      // att hi plane
__device__ __align__(16) __half g_attl[(size_t)MTOT*CEMB];      // att lo plane

// ---------------- helpers ---------------------------------------------------
__device__ __forceinline__ void mma_fp16(float c[4], const unsigned a[4],
                                         unsigned b0, unsigned b1) {
    asm volatile(
        "mma.sync.aligned.m16n8k16.row.col.f32.f16.f16.f32 "
        "{%0,%1,%2,%3}, {%4,%5,%6,%7}, {%8,%9}, {%0,%1,%2,%3};\n"
        : "+f"(c[0]), "+f"(c[1]), "+f"(c[2]), "+f"(c[3])
        : "r"(a[0]), "r"(a[1]), "r"(a[2]), "r"(a[3]),
          "r"(b0), "r"(b1));
}

__device__ __forceinline__ void ldsm4(unsigned r[4], uint32_t addr) {
    asm volatile(
        "ldmatrix.sync.aligned.m8n8.x4.shared.b16 {%0,%1,%2,%3}, [%4];"
        : "=r"(r[0]), "=r"(r[1]), "=r"(r[2]), "=r"(r[3]) : "r"(addr));
}

__device__ __forceinline__ unsigned pkh(__half x, __half y) {
    unsigned short a = *(unsigned short*)&x, b = *(unsigned short*)&y;
    return (unsigned)a | ((unsigned)b << 16);
}
__device__ __forceinline__ unsigned pkh2f(float a, float b) {
    return pkh(__float2half_rn(a), __float2half_rn(b));
}
__device__ __forceinline__ void split2h(float a, float b,
                                        unsigned &hi, unsigned &lo) {
    __half ah = __float2half_rn(a);
    __half bh = __float2half_rn(b);
    __half al = __float2half_rn(a - __half2float(ah));
    __half bl = __float2half_rn(b - __half2float(bh));
    hi = pkh(ah, bh);
    lo = pkh(al, bl);
}

__device__ __forceinline__ uint32_t smem_u32(const void* p) {
    uint32_t a;
    asm("{ .reg .u64 t; cvta.to.shared.u64 t, %1; cvt.u32.u64 %0, t; }"
        : "=r"(a) : "l"(p));
    return a;
}
__device__ __forceinline__ void cpa16(uint32_t dst, const void* src) {
    asm volatile("cp.async.cg.shared.global [%0], [%1], 16;\n"
                 :: "r"(dst), "l"(src));
}
#define CP_COMMIT() asm volatile("cp.async.commit_group;\n" ::: "memory")
#define CP_WAIT(n)  asm volatile("cp.async.wait_group %0;\n" :: "n"(n) : "memory")

// ---------------------------------------------------------------------------
// Prep kernels
// ---------------------------------------------------------------------------
__global__ void __launch_bounds__(256) round_x(const float* __restrict__ x)
{
    int i = blockIdx.x * 256 + threadIdx.x;
    float4 v = ((const float4*)x)[i];
    ((uint2*)g_xh)[i] = make_uint2(pkh2f(v.x, v.y), pkh2f(v.z, v.w));
}

__global__ void __launch_bounds__(256) split_transW(
    const float* __restrict__ Wq, const float* __restrict__ Wk,
    const float* __restrict__ Wv, const float* __restrict__ Wp)
{
    __shared__ float tile[32][33];
    const int z = blockIdx.z;
    const float* W = (z == 0) ? Wq : ((z == 1) ? Wk : ((z == 2) ? Wv : Wp));
    __half* outh = g_wt + (size_t)z * CEMB * CEMB;

    const int tx = threadIdx.x & 31;
    const int ty = threadIdx.x >> 5;
    const int k0 = blockIdx.y * 32;
    const int nn0 = blockIdx.x * 32;

#pragma unroll
    for (int j = 0; j < 4; j++)
        tile[ty + 8 * j][tx] = W[(size_t)(k0 + ty + 8 * j) * CEMB + nn0 + tx];
    __syncthreads();
#pragma unroll
    for (int j = 0; j < 4; j++) {
        float v = tile[tx][ty + 8 * j];
        outh[(size_t)(nn0 + ty + 8 * j) * CEMB + k0 + tx] = __float2half_rn(v);
    }
}

__global__ void __launch_bounds__(256) prep_rope()
{
    int idx = blockIdx.x * 256 + threadIdx.x;
    int t = idx >> 5, p = idx & 31;
    const float L2T = 13.287712379549449f / 64.0f;
    float inv = exp2f(-(float)(2 * p) * L2T);
    float sv, cv;
    sincosf((float)t * inv, &sv, &cv);
    g_rope[idx] = make_float2(cv, sv);
}

// ---------------------------------------------------------------------------
// fp16 x1 LDSM GEMM (QKV; validated round 10)
// ---------------------------------------------------------------------------
#define PL_B    10240
#define STG1_B  20480
#define GM1_SMEM (2 * STG1_B)  // 40960

__device__ __forceinline__ void gemm_main_x1(
    const __half* __restrict__ Ag, const __half* __restrict__ Bg,
    int m0, int n0, char* smp, float acc[2][8][4])
{
    const int tid  = threadIdx.x;
    const int warp = tid >> 5;
    const int lane = tid & 31;
    const int wm = warp >> 1;
    const int wn = warp & 1;
    const uint32_t sb = smem_u32(smp);

#pragma unroll
    for (int mt = 0; mt < 2; mt++)
#pragma unroll
        for (int nt = 0; nt < 8; nt++)
#pragma unroll
            for (int r = 0; r < 4; r++) acc[mt][nt][r] = 0.0f;

    const __half* sp[4];
    uint32_t doff[4];
#pragma unroll
    for (int i = 0; i < 4; i++) {
        int g = i * 256 + tid;
        int pl = g >> 9;
        int r  = (g >> 2) & 127;
        int sg = g & 3;
        const __half* base = pl ? Bg : Ag;
        int rbase = pl ? n0 : m0;
        sp[i]   = base + (size_t)(rbase + r) * CEMB + sg * 8;
        doff[i] = (uint32_t)(pl * PL_B + r * 80 + sg * 16);
    }

#define GM1_ISSUE(CK, S) do {                                 \
    const int kb_ = (CK) * 32;                                \
    uint32_t st_ = sb + (S) * STG1_B;                         \
    _Pragma("unroll")                                         \
    for (int i = 0; i < 4; i++)                               \
        cpa16(st_ + doff[i], sp[i] + kb_);                    \
    CP_COMMIT();                                              \
} while (0)

    GM1_ISSUE(0, 0);

    const int a_row = lane & 15;
    const int a_kh  = lane >> 4;
    const uint32_t aoff = (uint32_t)((wm * 32 + a_row) * 80 + a_kh * 16);
    const int b_n  = ((lane >> 4) << 3) + (lane & 7);
    const int b_kh = (lane >> 3) & 1;
    const uint32_t boff = (uint32_t)(PL_B + (wn * 64 + b_n) * 80 + b_kh * 16);

    for (int ck = 0; ck < 32; ck++) {
        if (ck + 1 < 32) {
            GM1_ISSUE(ck + 1, (ck + 1) & 1);
            CP_WAIT(1);
        } else {
            CP_WAIT(0);
        }
        __syncthreads();

        const uint32_t st = sb + (ck & 1) * STG1_B;
#pragma unroll
        for (int kk = 0; kk < 2; kk++) {
            unsigned Ah[2][4];
#pragma unroll
            for (int mt = 0; mt < 2; mt++)
                ldsm4(Ah[mt], st + aoff + mt * 1280 + kk * 32);
#pragma unroll
            for (int ntp = 0; ntp < 4; ntp++) {
                unsigned Bh[4];
                ldsm4(Bh, st + boff + ntp * 1280 + kk * 32);
#pragma unroll
                for (int mt = 0; mt < 2; mt++) {
                    mma_fp16(acc[mt][ntp * 2 + 0], Ah[mt], Bh[0], Bh[1]);
                    mma_fp16(acc[mt][ntp * 2 + 1], Ah[mt], Bh[2], Bh[3]);
                }
            }
        }
        __syncthreads();
    }
#undef GM1_ISSUE
}

// ---------------------------------------------------------------------------
// fp16 x2 LDSM GEMM (proj; validated round 8)
// ---------------------------------------------------------------------------
#define STG2_B  30720
#define GM2_SMEM (2 * STG2_B)  // 61440

__device__ __forceinline__ void gemm_main_x2(
    const __half* __restrict__ Ahg, const __half* __restrict__ Alg,
    const __half* __restrict__ Bg,
    int m0, int n0, char* smp, float acc[2][8][4])
{
    const int tid  = threadIdx.x;
    const int warp = tid >> 5;
    const int lane = tid & 31;
    const int wm = warp >> 1;
    const int wn = warp & 1;
    const uint32_t sb = smem_u32(smp);

#pragma unroll
    for (int mt = 0; mt < 2; mt++)
#pragma unroll
        for (int nt = 0; nt < 8; nt++)
#pragma unroll
            for (int r = 0; r < 4; r++) acc[mt][nt][r] = 0.0f;

    const __half* sp[6];
    uint32_t doff[6];
#pragma unroll
    for (int i = 0; i < 6; i++) {
        int g = i * 256 + tid;
        int pl = g >> 9;
        int r  = (g >> 2) & 127;
        int sg = g & 3;
        const __half* base = (pl == 0) ? Ahg : ((pl == 1) ? Alg : Bg);
        int rbase = (pl < 2) ? m0 : n0;
        sp[i]   = base + (size_t)(rbase + r) * CEMB + sg * 8;
        doff[i] = (uint32_t)(pl * PL_B + r * 80 + sg * 16);
    }

#define GM2_ISSUE(CK, S) do {                                 \
    const int kb_ = (CK) * 32;                                \
    uint32_t st_ = sb + (S) * STG2_B;                         \
    _Pragma("unroll")                                         \
    for (int i = 0; i < 6; i++)                               \
        cpa16(st_ + doff[i], sp[i] + kb_);                    \
    CP_COMMIT();                                              \
} while (0)

    GM2_ISSUE(0, 0);

    const int a_row = lane & 15;
    const int a_kh  = lane >> 4;
    const uint32_t aoff = (uint32_t)((wm * 32 + a_row) * 80 + a_kh * 16);
    const int b_n  = ((lane >> 4) << 3) + (lane & 7);
    const int b_kh = (lane >> 3) & 1;
    const uint32_t boff = (uint32_t)(2 * PL_B + (wn * 64 + b_n) * 80 + b_kh * 16);

    for (int ck = 0; ck < 32; ck++) {
        if (ck + 1 < 32) {
            GM2_ISSUE(ck + 1, (ck + 1) & 1);
            CP_WAIT(1);
        } else {
            CP_WAIT(0);
        }
        __syncthreads();

        const uint32_t st = sb + (ck & 1) * STG2_B;
#pragma unroll
        for (int kk = 0; kk < 2; kk++) {
            unsigned Ah[2][4], Al[2][4];
#pragma unroll
            for (int mt = 0; mt < 2; mt++) {
                ldsm4(Ah[mt], st + aoff + mt * 1280 + kk * 32);
                ldsm4(Al[mt], st + PL_B + aoff + mt * 1280 + kk * 32);
            }
#pragma unroll
            for (int ntp = 0; ntp < 4; ntp++) {
                unsigned Bh[4];
                ldsm4(Bh, st + boff + ntp * 1280 + kk * 32);
#pragma unroll
                for (int mt = 0; mt < 2; mt++) {
                    mma_fp16(acc[mt][ntp * 2 + 0], Ah[mt], Bh[0], Bh[1]);
                    mma_fp16(acc[mt][ntp * 2 + 0], Al[mt], Bh[0], Bh[1]);
                    mma_fp16(acc[mt][ntp * 2 + 1], Ah[mt], Bh[2], Bh[3]);
                    mma_fp16(acc[mt][ntp * 2 + 1], Al[mt], Bh[2], Bh[3]);
                }
            }
        }
        __syncthreads();
    }
#undef GM2_ISSUE
}

// ---------------------------------------------------------------------------
// QKV (x1): mode 0=Q(+RoPE)->fp32 g_q, 1=K(+RoPE)->fp16 g_kh, 2=V->g_vt trans
// ---------------------------------------------------------------------------
__global__ void __launch_bounds__(256, 2) qkv_gemm()
{
    extern __shared__ char smp[];
    const int mode = blockIdx.z;
    const int m0 = blockIdx.y * 128;
    const int n0 = blockIdx.x * 128;

    float acc[2][8][4];
    gemm_main_x1(g_xh, g_wt + (size_t)mode * CEMB * CEMB, m0, n0, smp, acc);

    const int warp = threadIdx.x >> 5;
    const int lane = threadIdx.x & 31;
    const int wm = warp >> 1;
    const int wn = warp & 1;

#pragma unroll
    for (int mt = 0; mt < 2; mt++) {
        const int row_base = m0 + wm * 32 + mt * 16 + (lane >> 2);
#pragma unroll
        for (int nt = 0; nt < 8; nt++) {
            const int col = n0 + wn * 64 + nt * 8 + (lane & 3) * 2;
            const int h = col >> 6;
            const int d = col & 63;
#pragma unroll
            for (int half = 0; half < 2; half++) {
                const int row = row_base + half * 8;
                const int b = row >> 11;
                const int t = row & 2047;
                float x0 = acc[mt][nt][half * 2];
                float x1 = acc[mt][nt][half * 2 + 1];
                float o0 = x0, o1 = x1;
                if (mode < 2) {
                    float2 cs = g_rope[t * 32 + (d >> 1)];
                    o0 = x0 * cs.x - x1 * cs.y;
                    o1 = x0 * cs.y + x1 * cs.x;
                }
                const int bh = b * NHEAD + h;
                if (mode == 0) {
                    size_t base = ((size_t)bh * TT + t) * HS + d;
                    *(float2*)(g_q + base) = make_float2(o0, o1);
                } else if (mode == 1) {
                    size_t base = ((size_t)bh * TT + t) * HS + d;
                    *(unsigned*)(g_kh + base) = pkh2f(o0, o1);
                } else {
                    size_t tb = ((size_t)bh * HS + d) * TT + t;
                    g_vt[tb]      = __float2half_rn(o0);
                    g_vt[tb + TT] = __float2half_rn(o1);
                }
            }
        }
    }
}

// ---------------------------------------------------------------------------
// Output projection (x2)
// ---------------------------------------------------------------------------
__global__ void __launch_bounds__(256, 2) proj_gemm(
    const float* __restrict__ bp, float* __restrict__ out)
{
    extern __shared__ char smp[];
    const int m0 = blockIdx.y * 128;
    const int n0 = blockIdx.x * 128;

    float acc[2][8][4];
    gemm_main_x2(g_atth, g_attl, g_wt + (size_t)3 * CEMB * CEMB,
                 m0, n0, smp, acc);

    const int warp = threadIdx.x >> 5;
    const int lane = threadIdx.x & 31;
    const int wm = warp >> 1;
    const int wn = warp & 1;

#pragma unroll
    for (int mt = 0; mt < 2; mt++) {
        const int row_base = m0 + wm * 32 + mt * 16 + (lane >> 2);
#pragma unroll
        for (int nt = 0; nt < 8; nt++) {
            const int col = n0 + wn * 64 + nt * 8 + (lane & 3) * 2;
            const float b0 = bp[col];
            const float b1 = bp[col + 1];
#pragma unroll
            for (int half = 0; half < 2; half++) {
                const int row = row_base + half * 8;
                *(float2*)(out + (size_t)row * CEMB + col) =
                    make_float2(acc[mt][nt][half * 2]     + b0,
                                acc[mt][nt][half * 2 + 1] + b1);
            }
        }
    }
}

// ---------------------------------------------------------------------------
// Flash attention, fp16 x1 both stages, cp.async double-buffered K/V.
// BM=128 (8 warps x m16), BN=64, D=64.
// ---------------------------------------------------------------------------
#define KVS 72
#define KVROWB (KVS * 2)       // 144 bytes per smem row

__global__ void __launch_bounds__(256) flash_fp16()
{
    __shared__ __half KS[2][64][KVS];
    __shared__ __half VS[2][64][KVS];   // [d][j]

    const int tid  = threadIdx.x;
    const int warp = tid >> 5;
    const int lane = tid & 31;
    const int qt   = gridDim.x - 1 - blockIdx.x;   // big tiles first
    const int q0   = qt * 128;
    const int bh   = blockIdx.y;

    const float* Q = g_q + (size_t)bh * TT * HS;
    const __half* K = g_kh + (size_t)bh * TT * HS;
    const __half* V = g_vt + (size_t)bh * HS * TT;

    const uint32_t ks_base = smem_u32(&KS[0][0][0]);
    const uint32_t vs_base = smem_u32(&VS[0][0][0]);

    const int lr = lane >> 2;
    const int lc = lane & 3;
    const int lrow = warp * 16 + lr;
    const int grow_a = q0 + lrow;
    const int grow_b = grow_a + 8;

    // Q fragments: scaled, single fp16
    unsigned qh[4][4];
#pragma unroll
    for (int ks = 0; ks < 4; ks++) {
        const int kd = ks * 16 + lc * 2;
        const float* qa = Q + (size_t)grow_a * HS;
        const float* qb = Q + (size_t)grow_b * HS;
        float2 v0 = *(const float2*)(qa + kd);
        float2 v1 = *(const float2*)(qb + kd);
        float2 v2 = *(const float2*)(qa + kd + 8);
        float2 v3 = *(const float2*)(qb + kd + 8);
        qh[ks][0] = pkh2f(v0.x * 0.125f, v0.y * 0.125f);
        qh[ks][1] = pkh2f(v1.x * 0.125f, v1.y * 0.125f);
        qh[ks][2] = pkh2f(v2.x * 0.125f, v2.y * 0.125f);
        qh[ks][3] = pkh2f(v3.x * 0.125f, v3.y * 0.125f);
    }

    // staging geometry: K tile 512 segs + V tile 512 segs; 256 thr -> 2+2 each
    const int sj  = tid >> 3;            // 0..31 base row
    const int sdq = (tid & 7) * 8;       // half offset within row
    const uint32_t kdst0 = (uint32_t)(sj * KVROWB + sdq * 2);
    const uint32_t kdst1 = (uint32_t)((sj + 32) * KVROWB + sdq * 2);

#define FL_ISSUE(KT, S) do {                                            \
    const int k0_ = (KT) * 64;                                          \
    uint32_t kb_ = ks_base + (S) * 64 * KVROWB;                         \
    uint32_t vb_ = vs_base + (S) * 64 * KVROWB;                         \
    cpa16(kb_ + kdst0, K + (size_t)(k0_ + sj) * HS + sdq);              \
    cpa16(kb_ + kdst1, K + (size_t)(k0_ + sj + 32) * HS + sdq);         \
    cpa16(vb_ + kdst0, V + (size_t)sj * TT + k0_ + sdq);                \
    cpa16(vb_ + kdst1, V + (size_t)(sj + 32) * TT + k0_ + sdq);         \
    CP_COMMIT();                                                        \
} while (0)

    float o[8][4];
#pragma unroll
    for (int nt = 0; nt < 8; nt++)
#pragma unroll
        for (int r = 0; r < 4; r++) o[nt][r] = 0.0f;
    float m_a = -1e30f, m_b = -1e30f, l_a = 0.0f, l_b = 0.0f;

    const int nkt = 2 * qt + 2;
    FL_ISSUE(0, 0);

    for (int kt = 0; kt < nkt; kt++) {
        if (kt + 1 < nkt) {
            FL_ISSUE(kt + 1, (kt + 1) & 1);
            CP_WAIT(1);
        } else {
            CP_WAIT(0);
        }
        __syncthreads();

        const int s = kt & 1;
        const int k0 = kt * 64;

        // S = Q K^T (fp16 x1)
        float p[8][4];
#pragma unroll
        for (int nt = 0; nt < 8; nt++)
#pragma unroll
            for (int r = 0; r < 4; r++) p[nt][r] = 0.0f;

#pragma unroll
        for (int ks = 0; ks < 4; ks++) {
            const int kd = ks * 16 + lc * 2;
#pragma unroll
            for (int nt = 0; nt < 8; nt++) {
                const int j = nt * 8 + lr;
                unsigned b0 = *(const unsigned*)&KS[s][j][kd];
                unsigned b1 = *(const unsigned*)&KS[s][j][kd + 8];
                mma_fp16(p[nt], qh[ks], b0, b1);
            }
        }

        // causal mask (tiles intersecting the diagonal band)
        if (kt + 2 >= nkt) {
#pragma unroll
            for (int nt = 0; nt < 8; nt++) {
                const int c = k0 + nt * 8 + lc * 2;
                if (c     > grow_a) p[nt][0] = -1e30f;
                if (c + 1 > grow_a) p[nt][1] = -1e30f;
                if (c     > grow_b) p[nt][2] = -1e30f;
                if (c + 1 > grow_b) p[nt][3] = -1e30f;
            }
        }

        // online softmax
        float ma = -1e30f, mb2 = -1e30f;
#pragma unroll
        for (int nt = 0; nt < 8; nt++) {
            ma  = fmaxf(ma,  fmaxf(p[nt][0], p[nt][1]));
            mb2 = fmaxf(mb2, fmaxf(p[nt][2], p[nt][3]));
        }
        ma  = fmaxf(ma,  __shfl_xor_sync(0xffffffffu, ma, 1));
        ma  = fmaxf(ma,  __shfl_xor_sync(0xffffffffu, ma, 2));
        mb2 = fmaxf(mb2, __shfl_xor_sync(0xffffffffu, mb2, 1));
        mb2 = fmaxf(mb2, __shfl_xor_sync(0xffffffffu, mb2, 2));

        const float mna = fmaxf(m_a, ma);
        const float mnb = fmaxf(m_b, mb2);
        const float ca  = __expf(m_a - mna);
        const float cbx = __expf(m_b - mnb);

        float sa = 0.0f, sb = 0.0f;
#pragma unroll
        for (int nt = 0; nt < 8; nt++) {
            p[nt][0] = __expf(p[nt][0] - mna);
            p[nt][1] = __expf(p[nt][1] - mna);
            p[nt][2] = __expf(p[nt][2] - mnb);
            p[nt][3] = __expf(p[nt][3] - mnb);
            sa += p[nt][0] + p[nt][1];
            sb += p[nt][2] + p[nt][3];
        }
        sa += __shfl_xor_sync(0xffffffffu, sa, 1);
        sa += __shfl_xor_sync(0xffffffffu, sa, 2);
        sb += __shfl_xor_sync(0xffffffffu, sb, 1);
        sb += __shfl_xor_sync(0xffffffffu, sb, 2);
        l_a = l_a * ca + sa;   m_a = mna;
        l_b = l_b * cbx + sb;  m_b = mnb;

#pragma unroll
        for (int nt = 0; nt < 8; nt++) {
            o[nt][0] *= ca;  o[nt][1] *= ca;
            o[nt][2] *= cbx; o[nt][3] *= cbx;
        }

        // P fragments: single fp16 (C-frag cols == A-frag k-pairs)
        unsigned pa[4][4];
#pragma unroll
        for (int g = 0; g < 4; g++) {
            pa[g][0] = pkh2f(p[2*g][0],   p[2*g][1]);
            pa[g][1] = pkh2f(p[2*g][2],   p[2*g][3]);
            pa[g][2] = pkh2f(p[2*g+1][0], p[2*g+1][1]);
            pa[g][3] = pkh2f(p[2*g+1][2], p[2*g+1][3]);
        }

        // O += P V (fp16 x1)
#pragma unroll
        for (int g = 0; g < 4; g++) {
            const int j0 = g * 16 + lc * 2;
#pragma unroll
            for (int nt = 0; nt < 8; nt++) {
                const int dcol = nt * 8 + lr;
                unsigned b0 = *(const unsigned*)&VS[s][dcol][j0];
                unsigned b1 = *(const unsigned*)&VS[s][dcol][j0 + 8];
                mma_fp16(o[nt], pa[g], b0, b1);
            }
        }
        __syncthreads();
    }
#undef FL_ISSUE

    // epilogue: normalize, write fp16 hi/lo att planes
    const float rla = 1.0f / l_a;
    const float rlb = 1.0f / l_b;
    const int b = bh >> 4;
    const int h = bh & 15;
    size_t oa = ((size_t)b * TT + grow_a) * CEMB + h * HS;
    size_t ob = ((size_t)b * TT + grow_b) * CEMB + h * HS;
#pragma unroll
    for (int nt = 0; nt < 8; nt++) {
        const int col = nt * 8 + lc * 2;
        unsigned hi, lo;
        split2h(o[nt][0] * rla, o[nt][1] * rla, hi, lo);
        *(unsigned*)(g_atth + oa + col) = hi;
        *(unsigned*)(g_attl + oa + col) = lo;
        split2h(o[nt][2] * rlb, o[nt][3] * rlb, hi, lo);
        *(unsigned*)(g_atth + ob + col) = hi;
        *(unsigned*)(g_attl + ob + col) = lo;
    }
}

// ---------------------------------------------------------------------------
extern "C" void kernel_launch(void* const* d_in, const int* in_sizes, int n_in,
                              void* d_out, int out_size)
{
    (void)in_sizes; (void)n_in; (void)out_size;
    const float* x  = (const float*)d_in[0];
    const float* Wq = (const float*)d_in[1];
    const float* Wk = (const float*)d_in[2];
    const float* Wv = (const float*)d_in[3];
    const float* Wp = (const float*)d_in[4];
    const float* bp = (const float*)d_in[5];
    float* out = (float*)d_out;

    cudaFuncSetAttribute(qkv_gemm,
        cudaFuncAttributeMaxDynamicSharedMemorySize, GM1_SMEM);
    cudaFuncSetAttribute(proj_gemm,
        cudaFuncAttributeMaxDynamicSharedMemorySize, GM2_SMEM);

    round_x<<<MTOT * CEMB / 4 / 256, 256>>>(x);
    split_transW<<<dim3(CEMB / 32, CEMB / 32, 4), 256>>>(Wq, Wk, Wv, Wp);
    prep_rope<<<TT * 32 / 256, 256>>>();

    qkv_gemm<<<dim3(CEMB / 128, MTOT / 128, 3), 256, GM1_SMEM>>>();

    flash_fp16<<<dim3(TT / 128, BB * NHEAD), 256>>>();

    proj_gemm<<<dim3(CEMB / 128, MTOT / 128), 256, GM2_SMEM>>>(bp, out);
}

// round 12
// speedup vs baseline: 2.4319x; 1.1467x over previous
#include <cuda_runtime.h>
#include <cuda_bf16.h>
#include <cuda_fp16.h>
#include <math.h>
#include <stdint.h>

#define NHEAD 16
#define HS    64
#define CEMB  1024
#define BB    4
#define TT    2048
#define MTOT  (BB*TT)          // 8192

// ---------------- device scratch (module-load allocated) -------------------
__device__ __align__(16) float g_q[(size_t)BB*NHEAD*TT*HS];
__device__ __align__(16) float2 g_rope[(size_t)TT*32];
__device__ __align__(16) __half g_kh[(size_t)BB*NHEAD*TT*HS];   // K fp16 [bh][t][d]
__device__ __align__(16) __half g_vt[(size_t)BB*NHEAD*TT*HS];   // V fp16 [bh][d][t]
__device__ __align__(16) __half g_xh[(size_t)MTOT*CEMB];        // x fp16
__device__ __align__(16) __half g_wt[(size_t)4*CEMB*CEMB];      // [mat][n][k]
__device__ __align__(16) __half g_att[(size_t)MTOT*CEMB];       // att fp16

// ---------------- helpers ---------------------------------------------------
__device__ __forceinline__ void mma_fp16(float c[4], const unsigned a[4],
                                         unsigned b0, unsigned b1) {
    asm volatile(
        "mma.sync.aligned.m16n8k16.row.col.f32.f16.f16.f32 "
        "{%0,%1,%2,%3}, {%4,%5,%6,%7}, {%8,%9}, {%0,%1,%2,%3};\n"
        : "+f"(c[0]), "+f"(c[1]), "+f"(c[2]), "+f"(c[3])
        : "r"(a[0]), "r"(a[1]), "r"(a[2]), "r"(a[3]),
          "r"(b0), "r"(b1));
}

__device__ __forceinline__ void ldsm4(unsigned r[4], uint32_t addr) {
    asm volatile(
        "ldmatrix.sync.aligned.m8n8.x4.shared.b16 {%0,%1,%2,%3}, [%4];"
        : "=r"(r[0]), "=r"(r[1]), "=r"(r[2]), "=r"(r[3]) : "r"(addr));
}

__device__ __forceinline__ unsigned pkh(__half x, __half y) {
    unsigned short a = *(unsigned short*)&x, b = *(unsigned short*)&y;
    return (unsigned)a | ((unsigned)b << 16);
}
__device__ __forceinline__ unsigned pkh2f(float a, float b) {
    return pkh(__float2half_rn(a), __float2half_rn(b));
}

__device__ __forceinline__ uint32_t smem_u32(const void* p) {
    uint32_t a;
    asm("{ .reg .u64 t; cvta.to.shared.u64 t, %1; cvt.u32.u64 %0, t; }"
        : "=r"(a) : "l"(p));
    return a;
}
__device__ __forceinline__ void cpa16(uint32_t dst, const void* src) {
    asm volatile("cp.async.cg.shared.global [%0], [%1], 16;\n"
                 :: "r"(dst), "l"(src));
}
#define CP_COMMIT() asm volatile("cp.async.commit_group;\n" ::: "memory")
#define CP_WAIT(n)  asm volatile("cp.async.wait_group %0;\n" :: "n"(n) : "memory")

// ---------------------------------------------------------------------------
// Prep kernels
// ---------------------------------------------------------------------------
__global__ void __launch_bounds__(256) round_x(const float* __restrict__ x)
{
    int i = blockIdx.x * 256 + threadIdx.x;
    float4 v = ((const float4*)x)[i];
    ((uint2*)g_xh)[i] = make_uint2(pkh2f(v.x, v.y), pkh2f(v.z, v.w));
}

__global__ void __launch_bounds__(256) split_transW(
    const float* __restrict__ Wq, const float* __restrict__ Wk,
    const float* __restrict__ Wv, const float* __restrict__ Wp)
{
    __shared__ float tile[32][33];
    const int z = blockIdx.z;
    const float* W = (z == 0) ? Wq : ((z == 1) ? Wk : ((z == 2) ? Wv : Wp));
    __half* outh = g_wt + (size_t)z * CEMB * CEMB;

    const int tx = threadIdx.x & 31;
    const int ty = threadIdx.x >> 5;
    const int k0 = blockIdx.y * 32;
    const int nn0 = blockIdx.x * 32;

#pragma unroll
    for (int j = 0; j < 4; j++)
        tile[ty + 8 * j][tx] = W[(size_t)(k0 + ty + 8 * j) * CEMB + nn0 + tx];
    __syncthreads();
#pragma unroll
    for (int j = 0; j < 4; j++) {
        float v = tile[tx][ty + 8 * j];
        outh[(size_t)(nn0 + ty + 8 * j) * CEMB + k0 + tx] = __float2half_rn(v);
    }
}

__global__ void __launch_bounds__(256) prep_rope()
{
    int idx = blockIdx.x * 256 + threadIdx.x;
    int t = idx >> 5, p = idx & 31;
    const float L2T = 13.287712379549449f / 64.0f;
    float inv = exp2f(-(float)(2 * p) * L2T);
    float sv, cv;
    sincosf((float)t * inv, &sv, &cv);
    g_rope[idx] = make_float2(cv, sv);
}

// ---------------------------------------------------------------------------
// fp16 x1 LDSM GEMM, 3-stage cp.async, ONE barrier per chunk.
// 128x128 tile, BK=32, 256 threads (8 warps, 4x2 of 32x64).
// Stage: A plane 0..10239, B plane 10240..20479.
// Safety: barrier at iter ck guarantees compute(ck-1) done for all warps;
// issue(ck+2) targets stage (ck+2)%3 == (ck-1)%3 whose readers all finished.
// ---------------------------------------------------------------------------
#define PL_B    10240
#define STG1_B  20480
#define GM1_SMEM (3 * STG1_B)  // 61440

__device__ __forceinline__ void gemm_main_x1(
    const __half* __restrict__ Ag, const __half* __restrict__ Bg,
    int m0, int n0, char* smp, float acc[2][8][4])
{
    const int tid  = threadIdx.x;
    const int warp = tid >> 5;
    const int lane = tid & 31;
    const int wm = warp >> 1;
    const int wn = warp & 1;
    const uint32_t sb = smem_u32(smp);

#pragma unroll
    for (int mt = 0; mt < 2; mt++)
#pragma unroll
        for (int nt = 0; nt < 8; nt++)
#pragma unroll
            for (int r = 0; r < 4; r++) acc[mt][nt][r] = 0.0f;

    const __half* sp[4];
    uint32_t doff[4];
#pragma unroll
    for (int i = 0; i < 4; i++) {
        int g = i * 256 + tid;
        int pl = g >> 9;
        int r  = (g >> 2) & 127;
        int sg = g & 3;
        const __half* base = pl ? Bg : Ag;
        int rbase = pl ? n0 : m0;
        sp[i]   = base + (size_t)(rbase + r) * CEMB + sg * 8;
        doff[i] = (uint32_t)(pl * PL_B + r * 80 + sg * 16);
    }

#define GM1_ISSUE(CK, S) do {                                 \
    const int kb_ = (CK) * 32;                                \
    uint32_t st_ = sb + (S) * STG1_B;                         \
    _Pragma("unroll")                                         \
    for (int i = 0; i < 4; i++)                               \
        cpa16(st_ + doff[i], sp[i] + kb_);                    \
    CP_COMMIT();                                              \
} while (0)

    GM1_ISSUE(0, 0);
    GM1_ISSUE(1, 1);

    const int a_row = lane & 15;
    const int a_kh  = lane >> 4;
    const uint32_t aoff = (uint32_t)((wm * 32 + a_row) * 80 + a_kh * 16);
    const int b_n  = ((lane >> 4) << 3) + (lane & 7);
    const int b_kh = (lane >> 3) & 1;
    const uint32_t boff = (uint32_t)(PL_B + (wn * 64 + b_n) * 80 + b_kh * 16);

    int stage = 0;   // = ck % 3
    for (int ck = 0; ck < 32; ck++) {
        if (ck + 1 < 32) CP_WAIT(1); else CP_WAIT(0);
        __syncthreads();

        if (ck + 2 < 32) {
            int s2 = stage + 2; if (s2 >= 3) s2 -= 3;
            GM1_ISSUE(ck + 2, s2);
        }

        const uint32_t st = sb + stage * STG1_B;
#pragma unroll
        for (int kk = 0; kk < 2; kk++) {
            unsigned Ah[2][4];
#pragma unroll
            for (int mt = 0; mt < 2; mt++)
                ldsm4(Ah[mt], st + aoff + mt * 1280 + kk * 32);
#pragma unroll
            for (int ntp = 0; ntp < 4; ntp++) {
                unsigned Bh[4];
                ldsm4(Bh, st + boff + ntp * 1280 + kk * 32);
#pragma unroll
                for (int mt = 0; mt < 2; mt++) {
                    mma_fp16(acc[mt][ntp * 2 + 0], Ah[mt], Bh[0], Bh[1]);
                    mma_fp16(acc[mt][ntp * 2 + 1], Ah[mt], Bh[2], Bh[3]);
                }
            }
        }
        if (++stage == 3) stage = 0;
    }
#undef GM1_ISSUE
}

// ---------------------------------------------------------------------------
// QKV (x1): mode 0=Q(+RoPE)->fp32 g_q, 1=K(+RoPE)->fp16 g_kh, 2=V->g_vt trans
// ---------------------------------------------------------------------------
__global__ void __launch_bounds__(256, 2) qkv_gemm()
{
    extern __shared__ char smp[];
    const int mode = blockIdx.z;
    const int m0 = blockIdx.y * 128;
    const int n0 = blockIdx.x * 128;

    float acc[2][8][4];
    gemm_main_x1(g_xh, g_wt + (size_t)mode * CEMB * CEMB, m0, n0, smp, acc);

    const int warp = threadIdx.x >> 5;
    const int lane = threadIdx.x & 31;
    const int wm = warp >> 1;
    const int wn = warp & 1;

#pragma unroll
    for (int mt = 0; mt < 2; mt++) {
        const int row_base = m0 + wm * 32 + mt * 16 + (lane >> 2);
#pragma unroll
        for (int nt = 0; nt < 8; nt++) {
            const int col = n0 + wn * 64 + nt * 8 + (lane & 3) * 2;
            const int h = col >> 6;
            const int d = col & 63;
#pragma unroll
            for (int half = 0; half < 2; half++) {
                const int row = row_base + half * 8;
                const int b = row >> 11;
                const int t = row & 2047;
                float x0 = acc[mt][nt][half * 2];
                float x1 = acc[mt][nt][half * 2 + 1];
                float o0 = x0, o1 = x1;
                if (mode < 2) {
                    float2 cs = g_rope[t * 32 + (d >> 1)];
                    o0 = x0 * cs.x - x1 * cs.y;
                    o1 = x0 * cs.y + x1 * cs.x;
                }
                const int bh = b * NHEAD + h;
                if (mode == 0) {
                    size_t base = ((size_t)bh * TT + t) * HS + d;
                    *(float2*)(g_q + base) = make_float2(o0, o1);
                } else if (mode == 1) {
                    size_t base = ((size_t)bh * TT + t) * HS + d;
                    *(unsigned*)(g_kh + base) = pkh2f(o0, o1);
                } else {
                    size_t tb = ((size_t)bh * HS + d) * TT + t;
                    g_vt[tb]      = __float2half_rn(o0);
                    g_vt[tb + TT] = __float2half_rn(o1);
                }
            }
        }
    }
}

// ---------------------------------------------------------------------------
// Output projection (x1): att fp16 @ WpT fp16 + bias -> fp32 out
// ---------------------------------------------------------------------------
__global__ void __launch_bounds__(256, 2) proj_gemm(
    const float* __restrict__ bp, float* __restrict__ out)
{
    extern __shared__ char smp[];
    const int m0 = blockIdx.y * 128;
    const int n0 = blockIdx.x * 128;

    float acc[2][8][4];
    gemm_main_x1(g_att, g_wt + (size_t)3 * CEMB * CEMB, m0, n0, smp, acc);

    const int warp = threadIdx.x >> 5;
    const int lane = threadIdx.x & 31;
    const int wm = warp >> 1;
    const int wn = warp & 1;

#pragma unroll
    for (int mt = 0; mt < 2; mt++) {
        const int row_base = m0 + wm * 32 + mt * 16 + (lane >> 2);
#pragma unroll
        for (int nt = 0; nt < 8; nt++) {
            const int col = n0 + wn * 64 + nt * 8 + (lane & 3) * 2;
            const float b0 = bp[col];
            const float b1 = bp[col + 1];
#pragma unroll
            for (int half = 0; half < 2; half++) {
                const int row = row_base + half * 8;
                *(float2*)(out + (size_t)row * CEMB + col) =
                    make_float2(acc[mt][nt][half * 2]     + b0,
                                acc[mt][nt][half * 2 + 1] + b1);
            }
        }
    }
}

// ---------------------------------------------------------------------------
// Flash attention, fp16 x1 both stages, cp.async double-buffered K/V
// (validated round 11). BM=128 (8 warps x m16), BN=64, D=64.
// ---------------------------------------------------------------------------
#define KVS 72
#define KVROWB (KVS * 2)       // 144 bytes per smem row

__global__ void __launch_bounds__(256) flash_fp16()
{
    __shared__ __half KS[2][64][KVS];
    __shared__ __half VS[2][64][KVS];   // [d][j]

    const int tid  = threadIdx.x;
    const int warp = tid >> 5;
    const int lane = tid & 31;
    const int qt   = gridDim.x - 1 - blockIdx.x;   // big tiles first
    const int q0   = qt * 128;
    const int bh   = blockIdx.y;

    const float* Q = g_q + (size_t)bh * TT * HS;
    const __half* K = g_kh + (size_t)bh * TT * HS;
    const __half* V = g_vt + (size_t)bh * HS * TT;

    const uint32_t ks_base = smem_u32(&KS[0][0][0]);
    const uint32_t vs_base = smem_u32(&VS[0][0][0]);

    const int lr = lane >> 2;
    const int lc = lane & 3;
    const int lrow = warp * 16 + lr;
    const int grow_a = q0 + lrow;
    const int grow_b = grow_a + 8;

    unsigned qh[4][4];
#pragma unroll
    for (int ks = 0; ks < 4; ks++) {
        const int kd = ks * 16 + lc * 2;
        const float* qa = Q + (size_t)grow_a * HS;
        const float* qb = Q + (size_t)grow_b * HS;
        float2 v0 = *(const float2*)(qa + kd);
        float2 v1 = *(const float2*)(qb + kd);
        float2 v2 = *(const float2*)(qa + kd + 8);
        float2 v3 = *(const float2*)(qb + kd + 8);
        qh[ks][0] = pkh2f(v0.x * 0.125f, v0.y * 0.125f);
        qh[ks][1] = pkh2f(v1.x * 0.125f, v1.y * 0.125f);
        qh[ks][2] = pkh2f(v2.x * 0.125f, v2.y * 0.125f);
        qh[ks][3] = pkh2f(v3.x * 0.125f, v3.y * 0.125f);
    }

    const int sj  = tid >> 3;
    const int sdq = (tid & 7) * 8;
    const uint32_t kdst0 = (uint32_t)(sj * KVROWB + sdq * 2);
    const uint32_t kdst1 = (uint32_t)((sj + 32) * KVROWB + sdq * 2);

#define FL_ISSUE(KT, S) do {                                            \
    const int k0_ = (KT) * 64;                                          \
    uint32_t kb_ = ks_base + (S) * 64 * KVROWB;                         \
    uint32_t vb_ = vs_base + (S) * 64 * KVROWB;                         \
    cpa16(kb_ + kdst0, K + (size_t)(k0_ + sj) * HS + sdq);              \
    cpa16(kb_ + kdst1, K + (size_t)(k0_ + sj + 32) * HS + sdq);         \
    cpa16(vb_ + kdst0, V + (size_t)sj * TT + k0_ + sdq);                \
    cpa16(vb_ + kdst1, V + (size_t)(sj + 32) * TT + k0_ + sdq);         \
    CP_COMMIT();                                                        \
} while (0)

    float o[8][4];
#pragma unroll
    for (int nt = 0; nt < 8; nt++)
#pragma unroll
        for (int r = 0; r < 4; r++) o[nt][r] = 0.0f;
    float m_a = -1e30f, m_b = -1e30f, l_a = 0.0f, l_b = 0.0f;

    const int nkt = 2 * qt + 2;
    FL_ISSUE(0, 0);

    for (int kt = 0; kt < nkt; kt++) {
        if (kt + 1 < nkt) {
            FL_ISSUE(kt + 1, (kt + 1) & 1);
            CP_WAIT(1);
        } else {
            CP_WAIT(0);
        }
        __syncthreads();

        const int s = kt & 1;
        const int k0 = kt * 64;

        float p[8][4];
#pragma unroll
        for (int nt = 0; nt < 8; nt++)
#pragma unroll
            for (int r = 0; r < 4; r++) p[nt][r] = 0.0f;

#pragma unroll
        for (int ks = 0; ks < 4; ks++) {
            const int kd = ks * 16 + lc * 2;
#pragma unroll
            for (int nt = 0; nt < 8; nt++) {
                const int j = nt * 8 + lr;
                unsigned b0 = *(const unsigned*)&KS[s][j][kd];
                unsigned b1 = *(const unsigned*)&KS[s][j][kd + 8];
                mma_fp16(p[nt], qh[ks], b0, b1);
            }
        }

        if (kt + 2 >= nkt) {
#pragma unroll
            for (int nt = 0; nt < 8; nt++) {
                const int c = k0 + nt * 8 + lc * 2;
                if (c     > grow_a) p[nt][0] = -1e30f;
                if (c + 1 > grow_a) p[nt][1] = -1e30f;
                if (c     > grow_b) p[nt][2] = -1e30f;
                if (c + 1 > grow_b) p[nt][3] = -1e30f;
            }
        }

        float ma = -1e30f, mb2 = -1e30f;
#pragma unroll
        for (int nt = 0; nt < 8; nt++) {
            ma  = fmaxf(ma,  fmaxf(p[nt][0], p[nt][1]));
            mb2 = fmaxf(mb2, fmaxf(p[nt][2], p[nt][3]));
        }
        ma  = fmaxf(ma,  __shfl_xor_sync(0xffffffffu, ma, 1));
        ma  = fmaxf(ma,  __shfl_xor_sync(0xffffffffu, ma, 2));
        mb2 = fmaxf(mb2, __shfl_xor_sync(0xffffffffu, mb2, 1));
        mb2 = fmaxf(mb2, __shfl_xor_sync(0xffffffffu, mb2, 2));

        const float mna = fmaxf(m_a, ma);
        const float mnb = fmaxf(m_b, mb2);
        const float ca  = __expf(m_a - mna);
        const float cbx = __expf(m_b - mnb);

        float sa = 0.0f, sb = 0.0f;
#pragma unroll
        for (int nt = 0; nt < 8; nt++) {
            p[nt][0] = __expf(p[nt][0] - mna);
            p[nt][1] = __expf(p[nt][1] - mna);
            p[nt][2] = __expf(p[nt][2] - mnb);
            p[nt][3] = __expf(p[nt][3] - mnb);
            sa += p[nt][0] + p[nt][1];
            sb += p[nt][2] + p[nt][3];
        }
        sa += __shfl_xor_sync(0xffffffffu, sa, 1);
        sa += __shfl_xor_sync(0xffffffffu, sa, 2);
        sb += __shfl_xor_sync(0xffffffffu, sb, 1);
        sb += __shfl_xor_sync(0xffffffffu, sb, 2);
        l_a = l_a * ca + sa;   m_a = mna;
        l_b = l_b * cbx + sb;  m_b = mnb;

#pragma unroll
        for (int nt = 0; nt < 8; nt++) {
            o[nt][0] *= ca;  o[nt][1] *= ca;
            o[nt][2] *= cbx; o[nt][3] *= cbx;
        }

        unsigned pa[4][4];
#pragma unroll
        for (int g = 0; g < 4; g++) {
            pa[g][0] = pkh2f(p[2*g][0],   p[2*g][1]);
            pa[g][1] = pkh2f(p[2*g][2],   p[2*g][3]);
            pa[g][2] = pkh2f(p[2*g+1][0], p[2*g+1][1]);
            pa[g][3] = pkh2f(p[2*g+1][2], p[2*g+1][3]);
        }

#pragma unroll
        for (int g = 0; g < 4; g++) {
            const int j0 = g * 16 + lc * 2;
#pragma unroll
            for (int nt = 0; nt < 8; nt++) {
                const int dcol = nt * 8 + lr;
                unsigned b0 = *(const unsigned*)&VS[s][dcol][j0];
                unsigned b1 = *(const unsigned*)&VS[s][dcol][j0 + 8];
                mma_fp16(o[nt], pa[g], b0, b1);
            }
        }
        __syncthreads();
    }
#undef FL_ISSUE

    // epilogue: normalize, write single fp16 att plane
    const float rla = 1.0f / l_a;
    const float rlb = 1.0f / l_b;
    const int b = bh >> 4;
    const int h = bh & 15;
    size_t oa = ((size_t)b * TT + grow_a) * CEMB + h * HS;
    size_t ob = ((size_t)b * TT + grow_b) * CEMB + h * HS;
#pragma unroll
    for (int nt = 0; nt < 8; nt++) {
        const int col = nt * 8 + lc * 2;
        *(unsigned*)(g_att + oa + col) = pkh2f(o[nt][0] * rla, o[nt][1] * rla);
        *(unsigned*)(g_att + ob + col) = pkh2f(o[nt][2] * rlb, o[nt][3] * rlb);
    }
}

// ---------------------------------------------------------------------------
extern "C" void kernel_launch(void* const* d_in, const int* in_sizes, int n_in,
                              void* d_out, int out_size)
{
    (void)in_sizes; (void)n_in; (void)out_size;
    const float* x  = (const float*)d_in[0];
    const float* Wq = (const float*)d_in[1];
    const float* Wk = (const float*)d_in[2];
    const float* Wv = (const float*)d_in[3];
    const float* Wp = (const float*)d_in[4];
    const float* bp = (const float*)d_in[5];
    float* out = (float*)d_out;

    cudaFuncSetAttribute(qkv_gemm,
        cudaFuncAttributeMaxDynamicSharedMemorySize, GM1_SMEM);
    cudaFuncSetAttribute(proj_gemm,
        cudaFuncAttributeMaxDynamicSharedMemorySize, GM1_SMEM);

    round_x<<<MTOT * CEMB / 4 / 256, 256>>>(x);
    split_transW<<<dim3(CEMB / 32, CEMB / 32, 4), 256>>>(Wq, Wk, Wv, Wp);
    prep_rope<<<TT * 32 / 256, 256>>>();

    qkv_gemm<<<dim3(CEMB / 128, MTOT / 128, 3), 256, GM1_SMEM>>>();

    flash_fp16<<<dim3(TT / 128, BB * NHEAD), 256>>>();

    proj_gemm<<<dim3(CEMB / 128, MTOT / 128), 256, GM1_SMEM>>>(bp, out);
}

// round 13
// speedup vs baseline: 2.4462x; 1.0059x over previous
#include <cuda_runtime.h>
#include <cuda_bf16.h>
#include <cuda_fp16.h>
#include <math.h>
#include <stdint.h>

#define NHEAD 16
#define HS    64
#define CEMB  1024
#define BB    4
#define TT    2048
#define MTOT  (BB*TT)          // 8192

// ---------------- device scratch (module-load allocated) -------------------
__device__ __align__(16) float2 g_rope[(size_t)TT*32];
__device__ __align__(16) __half g_qh[(size_t)BB*NHEAD*TT*HS];   // Q fp16 (pre-scaled)
__device__ __align__(16) __half g_kh[(size_t)BB*NHEAD*TT*HS];   // K fp16 [bh][t][d]
__device__ __align__(16) __half g_vt[(size_t)BB*NHEAD*TT*HS];   // V fp16 [bh][d][t]
__device__ __align__(16) __half g_xh[(size_t)MTOT*CEMB];        // x fp16
__device__ __align__(16) __half g_wt[(size_t)4*CEMB*CEMB];      // [mat][n][k]
__device__ __align__(16) __half g_att[(size_t)MTOT*CEMB];       // att fp16

// ---------------- helpers ---------------------------------------------------
__device__ __forceinline__ void mma_fp16(float c[4], const unsigned a[4],
                                         unsigned b0, unsigned b1) {
    asm volatile(
        "mma.sync.aligned.m16n8k16.row.col.f32.f16.f16.f32 "
        "{%0,%1,%2,%3}, {%4,%5,%6,%7}, {%8,%9}, {%0,%1,%2,%3};\n"
        : "+f"(c[0]), "+f"(c[1]), "+f"(c[2]), "+f"(c[3])
        : "r"(a[0]), "r"(a[1]), "r"(a[2]), "r"(a[3]),
          "r"(b0), "r"(b1));
}

__device__ __forceinline__ void ldsm4(unsigned r[4], uint32_t addr) {
    asm volatile(
        "ldmatrix.sync.aligned.m8n8.x4.shared.b16 {%0,%1,%2,%3}, [%4];"
        : "=r"(r[0]), "=r"(r[1]), "=r"(r[2]), "=r"(r[3]) : "r"(addr));
}

__device__ __forceinline__ unsigned pkh(__half x, __half y) {
    unsigned short a = *(unsigned short*)&x, b = *(unsigned short*)&y;
    return (unsigned)a | ((unsigned)b << 16);
}
__device__ __forceinline__ unsigned pkh2f(float a, float b) {
    return pkh(__float2half_rn(a), __float2half_rn(b));
}

__device__ __forceinline__ uint32_t smem_u32(const void* p) {
    uint32_t a;
    asm("{ .reg .u64 t; cvta.to.shared.u64 t, %1; cvt.u32.u64 %0, t; }"
        : "=r"(a) : "l"(p));
    return a;
}
__device__ __forceinline__ void cpa16(uint32_t dst, const void* src) {
    asm volatile("cp.async.cg.shared.global [%0], [%1], 16;\n"
                 :: "r"(dst), "l"(src));
}
#define CP_COMMIT() asm volatile("cp.async.commit_group;\n" ::: "memory")
#define CP_WAIT(n)  asm volatile("cp.async.wait_group %0;\n" :: "n"(n) : "memory")

// ---------------------------------------------------------------------------
// Prep kernels
// ---------------------------------------------------------------------------
__global__ void __launch_bounds__(256) round_x(const float* __restrict__ x)
{
    int i = blockIdx.x * 256 + threadIdx.x;
    float4 v = ((const float4*)x)[i];
    ((uint2*)g_xh)[i] = make_uint2(pkh2f(v.x, v.y), pkh2f(v.z, v.w));
}

__global__ void __launch_bounds__(256) split_transW(
    const float* __restrict__ Wq, const float* __restrict__ Wk,
    const float* __restrict__ Wv, const float* __restrict__ Wp)
{
    __shared__ float tile[32][33];
    const int z = blockIdx.z;
    const float* W = (z == 0) ? Wq : ((z == 1) ? Wk : ((z == 2) ? Wv : Wp));
    __half* outh = g_wt + (size_t)z * CEMB * CEMB;

    const int tx = threadIdx.x & 31;
    const int ty = threadIdx.x >> 5;
    const int k0 = blockIdx.y * 32;
    const int nn0 = blockIdx.x * 32;

#pragma unroll
    for (int j = 0; j < 4; j++)
        tile[ty + 8 * j][tx] = W[(size_t)(k0 + ty + 8 * j) * CEMB + nn0 + tx];
    __syncthreads();
#pragma unroll
    for (int j = 0; j < 4; j++) {
        float v = tile[tx][ty + 8 * j];
        outh[(size_t)(nn0 + ty + 8 * j) * CEMB + k0 + tx] = __float2half_rn(v);
    }
}

__global__ void __launch_bounds__(256) prep_rope()
{
    int idx = blockIdx.x * 256 + threadIdx.x;
    int t = idx >> 5, p = idx & 31;
    const float L2T = 13.287712379549449f / 64.0f;
    float inv = exp2f(-(float)(2 * p) * L2T);
    float sv, cv;
    sincosf((float)t * inv, &sv, &cv);
    g_rope[idx] = make_float2(cv, sv);
}

// ---------------------------------------------------------------------------
// fp16 x1 LDSM GEMM, 3-stage cp.async, one barrier per chunk (validated r12).
// ---------------------------------------------------------------------------
#define PL_B    10240
#define STG1_B  20480
#define GM1_SMEM (3 * STG1_B)  // 61440

__device__ __forceinline__ void gemm_main_x1(
    const __half* __restrict__ Ag, const __half* __restrict__ Bg,
    int m0, int n0, char* smp, float acc[2][8][4])
{
    const int tid  = threadIdx.x;
    const int warp = tid >> 5;
    const int lane = tid & 31;
    const int wm = warp >> 1;
    const int wn = warp & 1;
    const uint32_t sb = smem_u32(smp);

#pragma unroll
    for (int mt = 0; mt < 2; mt++)
#pragma unroll
        for (int nt = 0; nt < 8; nt++)
#pragma unroll
            for (int r = 0; r < 4; r++) acc[mt][nt][r] = 0.0f;

    const __half* sp[4];
    uint32_t doff[4];
#pragma unroll
    for (int i = 0; i < 4; i++) {
        int g = i * 256 + tid;
        int pl = g >> 9;
        int r  = (g >> 2) & 127;
        int sg = g & 3;
        const __half* base = pl ? Bg : Ag;
        int rbase = pl ? n0 : m0;
        sp[i]   = base + (size_t)(rbase + r) * CEMB + sg * 8;
        doff[i] = (uint32_t)(pl * PL_B + r * 80 + sg * 16);
    }

#define GM1_ISSUE(CK, S) do {                                 \
    const int kb_ = (CK) * 32;                                \
    uint32_t st_ = sb + (S) * STG1_B;                         \
    _Pragma("unroll")                                         \
    for (int i = 0; i < 4; i++)                               \
        cpa16(st_ + doff[i], sp[i] + kb_);                    \
    CP_COMMIT();                                              \
} while (0)

    GM1_ISSUE(0, 0);
    GM1_ISSUE(1, 1);

    const int a_row = lane & 15;
    const int a_kh  = lane >> 4;
    const uint32_t aoff = (uint32_t)((wm * 32 + a_row) * 80 + a_kh * 16);
    const int b_n  = ((lane >> 4) << 3) + (lane & 7);
    const int b_kh = (lane >> 3) & 1;
    const uint32_t boff = (uint32_t)(PL_B + (wn * 64 + b_n) * 80 + b_kh * 16);

    int stage = 0;
    for (int ck = 0; ck < 32; ck++) {
        if (ck + 1 < 32) CP_WAIT(1); else CP_WAIT(0);
        __syncthreads();

        if (ck + 2 < 32) {
            int s2 = stage + 2; if (s2 >= 3) s2 -= 3;
            GM1_ISSUE(ck + 2, s2);
        }

        const uint32_t st = sb + stage * STG1_B;
#pragma unroll
        for (int kk = 0; kk < 2; kk++) {
            unsigned Ah[2][4];
#pragma unroll
            for (int mt = 0; mt < 2; mt++)
                ldsm4(Ah[mt], st + aoff + mt * 1280 + kk * 32);
#pragma unroll
            for (int ntp = 0; ntp < 4; ntp++) {
                unsigned Bh[4];
                ldsm4(Bh, st + boff + ntp * 1280 + kk * 32);
#pragma unroll
                for (int mt = 0; mt < 2; mt++) {
                    mma_fp16(acc[mt][ntp * 2 + 0], Ah[mt], Bh[0], Bh[1]);
                    mma_fp16(acc[mt][ntp * 2 + 1], Ah[mt], Bh[2], Bh[3]);
                }
            }
        }
        if (++stage == 3) stage = 0;
    }
#undef GM1_ISSUE
}

// ---------------------------------------------------------------------------
// QKV (x1): mode 0=Q(+RoPE)->fp16 pre-scaled, 1=K(+RoPE)->fp16, 2=V->trans
// ---------------------------------------------------------------------------
__global__ void __launch_bounds__(256, 2) qkv_gemm()
{
    extern __shared__ char smp[];
    const int mode = blockIdx.z;
    const int m0 = blockIdx.y * 128;
    const int n0 = blockIdx.x * 128;

    float acc[2][8][4];
    gemm_main_x1(g_xh, g_wt + (size_t)mode * CEMB * CEMB, m0, n0, smp, acc);

    const int warp = threadIdx.x >> 5;
    const int lane = threadIdx.x & 31;
    const int wm = warp >> 1;
    const int wn = warp & 1;

#pragma unroll
    for (int mt = 0; mt < 2; mt++) {
        const int row_base = m0 + wm * 32 + mt * 16 + (lane >> 2);
#pragma unroll
        for (int nt = 0; nt < 8; nt++) {
            const int col = n0 + wn * 64 + nt * 8 + (lane & 3) * 2;
            const int h = col >> 6;
            const int d = col & 63;
#pragma unroll
            for (int half = 0; half < 2; half++) {
                const int row = row_base + half * 8;
                const int b = row >> 11;
                const int t = row & 2047;
                float x0 = acc[mt][nt][half * 2];
                float x1 = acc[mt][nt][half * 2 + 1];
                float o0 = x0, o1 = x1;
                if (mode < 2) {
                    float2 cs = g_rope[t * 32 + (d >> 1)];
                    o0 = x0 * cs.x - x1 * cs.y;
                    o1 = x0 * cs.y + x1 * cs.x;
                }
                const int bh = b * NHEAD + h;
                if (mode == 0) {
                    size_t base = ((size_t)bh * TT + t) * HS + d;
                    *(unsigned*)(g_qh + base) =
                        pkh2f(o0 * 0.125f, o1 * 0.125f);
                } else if (mode == 1) {
                    size_t base = ((size_t)bh * TT + t) * HS + d;
                    *(unsigned*)(g_kh + base) = pkh2f(o0, o1);
                } else {
                    size_t tb = ((size_t)bh * HS + d) * TT + t;
                    g_vt[tb]      = __float2half_rn(o0);
                    g_vt[tb + TT] = __float2half_rn(o1);
                }
            }
        }
    }
}

// ---------------------------------------------------------------------------
// Output projection (x1): att fp16 @ WpT fp16 + bias -> fp32 out
// ---------------------------------------------------------------------------
__global__ void __launch_bounds__(256, 2) proj_gemm(
    const float* __restrict__ bp, float* __restrict__ out)
{
    extern __shared__ char smp[];
    const int m0 = blockIdx.y * 128;
    const int n0 = blockIdx.x * 128;

    float acc[2][8][4];
    gemm_main_x1(g_att, g_wt + (size_t)3 * CEMB * CEMB, m0, n0, smp, acc);

    const int warp = threadIdx.x >> 5;
    const int lane = threadIdx.x & 31;
    const int wm = warp >> 1;
    const int wn = warp & 1;

#pragma unroll
    for (int mt = 0; mt < 2; mt++) {
        const int row_base = m0 + wm * 32 + mt * 16 + (lane >> 2);
#pragma unroll
        for (int nt = 0; nt < 8; nt++) {
            const int col = n0 + wn * 64 + nt * 8 + (lane & 3) * 2;
            const float b0 = bp[col];
            const float b1 = bp[col + 1];
#pragma unroll
            for (int half = 0; half < 2; half++) {
                const int row = row_base + half * 8;
                *(float2*)(out + (size_t)row * CEMB + col) =
                    make_float2(acc[mt][nt][half * 2]     + b0,
                                acc[mt][nt][half * 2 + 1] + b1);
            }
        }
    }
}

// ---------------------------------------------------------------------------
// Flash attention, fp16 x1, 3-stage single-barrier cp.async K/V pipeline.
// BM=128 (8 warps x m16), BN=64, D=64. Dynamic smem: 3 stages x (K+V planes).
// Stage layout: K [64][72] at +0, V [64][72] at +9216; stage stride 18432 B.
// ---------------------------------------------------------------------------
#define KVS 72
#define KVROWB (KVS * 2)           // 144 B per row
#define FL_KPL (64 * KVROWB)       // 9216 B per plane
#define FL_STG (2 * FL_KPL)        // 18432 B per stage
#define FL_SMEM (3 * FL_STG)       // 55296 B

__global__ void __launch_bounds__(256) flash_fp16()
{
    extern __shared__ char fsm[];
    const uint32_t sb = smem_u32(fsm);

    const int tid  = threadIdx.x;
    const int warp = tid >> 5;
    const int lane = tid & 31;
    const int qt   = gridDim.x - 1 - blockIdx.x;   // big tiles first
    const int q0   = qt * 128;
    const int bh   = blockIdx.y;

    const __half* Q = g_qh + (size_t)bh * TT * HS;
    const __half* K = g_kh + (size_t)bh * TT * HS;
    const __half* V = g_vt + (size_t)bh * HS * TT;

    const int lr = lane >> 2;
    const int lc = lane & 3;
    const int lrow = warp * 16 + lr;
    const int grow_a = q0 + lrow;
    const int grow_b = grow_a + 8;

    // Q fragments: pre-scaled fp16 pairs, direct 32-bit loads
    unsigned qh[4][4];
#pragma unroll
    for (int ks = 0; ks < 4; ks++) {
        const int kd = ks * 16 + lc * 2;
        const __half* qa = Q + (size_t)grow_a * HS;
        const __half* qb = Q + (size_t)grow_b * HS;
        qh[ks][0] = *(const unsigned*)(qa + kd);
        qh[ks][1] = *(const unsigned*)(qb + kd);
        qh[ks][2] = *(const unsigned*)(qa + kd + 8);
        qh[ks][3] = *(const unsigned*)(qb + kd + 8);
    }

    // staging geometry
    const int sj  = tid >> 3;
    const int sdq = (tid & 7) * 8;
    const uint32_t kdst0 = (uint32_t)(sj * KVROWB + sdq * 2);
    const uint32_t kdst1 = (uint32_t)((sj + 32) * KVROWB + sdq * 2);

#define FL_ISSUE(KT, S) do {                                            \
    const int k0_ = (KT) * 64;                                          \
    uint32_t kb_ = sb + (S) * FL_STG;                                   \
    uint32_t vb_ = kb_ + FL_KPL;                                        \
    cpa16(kb_ + kdst0, K + (size_t)(k0_ + sj) * HS + sdq);              \
    cpa16(kb_ + kdst1, K + (size_t)(k0_ + sj + 32) * HS + sdq);         \
    cpa16(vb_ + kdst0, V + (size_t)sj * TT + k0_ + sdq);                \
    cpa16(vb_ + kdst1, V + (size_t)(sj + 32) * TT + k0_ + sdq);         \
    CP_COMMIT();                                                        \
} while (0)

    float o[8][4];
#pragma unroll
    for (int nt = 0; nt < 8; nt++)
#pragma unroll
        for (int r = 0; r < 4; r++) o[nt][r] = 0.0f;
    float m_a = -1e30f, m_b = -1e30f, l_a = 0.0f, l_b = 0.0f;

    const int nkt = 2 * qt + 2;
    FL_ISSUE(0, 0);
    if (nkt > 1) FL_ISSUE(1, 1);

    int stage = 0;
    for (int kt = 0; kt < nkt; kt++) {
        if (kt + 1 < nkt) CP_WAIT(1); else CP_WAIT(0);
        __syncthreads();

        if (kt + 2 < nkt) {
            int s2 = stage + 2; if (s2 >= 3) s2 -= 3;
            FL_ISSUE(kt + 2, s2);
        }

        const char* kpl = fsm + stage * FL_STG;
        const __half (*KSs)[KVS] = (const __half(*)[KVS])kpl;
        const __half (*VSs)[KVS] = (const __half(*)[KVS])(kpl + FL_KPL);
        const int k0 = kt * 64;

        // S = Q K^T (fp16 x1)
        float p[8][4];
#pragma unroll
        for (int nt = 0; nt < 8; nt++)
#pragma unroll
            for (int r = 0; r < 4; r++) p[nt][r] = 0.0f;

#pragma unroll
        for (int ks = 0; ks < 4; ks++) {
            const int kd = ks * 16 + lc * 2;
#pragma unroll
            for (int nt = 0; nt < 8; nt++) {
                const int j = nt * 8 + lr;
                unsigned b0 = *(const unsigned*)&KSs[j][kd];
                unsigned b1 = *(const unsigned*)&KSs[j][kd + 8];
                mma_fp16(p[nt], qh[ks], b0, b1);
            }
        }

        // causal mask (tiles intersecting the diagonal band)
        if (kt + 2 >= nkt) {
#pragma unroll
            for (int nt = 0; nt < 8; nt++) {
                const int c = k0 + nt * 8 + lc * 2;
                if (c     > grow_a) p[nt][0] = -1e30f;
                if (c + 1 > grow_a) p[nt][1] = -1e30f;
                if (c     > grow_b) p[nt][2] = -1e30f;
                if (c + 1 > grow_b) p[nt][3] = -1e30f;
            }
        }

        // online softmax
        float ma = -1e30f, mb2 = -1e30f;
#pragma unroll
        for (int nt = 0; nt < 8; nt++) {
            ma  = fmaxf(ma,  fmaxf(p[nt][0], p[nt][1]));
            mb2 = fmaxf(mb2, fmaxf(p[nt][2], p[nt][3]));
        }
        ma  = fmaxf(ma,  __shfl_xor_sync(0xffffffffu, ma, 1));
        ma  = fmaxf(ma,  __shfl_xor_sync(0xffffffffu, ma, 2));
        mb2 = fmaxf(mb2, __shfl_xor_sync(0xffffffffu, mb2, 1));
        mb2 = fmaxf(mb2, __shfl_xor_sync(0xffffffffu, mb2, 2));

        const float mna = fmaxf(m_a, ma);
        const float mnb = fmaxf(m_b, mb2);
        const float ca  = __expf(m_a - mna);
        const float cbx = __expf(m_b - mnb);

        float sa = 0.0f, sb2 = 0.0f;
#pragma unroll
        for (int nt = 0; nt < 8; nt++) {
            p[nt][0] = __expf(p[nt][0] - mna);
            p[nt][1] = __expf(p[nt][1] - mna);
            p[nt][2] = __expf(p[nt][2] - mnb);
            p[nt][3] = __expf(p[nt][3] - mnb);
            sa  += p[nt][0] + p[nt][1];
            sb2 += p[nt][2] + p[nt][3];
        }
        sa  += __shfl_xor_sync(0xffffffffu, sa, 1);
        sa  += __shfl_xor_sync(0xffffffffu, sa, 2);
        sb2 += __shfl_xor_sync(0xffffffffu, sb2, 1);
        sb2 += __shfl_xor_sync(0xffffffffu, sb2, 2);
        l_a = l_a * ca + sa;    m_a = mna;
        l_b = l_b * cbx + sb2;  m_b = mnb;

#pragma unroll
        for (int nt = 0; nt < 8; nt++) {
            o[nt][0] *= ca;  o[nt][1] *= ca;
            o[nt][2] *= cbx; o[nt][3] *= cbx;
        }

        // P fragments: single fp16
        unsigned pa[4][4];
#pragma unroll
        for (int g = 0; g < 4; g++) {
            pa[g][0] = pkh2f(p[2*g][0],   p[2*g][1]);
            pa[g][1] = pkh2f(p[2*g][2],   p[2*g][3]);
            pa[g][2] = pkh2f(p[2*g+1][0], p[2*g+1][1]);
            pa[g][3] = pkh2f(p[2*g+1][2], p[2*g+1][3]);
        }

        // O += P V (fp16 x1)
#pragma unroll
        for (int g = 0; g < 4; g++) {
            const int j0 = g * 16 + lc * 2;
#pragma unroll
            for (int nt = 0; nt < 8; nt++) {
                const int dcol = nt * 8 + lr;
                unsigned b0 = *(const unsigned*)&VSs[dcol][j0];
                unsigned b1 = *(const unsigned*)&VSs[dcol][j0 + 8];
                mma_fp16(o[nt], pa[g], b0, b1);
            }
        }
        if (++stage == 3) stage = 0;
    }
#undef FL_ISSUE

    // epilogue: normalize, write single fp16 att plane
    const float rla = 1.0f / l_a;
    const float rlb = 1.0f / l_b;
    const int b = bh >> 4;
    const int h = bh & 15;
    size_t oa = ((size_t)b * TT + grow_a) * CEMB + h * HS;
    size_t ob = ((size_t)b * TT + grow_b) * CEMB + h * HS;
#pragma unroll
    for (int nt = 0; nt < 8; nt++) {
        const int col = nt * 8 + lc * 2;
        *(unsigned*)(g_att + oa + col) = pkh2f(o[nt][0] * rla, o[nt][1] * rla);
        *(unsigned*)(g_att + ob + col) = pkh2f(o[nt][2] * rlb, o[nt][3] * rlb);
    }
}

// ---------------------------------------------------------------------------
extern "C" void kernel_launch(void* const* d_in, const int* in_sizes, int n_in,
                              void* d_out, int out_size)
{
    (void)in_sizes; (void)n_in; (void)out_size;
    const float* x  = (const float*)d_in[0];
    const float* Wq = (const float*)d_in[1];
    const float* Wk = (const float*)d_in[2];
    const float* Wv = (const float*)d_in[3];
    const float* Wp = (const float*)d_in[4];
    const float* bp = (const float*)d_in[5];
    float* out = (float*)d_out;

    cudaFuncSetAttribute(qkv_gemm,
        cudaFuncAttributeMaxDynamicSharedMemorySize, GM1_SMEM);
    cudaFuncSetAttribute(proj_gemm,
        cudaFuncAttributeMaxDynamicSharedMemorySize, GM1_SMEM);
    cudaFuncSetAttribute(flash_fp16,
        cudaFuncAttributeMaxDynamicSharedMemorySize, FL_SMEM);

    round_x<<<MTOT * CEMB / 4 / 256, 256>>>(x);
    split_transW<<<dim3(CEMB / 32, CEMB / 32, 4), 256>>>(Wq, Wk, Wv, Wp);
    prep_rope<<<TT * 32 / 256, 256>>>();

    qkv_gemm<<<dim3(CEMB / 128, MTOT / 128, 3), 256, GM1_SMEM>>>();

    flash_fp16<<<dim3(TT / 128, BB * NHEAD), 256, FL_SMEM>>>();

    proj_gemm<<<dim3(CEMB / 128, MTOT / 128), 256, GM1_SMEM>>>(bp, out);
}

// round 14
// speedup vs baseline: 2.6400x; 1.0792x over previous
#include <cuda_runtime.h>
#include <cuda_bf16.h>
#include <cuda_fp16.h>
#include <math.h>
#include <stdint.h>

#define NHEAD 16
#define HS    64
#define CEMB  1024
#define BB    4
#define TT    2048
#define MTOT  (BB*TT)          // 8192

// ---------------- device scratch (module-load allocated) -------------------
__device__ __align__(16) float2 g_rope[(size_t)TT*32];
__device__ __align__(16) __half g_qh[(size_t)BB*NHEAD*TT*HS];   // Q fp16 (scaled*log2e)
__device__ __align__(16) __half g_kh[(size_t)BB*NHEAD*TT*HS];   // K fp16 [bh][t][d]
__device__ __align__(16) __half g_vt[(size_t)BB*NHEAD*TT*HS];   // V fp16 [bh][d][t]
__device__ __align__(16) __half g_xh[(size_t)MTOT*CEMB];        // x fp16
__device__ __align__(16) __half g_wt[(size_t)4*CEMB*CEMB];      // [mat][n][k]
__device__ __align__(16) __half g_att[(size_t)MTOT*CEMB];       // att fp16

// ---------------- helpers ---------------------------------------------------
__device__ __forceinline__ void mma_fp16(float c[4], const unsigned a[4],
                                         unsigned b0, unsigned b1) {
    asm volatile(
        "mma.sync.aligned.m16n8k16.row.col.f32.f16.f16.f32 "
        "{%0,%1,%2,%3}, {%4,%5,%6,%7}, {%8,%9}, {%0,%1,%2,%3};\n"
        : "+f"(c[0]), "+f"(c[1]), "+f"(c[2]), "+f"(c[3])
        : "r"(a[0]), "r"(a[1]), "r"(a[2]), "r"(a[3]),
          "r"(b0), "r"(b1));
}

__device__ __forceinline__ void ldsm4(unsigned r[4], uint32_t addr) {
    asm volatile(
        "ldmatrix.sync.aligned.m8n8.x4.shared.b16 {%0,%1,%2,%3}, [%4];"
        : "=r"(r[0]), "=r"(r[1]), "=r"(r[2]), "=r"(r[3]) : "r"(addr));
}

__device__ __forceinline__ unsigned pkh(__half x, __half y) {
    unsigned short a = *(unsigned short*)&x, b = *(unsigned short*)&y;
    return (unsigned)a | ((unsigned)b << 16);
}
__device__ __forceinline__ unsigned pkh2f(float a, float b) {
    return pkh(__float2half_rn(a), __float2half_rn(b));
}

__device__ __forceinline__ uint32_t smem_u32(const void* p) {
    uint32_t a;
    asm("{ .reg .u64 t; cvta.to.shared.u64 t, %1; cvt.u32.u64 %0, t; }"
        : "=r"(a) : "l"(p));
    return a;
}
__device__ __forceinline__ void cpa16(uint32_t dst, const void* src) {
    asm volatile("cp.async.cg.shared.global [%0], [%1], 16;\n"
                 :: "r"(dst), "l"(src));
}
#define CP_COMMIT() asm volatile("cp.async.commit_group;\n" ::: "memory")
#define CP_WAIT(n)  asm volatile("cp.async.wait_group %0;\n" :: "n"(n) : "memory")

// ---------------------------------------------------------------------------
// Prep kernels
// ---------------------------------------------------------------------------
__global__ void __launch_bounds__(256) round_x(const float* __restrict__ x)
{
    int i = blockIdx.x * 256 + threadIdx.x;
    float4 v = ((const float4*)x)[i];
    ((uint2*)g_xh)[i] = make_uint2(pkh2f(v.x, v.y), pkh2f(v.z, v.w));
}

__global__ void __launch_bounds__(256) split_transW(
    const float* __restrict__ Wq, const float* __restrict__ Wk,
    const float* __restrict__ Wv, const float* __restrict__ Wp)
{
    __shared__ float tile[32][33];
    const int z = blockIdx.z;
    const float* W = (z == 0) ? Wq : ((z == 1) ? Wk : ((z == 2) ? Wv : Wp));
    __half* outh = g_wt + (size_t)z * CEMB * CEMB;

    const int tx = threadIdx.x & 31;
    const int ty = threadIdx.x >> 5;
    const int k0 = blockIdx.y * 32;
    const int nn0 = blockIdx.x * 32;

#pragma unroll
    for (int j = 0; j < 4; j++)
        tile[ty + 8 * j][tx] = W[(size_t)(k0 + ty + 8 * j) * CEMB + nn0 + tx];
    __syncthreads();
#pragma unroll
    for (int j = 0; j < 4; j++) {
        float v = tile[tx][ty + 8 * j];
        outh[(size_t)(nn0 + ty + 8 * j) * CEMB + k0 + tx] = __float2half_rn(v);
    }
}

__global__ void __launch_bounds__(256) prep_rope()
{
    int idx = blockIdx.x * 256 + threadIdx.x;
    int t = idx >> 5, p = idx & 31;
    const float L2T = 13.287712379549449f / 64.0f;
    float inv = exp2f(-(float)(2 * p) * L2T);
    float sv, cv;
    sincosf((float)t * inv, &sv, &cv);
    g_rope[idx] = make_float2(cv, sv);
}

// ---------------------------------------------------------------------------
// fp16 x1 LDSM GEMM, BK=64, 3-stage cp.async, one barrier per chunk.
// 128x128 tile, 256 threads (8 warps, 4x2 of 32x64).
// Plane: 128 rows x 144 B (64 halves data + 16 B pad). A at 0, B at PL_B.
// ---------------------------------------------------------------------------
#define PL_B    18432
#define STG1_B  36864
#define GM1_SMEM (3 * STG1_B)  // 110592

__device__ __forceinline__ void gemm_main_x1(
    const __half* __restrict__ Ag, const __half* __restrict__ Bg,
    int m0, int n0, char* smp, float acc[2][8][4])
{
    const int tid  = threadIdx.x;
    const int warp = tid >> 5;
    const int lane = tid & 31;
    const int wm = warp >> 1;
    const int wn = warp & 1;
    const uint32_t sb = smem_u32(smp);

#pragma unroll
    for (int mt = 0; mt < 2; mt++)
#pragma unroll
        for (int nt = 0; nt < 8; nt++)
#pragma unroll
            for (int r = 0; r < 4; r++) acc[mt][nt][r] = 0.0f;

    // staging: 2 planes * 128 rows * 8 segs = 2048 segs / 256 thr = 8 each
    const __half* sp[8];
    uint32_t doff[8];
#pragma unroll
    for (int i = 0; i < 8; i++) {
        int g = i * 256 + tid;
        int pl = g >> 10;            // 0..1
        int r  = (g >> 3) & 127;
        int sq = g & 7;
        const __half* base = pl ? Bg : Ag;
        int rbase = pl ? n0 : m0;
        sp[i]   = base + (size_t)(rbase + r) * CEMB + sq * 8;
        doff[i] = (uint32_t)(pl * PL_B + r * 144 + sq * 16);
    }

#define GM1_ISSUE(CK, S) do {                                 \
    const int kb_ = (CK) * 64;                                \
    uint32_t st_ = sb + (S) * STG1_B;                         \
    _Pragma("unroll")                                         \
    for (int i = 0; i < 8; i++)                               \
        cpa16(st_ + doff[i], sp[i] + kb_);                    \
    CP_COMMIT();                                              \
} while (0)

    GM1_ISSUE(0, 0);
    GM1_ISSUE(1, 1);

    const int a_row = lane & 15;
    const int a_kh  = lane >> 4;
    const uint32_t aoff = (uint32_t)((wm * 32 + a_row) * 144 + a_kh * 16);
    const int b_n  = ((lane >> 4) << 3) + (lane & 7);
    const int b_kh = (lane >> 3) & 1;
    const uint32_t boff = (uint32_t)(PL_B + (wn * 64 + b_n) * 144 + b_kh * 16);

    int stage = 0;
    for (int ck = 0; ck < 16; ck++) {
        if (ck + 1 < 16) CP_WAIT(1); else CP_WAIT(0);
        __syncthreads();

        if (ck + 2 < 16) {
            int s2 = stage + 2; if (s2 >= 3) s2 -= 3;
            GM1_ISSUE(ck + 2, s2);
        }

        const uint32_t st = sb + stage * STG1_B;
#pragma unroll
        for (int kk = 0; kk < 4; kk++) {
            unsigned Ah[2][4];
#pragma unroll
            for (int mt = 0; mt < 2; mt++)
                ldsm4(Ah[mt], st + aoff + mt * 2304 + kk * 32);
#pragma unroll
            for (int ntp = 0; ntp < 4; ntp++) {
                unsigned Bh[4];
                ldsm4(Bh, st + boff + ntp * 2304 + kk * 32);
#pragma unroll
                for (int mt = 0; mt < 2; mt++) {
                    mma_fp16(acc[mt][ntp * 2 + 0], Ah[mt], Bh[0], Bh[1]);
                    mma_fp16(acc[mt][ntp * 2 + 1], Ah[mt], Bh[2], Bh[3]);
                }
            }
        }
        if (++stage == 3) stage = 0;
    }
#undef GM1_ISSUE
}

// ---------------------------------------------------------------------------
// QKV (x1): mode 0=Q(+RoPE)->fp16 scaled*log2e, 1=K(+RoPE)->fp16, 2=V->trans
// ---------------------------------------------------------------------------
__global__ void __launch_bounds__(256, 2) qkv_gemm()
{
    extern __shared__ char smp[];
    const int mode = blockIdx.z;
    const int m0 = blockIdx.y * 128;
    const int n0 = blockIdx.x * 128;

    float acc[2][8][4];
    gemm_main_x1(g_xh, g_wt + (size_t)mode * CEMB * CEMB, m0, n0, smp, acc);

    const int warp = threadIdx.x >> 5;
    const int lane = threadIdx.x & 31;
    const int wm = warp >> 1;
    const int wn = warp & 1;
    const float QSCALE = 0.125f * 1.4426950408889634f;  // 1/sqrt(64) * log2(e)

#pragma unroll
    for (int mt = 0; mt < 2; mt++) {
        const int row_base = m0 + wm * 32 + mt * 16 + (lane >> 2);
#pragma unroll
        for (int nt = 0; nt < 8; nt++) {
            const int col = n0 + wn * 64 + nt * 8 + (lane & 3) * 2;
            const int h = col >> 6;
            const int d = col & 63;
#pragma unroll
            for (int half = 0; half < 2; half++) {
                const int row = row_base + half * 8;
                const int b = row >> 11;
                const int t = row & 2047;
                float x0 = acc[mt][nt][half * 2];
                float x1 = acc[mt][nt][half * 2 + 1];
                float o0 = x0, o1 = x1;
                if (mode < 2) {
                    float2 cs = g_rope[t * 32 + (d >> 1)];
                    o0 = x0 * cs.x - x1 * cs.y;
                    o1 = x0 * cs.y + x1 * cs.x;
                }
                const int bh = b * NHEAD + h;
                if (mode == 0) {
                    size_t base = ((size_t)bh * TT + t) * HS + d;
                    *(unsigned*)(g_qh + base) =
                        pkh2f(o0 * QSCALE, o1 * QSCALE);
                } else if (mode == 1) {
                    size_t base = ((size_t)bh * TT + t) * HS + d;
                    *(unsigned*)(g_kh + base) = pkh2f(o0, o1);
                } else {
                    size_t tb = ((size_t)bh * HS + d) * TT + t;
                    g_vt[tb]      = __float2half_rn(o0);
                    g_vt[tb + TT] = __float2half_rn(o1);
                }
            }
        }
    }
}

// ---------------------------------------------------------------------------
// Output projection (x1): att fp16 @ WpT fp16 + bias -> fp32 out
// ---------------------------------------------------------------------------
__global__ void __launch_bounds__(256, 2) proj_gemm(
    const float* __restrict__ bp, float* __restrict__ out)
{
    extern __shared__ char smp[];
    const int m0 = blockIdx.y * 128;
    const int n0 = blockIdx.x * 128;

    float acc[2][8][4];
    gemm_main_x1(g_att, g_wt + (size_t)3 * CEMB * CEMB, m0, n0, smp, acc);

    const int warp = threadIdx.x >> 5;
    const int lane = threadIdx.x & 31;
    const int wm = warp >> 1;
    const int wn = warp & 1;

#pragma unroll
    for (int mt = 0; mt < 2; mt++) {
        const int row_base = m0 + wm * 32 + mt * 16 + (lane >> 2);
#pragma unroll
        for (int nt = 0; nt < 8; nt++) {
            const int col = n0 + wn * 64 + nt * 8 + (lane & 3) * 2;
            const float b0 = bp[col];
            const float b1 = bp[col + 1];
#pragma unroll
            for (int half = 0; half < 2; half++) {
                const int row = row_base + half * 8;
                *(float2*)(out + (size_t)row * CEMB + col) =
                    make_float2(acc[mt][nt][half * 2]     + b0,
                                acc[mt][nt][half * 2 + 1] + b1);
            }
        }
    }
}

// ---------------------------------------------------------------------------
// Flash attention, fp16 x1, 3-stage single-barrier cp.async, exp2-domain
// softmax (Q pre-scaled by log2e). BM=128 (8 warps x m16), BN=64, D=64.
// ---------------------------------------------------------------------------
#define KVS 72
#define KVROWB (KVS * 2)           // 144 B per row
#define FL_KPL (64 * KVROWB)       // 9216 B per plane
#define FL_STG (2 * FL_KPL)        // 18432 B per stage
#define FL_SMEM (3 * FL_STG)       // 55296 B

__global__ void __launch_bounds__(256) flash_fp16()
{
    extern __shared__ char fsm[];
    const uint32_t sb = smem_u32(fsm);

    const int tid  = threadIdx.x;
    const int warp = tid >> 5;
    const int lane = tid & 31;
    const int qt   = gridDim.x - 1 - blockIdx.x;   // big tiles first
    const int q0   = qt * 128;
    const int bh   = blockIdx.y;

    const __half* Q = g_qh + (size_t)bh * TT * HS;
    const __half* K = g_kh + (size_t)bh * TT * HS;
    const __half* V = g_vt + (size_t)bh * HS * TT;

    const int lr = lane >> 2;
    const int lc = lane & 3;
    const int lrow = warp * 16 + lr;
    const int grow_a = q0 + lrow;
    const int grow_b = grow_a + 8;

    unsigned qh[4][4];
#pragma unroll
    for (int ks = 0; ks < 4; ks++) {
        const int kd = ks * 16 + lc * 2;
        const __half* qa = Q + (size_t)grow_a * HS;
        const __half* qb = Q + (size_t)grow_b * HS;
        qh[ks][0] = *(const unsigned*)(qa + kd);
        qh[ks][1] = *(const unsigned*)(qb + kd);
        qh[ks][2] = *(const unsigned*)(qa + kd + 8);
        qh[ks][3] = *(const unsigned*)(qb + kd + 8);
    }

    const int sj  = tid >> 3;
    const int sdq = (tid & 7) * 8;
    const uint32_t kdst0 = (uint32_t)(sj * KVROWB + sdq * 2);
    const uint32_t kdst1 = (uint32_t)((sj + 32) * KVROWB + sdq * 2);

#define FL_ISSUE(KT, S) do {                                            \
    const int k0_ = (KT) * 64;                                          \
    uint32_t kb_ = sb + (S) * FL_STG;                                   \
    uint32_t vb_ = kb_ + FL_KPL;                                        \
    cpa16(kb_ + kdst0, K + (size_t)(k0_ + sj) * HS + sdq);              \
    cpa16(kb_ + kdst1, K + (size_t)(k0_ + sj + 32) * HS + sdq);         \
    cpa16(vb_ + kdst0, V + (size_t)sj * TT + k0_ + sdq);                \
    cpa16(vb_ + kdst1, V + (size_t)(sj + 32) * TT + k0_ + sdq);         \
    CP_COMMIT();                                                        \
} while (0)

    float o[8][4];
#pragma unroll
    for (int nt = 0; nt < 8; nt++)
#pragma unroll
        for (int r = 0; r < 4; r++) o[nt][r] = 0.0f;
    float m_a = -1e30f, m_b = -1e30f, l_a = 0.0f, l_b = 0.0f;

    const int nkt = 2 * qt + 2;
    FL_ISSUE(0, 0);
    if (nkt > 1) FL_ISSUE(1, 1);

    int stage = 0;
    for (int kt = 0; kt < nkt; kt++) {
        if (kt + 1 < nkt) CP_WAIT(1); else CP_WAIT(0);
        __syncthreads();

        if (kt + 2 < nkt) {
            int s2 = stage + 2; if (s2 >= 3) s2 -= 3;
            FL_ISSUE(kt + 2, s2);
        }

        const char* kpl = fsm + stage * FL_STG;
        const __half (*KSs)[KVS] = (const __half(*)[KVS])kpl;
        const __half (*VSs)[KVS] = (const __half(*)[KVS])(kpl + FL_KPL);
        const int k0 = kt * 64;

        float p[8][4];
#pragma unroll
        for (int nt = 0; nt < 8; nt++)
#pragma unroll
            for (int r = 0; r < 4; r++) p[nt][r] = 0.0f;

#pragma unroll
        for (int ks = 0; ks < 4; ks++) {
            const int kd = ks * 16 + lc * 2;
#pragma unroll
            for (int nt = 0; nt < 8; nt++) {
                const int j = nt * 8 + lr;
                unsigned b0 = *(const unsigned*)&KSs[j][kd];
                unsigned b1 = *(const unsigned*)&KSs[j][kd + 8];
                mma_fp16(p[nt], qh[ks], b0, b1);
            }
        }

        if (kt + 2 >= nkt) {
#pragma unroll
            for (int nt = 0; nt < 8; nt++) {
                const int c = k0 + nt * 8 + lc * 2;
                if (c     > grow_a) p[nt][0] = -1e30f;
                if (c + 1 > grow_a) p[nt][1] = -1e30f;
                if (c     > grow_b) p[nt][2] = -1e30f;
                if (c + 1 > grow_b) p[nt][3] = -1e30f;
            }
        }

        float ma = -1e30f, mb2 = -1e30f;
#pragma unroll
        for (int nt = 0; nt < 8; nt++) {
            ma  = fmaxf(ma,  fmaxf(p[nt][0], p[nt][1]));
            mb2 = fmaxf(mb2, fmaxf(p[nt][2], p[nt][3]));
        }
        ma  = fmaxf(ma,  __shfl_xor_sync(0xffffffffu, ma, 1));
        ma  = fmaxf(ma,  __shfl_xor_sync(0xffffffffu, ma, 2));
        mb2 = fmaxf(mb2, __shfl_xor_sync(0xffffffffu, mb2, 1));
        mb2 = fmaxf(mb2, __shfl_xor_sync(0xffffffffu, mb2, 2));

        const float mna = fmaxf(m_a, ma);
        const float mnb = fmaxf(m_b, mb2);
        const float ca  = exp2f(m_a - mna);
        const float cbx = exp2f(m_b - mnb);

        float sa = 0.0f, sb2 = 0.0f;
#pragma unroll
        for (int nt = 0; nt < 8; nt++) {
            p[nt][0] = exp2f(p[nt][0] - mna);
            p[nt][1] = exp2f(p[nt][1] - mna);
            p[nt][2] = exp2f(p[nt][2] - mnb);
            p[nt][3] = exp2f(p[nt][3] - mnb);
            sa  += p[nt][0] + p[nt][1];
            sb2 += p[nt][2] + p[nt][3];
        }
        sa  += __shfl_xor_sync(0xffffffffu, sa, 1);
        sa  += __shfl_xor_sync(0xffffffffu, sa, 2);
        sb2 += __shfl_xor_sync(0xffffffffu, sb2, 1);
        sb2 += __shfl_xor_sync(0xffffffffu, sb2, 2);
        l_a = l_a * ca + sa;    m_a = mna;
        l_b = l_b * cbx + sb2;  m_b = mnb;

#pragma unroll
        for (int nt = 0; nt < 8; nt++) {
            o[nt][0] *= ca;  o[nt][1] *= ca;
            o[nt][2] *= cbx; o[nt][3] *= cbx;
        }

        unsigned pa[4][4];
#pragma unroll
        for (int g = 0; g < 4; g++) {
            pa[g][0] = pkh2f(p[2*g][0],   p[2*g][1]);
            pa[g][1] = pkh2f(p[2*g][2],   p[2*g][3]);
            pa[g][2] = pkh2f(p[2*g+1][0], p[2*g+1][1]);
            pa[g][3] = pkh2f(p[2*g+1][2], p[2*g+1][3]);
        }

#pragma unroll
        for (int g = 0; g < 4; g++) {
            const int j0 = g * 16 + lc * 2;
#pragma unroll
            for (int nt = 0; nt < 8; nt++) {
                const int dcol = nt * 8 + lr;
                unsigned b0 = *(const unsigned*)&VSs[dcol][j0];
                unsigned b1 = *(const unsigned*)&VSs[dcol][j0 + 8];
                mma_fp16(o[nt], pa[g], b0, b1);
            }
        }
        if (++stage == 3) stage = 0;
    }
#undef FL_ISSUE

    const float rla = 1.0f / l_a;
    const float rlb = 1.0f / l_b;
    const int b = bh >> 4;
    const int h = bh & 15;
    size_t oa = ((size_t)b * TT + grow_a) * CEMB + h * HS;
    size_t ob = ((size_t)b * TT + grow_b) * CEMB + h * HS;
#pragma unroll
    for (int nt = 0; nt < 8; nt++) {
        const int col = nt * 8 + lc * 2;
        *(unsigned*)(g_att + oa + col) = pkh2f(o[nt][0] * rla, o[nt][1] * rla);
        *(unsigned*)(g_att + ob + col) = pkh2f(o[nt][2] * rlb, o[nt][3] * rlb);
    }
}

// ---------------------------------------------------------------------------
extern "C" void kernel_launch(void* const* d_in, const int* in_sizes, int n_in,
                              void* d_out, int out_size)
{
    (void)in_sizes; (void)n_in; (void)out_size;
    const float* x  = (const float*)d_in[0];
    const float* Wq = (const float*)d_in[1];
    const float* Wk = (const float*)d_in[2];
    const float* Wv = (const float*)d_in[3];
    const float* Wp = (const float*)d_in[4];
    const float* bp = (const float*)d_in[5];
    float* out = (float*)d_out;

    cudaFuncSetAttribute(qkv_gemm,
        cudaFuncAttributeMaxDynamicSharedMemorySize, GM1_SMEM);
    cudaFuncSetAttribute(proj_gemm,
        cudaFuncAttributeMaxDynamicSharedMemorySize, GM1_SMEM);
    cudaFuncSetAttribute(flash_fp16,
        cudaFuncAttributeMaxDynamicSharedMemorySize, FL_SMEM);

    round_x<<<MTOT * CEMB / 4 / 256, 256>>>(x);
    split_transW<<<dim3(CEMB / 32, CEMB / 32, 4), 256>>>(Wq, Wk, Wv, Wp);
    prep_rope<<<TT * 32 / 256, 256>>>();

    qkv_gemm<<<dim3(CEMB / 128, MTOT / 128, 3), 256, GM1_SMEM>>>();

    flash_fp16<<<dim3(TT / 128, BB * NHEAD), 256, FL_SMEM>>>();

    proj_gemm<<<dim3(CEMB / 128, MTOT / 128), 256, GM1_SMEM>>>(bp, out);
}

// round 15
// speedup vs baseline: 2.7055x; 1.0248x over previous
#include <cuda_runtime.h>
#include <cuda_bf16.h>
#include <cuda_fp16.h>
#include <math.h>
#include <stdint.h>

#define NHEAD 16
#define HS    64
#define CEMB  1024
#define BB    4
#define TT    2048
#define MTOT  (BB*TT)          // 8192

// ---------------- device scratch (module-load allocated) -------------------
__device__ __align__(16) float2 g_rope[(size_t)TT*32];
__device__ __align__(16) __half g_qh[(size_t)BB*NHEAD*TT*HS];   // Q fp16 (scaled*log2e)
__device__ __align__(16) __half g_kh[(size_t)BB*NHEAD*TT*HS];   // K fp16 [bh][t][d]
__device__ __align__(16) __half g_vt[(size_t)BB*NHEAD*TT*HS];   // V fp16 [bh][d][t]
__device__ __align__(16) __half g_xh[(size_t)MTOT*CEMB];        // x fp16
__device__ __align__(16) __half g_wt[(size_t)4*CEMB*CEMB];      // [mat][n][k]
__device__ __align__(16) __half g_att[(size_t)MTOT*CEMB];       // att fp16

// ---------------- helpers ---------------------------------------------------
__device__ __forceinline__ void mma_fp16(float c[4], const unsigned a[4],
                                         unsigned b0, unsigned b1) {
    asm volatile(
        "mma.sync.aligned.m16n8k16.row.col.f32.f16.f16.f32 "
        "{%0,%1,%2,%3}, {%4,%5,%6,%7}, {%8,%9}, {%0,%1,%2,%3};\n"
        : "+f"(c[0]), "+f"(c[1]), "+f"(c[2]), "+f"(c[3])
        : "r"(a[0]), "r"(a[1]), "r"(a[2]), "r"(a[3]),
          "r"(b0), "r"(b1));
}

__device__ __forceinline__ void ldsm4(unsigned r[4], uint32_t addr) {
    asm volatile(
        "ldmatrix.sync.aligned.m8n8.x4.shared.b16 {%0,%1,%2,%3}, [%4];"
        : "=r"(r[0]), "=r"(r[1]), "=r"(r[2]), "=r"(r[3]) : "r"(addr));
}

__device__ __forceinline__ unsigned pkh(__half x, __half y) {
    unsigned short a = *(unsigned short*)&x, b = *(unsigned short*)&y;
    return (unsigned)a | ((unsigned)b << 16);
}
__device__ __forceinline__ unsigned pkh2f(float a, float b) {
    return pkh(__float2half_rn(a), __float2half_rn(b));
}

__device__ __forceinline__ uint32_t smem_u32(const void* p) {
    uint32_t a;
    asm("{ .reg .u64 t; cvta.to.shared.u64 t, %1; cvt.u32.u64 %0, t; }"
        : "=r"(a) : "l"(p));
    return a;
}
__device__ __forceinline__ void cpa16(uint32_t dst, const void* src) {
    asm volatile("cp.async.cg.shared.global [%0], [%1], 16;\n"
                 :: "r"(dst), "l"(src));
}
#define CP_COMMIT() asm volatile("cp.async.commit_group;\n" ::: "memory")
#define CP_WAIT(n)  asm volatile("cp.async.wait_group %0;\n" :: "n"(n) : "memory")

// ---------------------------------------------------------------------------
// Fused prep: blocks [0,8192) round x; [8192,12288) transpose+round W;
// [12288,12544) RoPE table.
// ---------------------------------------------------------------------------
__global__ void __launch_bounds__(256) prep_all(
    const float* __restrict__ x,
    const float* __restrict__ Wq, const float* __restrict__ Wk,
    const float* __restrict__ Wv, const float* __restrict__ Wp)
{
    __shared__ float tile[32][33];
    const int bid = blockIdx.x;
    const int tid = threadIdx.x;

    if (bid < 8192) {
        int i = bid * 256 + tid;
        float4 v = ((const float4*)x)[i];
        ((uint2*)g_xh)[i] = make_uint2(pkh2f(v.x, v.y), pkh2f(v.z, v.w));
    } else if (bid < 12288) {
        const int b2 = bid - 8192;
        const int z = b2 >> 10;
        const int rem = b2 & 1023;
        const int by = rem >> 5;       // k block
        const int bx = rem & 31;       // n block
        const float* W = (z == 0) ? Wq : ((z == 1) ? Wk : ((z == 2) ? Wv : Wp));
        __half* outh = g_wt + (size_t)z * CEMB * CEMB;
        const int tx = tid & 31;
        const int ty = tid >> 5;
        const int k0 = by * 32;
        const int nn0 = bx * 32;
#pragma unroll
        for (int j = 0; j < 4; j++)
            tile[ty + 8 * j][tx] =
                W[(size_t)(k0 + ty + 8 * j) * CEMB + nn0 + tx];
        __syncthreads();
#pragma unroll
        for (int j = 0; j < 4; j++) {
            float v = tile[tx][ty + 8 * j];
            outh[(size_t)(nn0 + ty + 8 * j) * CEMB + k0 + tx] =
                __float2half_rn(v);
        }
    } else {
        int idx = (bid - 12288) * 256 + tid;
        int t = idx >> 5, p = idx & 31;
        const float L2T = 13.287712379549449f / 64.0f;
        float inv = exp2f(-(float)(2 * p) * L2T);
        float sv, cv;
        sincosf((float)t * inv, &sv, &cv);
        g_rope[idx] = make_float2(cv, sv);
    }
}

// ---------------------------------------------------------------------------
// fp16 x1 LDSM GEMM, BK=64, 3-stage cp.async, one barrier per chunk (r14).
// ---------------------------------------------------------------------------
#define PL_B    18432
#define STG1_B  36864
#define GM1_SMEM (3 * STG1_B)  // 110592

__device__ __forceinline__ void gemm_main_x1(
    const __half* __restrict__ Ag, const __half* __restrict__ Bg,
    int m0, int n0, char* smp, float acc[2][8][4])
{
    const int tid  = threadIdx.x;
    const int warp = tid >> 5;
    const int lane = tid & 31;
    const int wm = warp >> 1;
    const int wn = warp & 1;
    const uint32_t sb = smem_u32(smp);

#pragma unroll
    for (int mt = 0; mt < 2; mt++)
#pragma unroll
        for (int nt = 0; nt < 8; nt++)
#pragma unroll
            for (int r = 0; r < 4; r++) acc[mt][nt][r] = 0.0f;

    const __half* sp[8];
    uint32_t doff[8];
#pragma unroll
    for (int i = 0; i < 8; i++) {
        int g = i * 256 + tid;
        int pl = g >> 10;
        int r  = (g >> 3) & 127;
        int sq = g & 7;
        const __half* base = pl ? Bg : Ag;
        int rbase = pl ? n0 : m0;
        sp[i]   = base + (size_t)(rbase + r) * CEMB + sq * 8;
        doff[i] = (uint32_t)(pl * PL_B + r * 144 + sq * 16);
    }

#define GM1_ISSUE(CK, S) do {                                 \
    const int kb_ = (CK) * 64;                                \
    uint32_t st_ = sb + (S) * STG1_B;                         \
    _Pragma("unroll")                                         \
    for (int i = 0; i < 8; i++)                               \
        cpa16(st_ + doff[i], sp[i] + kb_);                    \
    CP_COMMIT();                                              \
} while (0)

    GM1_ISSUE(0, 0);
    GM1_ISSUE(1, 1);

    const int a_row = lane & 15;
    const int a_kh  = lane >> 4;
    const uint32_t aoff = (uint32_t)((wm * 32 + a_row) * 144 + a_kh * 16);
    const int b_n  = ((lane >> 4) << 3) + (lane & 7);
    const int b_kh = (lane >> 3) & 1;
    const uint32_t boff = (uint32_t)(PL_B + (wn * 64 + b_n) * 144 + b_kh * 16);

    int stage = 0;
    for (int ck = 0; ck < 16; ck++) {
        if (ck + 1 < 16) CP_WAIT(1); else CP_WAIT(0);
        __syncthreads();

        if (ck + 2 < 16) {
            int s2 = stage + 2; if (s2 >= 3) s2 -= 3;
            GM1_ISSUE(ck + 2, s2);
        }

        const uint32_t st = sb + stage * STG1_B;
#pragma unroll
        for (int kk = 0; kk < 4; kk++) {
            unsigned Ah[2][4];
#pragma unroll
            for (int mt = 0; mt < 2; mt++)
                ldsm4(Ah[mt], st + aoff + mt * 2304 + kk * 32);
#pragma unroll
            for (int ntp = 0; ntp < 4; ntp++) {
                unsigned Bh[4];
                ldsm4(Bh, st + boff + ntp * 2304 + kk * 32);
#pragma unroll
                for (int mt = 0; mt < 2; mt++) {
                    mma_fp16(acc[mt][ntp * 2 + 0], Ah[mt], Bh[0], Bh[1]);
                    mma_fp16(acc[mt][ntp * 2 + 1], Ah[mt], Bh[2], Bh[3]);
                }
            }
        }
        if (++stage == 3) stage = 0;
    }
#undef GM1_ISSUE
}

// ---------------------------------------------------------------------------
// QKV (x1): mode 0=Q(+RoPE)->fp16 scaled*log2e, 1=K(+RoPE)->fp16, 2=V->trans
// ---------------------------------------------------------------------------
__global__ void __launch_bounds__(256, 2) qkv_gemm()
{
    extern __shared__ char smp[];
    const int mode = blockIdx.z;
    const int m0 = blockIdx.y * 128;
    const int n0 = blockIdx.x * 128;

    float acc[2][8][4];
    gemm_main_x1(g_xh, g_wt + (size_t)mode * CEMB * CEMB, m0, n0, smp, acc);

    const int warp = threadIdx.x >> 5;
    const int lane = threadIdx.x & 31;
    const int wm = warp >> 1;
    const int wn = warp & 1;
    const float QSCALE = 0.125f * 1.4426950408889634f;

#pragma unroll
    for (int mt = 0; mt < 2; mt++) {
        const int row_base = m0 + wm * 32 + mt * 16 + (lane >> 2);
#pragma unroll
        for (int nt = 0; nt < 8; nt++) {
            const int col = n0 + wn * 64 + nt * 8 + (lane & 3) * 2;
            const int h = col >> 6;
            const int d = col & 63;
#pragma unroll
            for (int half = 0; half < 2; half++) {
                const int row = row_base + half * 8;
                const int b = row >> 11;
                const int t = row & 2047;
                float x0 = acc[mt][nt][half * 2];
                float x1 = acc[mt][nt][half * 2 + 1];
                float o0 = x0, o1 = x1;
                if (mode < 2) {
                    float2 cs = g_rope[t * 32 + (d >> 1)];
                    o0 = x0 * cs.x - x1 * cs.y;
                    o1 = x0 * cs.y + x1 * cs.x;
                }
                const int bh = b * NHEAD + h;
                if (mode == 0) {
                    size_t base = ((size_t)bh * TT + t) * HS + d;
                    *(unsigned*)(g_qh + base) =
                        pkh2f(o0 * QSCALE, o1 * QSCALE);
                } else if (mode == 1) {
                    size_t base = ((size_t)bh * TT + t) * HS + d;
                    *(unsigned*)(g_kh + base) = pkh2f(o0, o1);
                } else {
                    size_t tb = ((size_t)bh * HS + d) * TT + t;
                    g_vt[tb]      = __float2half_rn(o0);
                    g_vt[tb + TT] = __float2half_rn(o1);
                }
            }
        }
    }
}

// ---------------------------------------------------------------------------
// Output projection (x1): att fp16 @ WpT fp16 + bias -> fp32 out
// ---------------------------------------------------------------------------
__global__ void __launch_bounds__(256, 2) proj_gemm(
    const float* __restrict__ bp, float* __restrict__ out)
{
    extern __shared__ char smp[];
    const int m0 = blockIdx.y * 128;
    const int n0 = blockIdx.x * 128;

    float acc[2][8][4];
    gemm_main_x1(g_att, g_wt + (size_t)3 * CEMB * CEMB, m0, n0, smp, acc);

    const int warp = threadIdx.x >> 5;
    const int lane = threadIdx.x & 31;
    const int wm = warp >> 1;
    const int wn = warp & 1;

#pragma unroll
    for (int mt = 0; mt < 2; mt++) {
        const int row_base = m0 + wm * 32 + mt * 16 + (lane >> 2);
#pragma unroll
        for (int nt = 0; nt < 8; nt++) {
            const int col = n0 + wn * 64 + nt * 8 + (lane & 3) * 2;
            const float b0 = bp[col];
            const float b1 = bp[col + 1];
#pragma unroll
            for (int half = 0; half < 2; half++) {
                const int row = row_base + half * 8;
                *(float2*)(out + (size_t)row * CEMB + col) =
                    make_float2(acc[mt][nt][half * 2]     + b0,
                                acc[mt][nt][half * 2 + 1] + b1);
            }
        }
    }
}

// ---------------------------------------------------------------------------
// Flash attention, fp16 x1, PAIRED KV tiles: one cp.async batch + one barrier
// per 2 tiles. 3-stage pipeline over pair-stages {K0,V0,K1,V1}.
// BM=128 (8 warps x m16), BN=64 per tile, D=64. exp2-domain softmax.
// ---------------------------------------------------------------------------
#define KVS 72
#define KVROWB (KVS * 2)           // 144 B per row
#define FL_TPL (64 * KVROWB)       // 9216 B per tile plane (K or V)
#define FL_PRB (4 * FL_TPL)        // 36864 B per pair stage
#define FL_SMEM (3 * FL_PRB)       // 110592 B

__global__ void __launch_bounds__(256, 2) flash_fp16()
{
    extern __shared__ char fsm[];
    const uint32_t sb = smem_u32(fsm);

    const int tid  = threadIdx.x;
    const int warp = tid >> 5;
    const int lane = tid & 31;
    const int qt   = gridDim.x - 1 - blockIdx.x;   // big tiles first
    const int q0   = qt * 128;
    const int bh   = blockIdx.y;

    const __half* Q = g_qh + (size_t)bh * TT * HS;
    const __half* K = g_kh + (size_t)bh * TT * HS;
    const __half* V = g_vt + (size_t)bh * HS * TT;

    const int lr = lane >> 2;
    const int lc = lane & 3;
    const int lrow = warp * 16 + lr;
    const int grow_a = q0 + lrow;
    const int grow_b = grow_a + 8;

    unsigned qh[4][4];
#pragma unroll
    for (int ks = 0; ks < 4; ks++) {
        const int kd = ks * 16 + lc * 2;
        const __half* qa = Q + (size_t)grow_a * HS;
        const __half* qb = Q + (size_t)grow_b * HS;
        qh[ks][0] = *(const unsigned*)(qa + kd);
        qh[ks][1] = *(const unsigned*)(qb + kd);
        qh[ks][2] = *(const unsigned*)(qa + kd + 8);
        qh[ks][3] = *(const unsigned*)(qb + kd + 8);
    }

    const int sj  = tid >> 3;
    const int sdq = (tid & 7) * 8;
    const uint32_t kdst0 = (uint32_t)(sj * KVROWB + sdq * 2);
    const uint32_t kdst1 = (uint32_t)((sj + 32) * KVROWB + sdq * 2);

    // one pair = tiles 2*PAIR, 2*PAIR+1; stage holds {K0,V0,K1,V1}
#define FL_ISSUE(PAIR, S) do {                                           \
    uint32_t base_ = sb + (S) * FL_PRB;                                  \
    _Pragma("unroll")                                                    \
    for (int sub_ = 0; sub_ < 2; sub_++) {                               \
        const int k0_ = ((PAIR) * 2 + sub_) * 64;                        \
        uint32_t kb_ = base_ + sub_ * 2 * FL_TPL;                        \
        uint32_t vb_ = kb_ + FL_TPL;                                     \
        cpa16(kb_ + kdst0, K + (size_t)(k0_ + sj) * HS + sdq);           \
        cpa16(kb_ + kdst1, K + (size_t)(k0_ + sj + 32) * HS + sdq);      \
        cpa16(vb_ + kdst0, V + (size_t)sj * TT + k0_ + sdq);             \
        cpa16(vb_ + kdst1, V + (size_t)(sj + 32) * TT + k0_ + sdq);      \
    }                                                                    \
    CP_COMMIT();                                                         \
} while (0)

    float o[8][4];
#pragma unroll
    for (int nt = 0; nt < 8; nt++)
#pragma unroll
        for (int r = 0; r < 4; r++) o[nt][r] = 0.0f;
    float m_a = -1e30f, m_b = -1e30f, l_a = 0.0f, l_b = 0.0f;

    const int nkt = 2 * qt + 2;       // always even
    const int np  = nkt >> 1;
    FL_ISSUE(0, 0);
    if (np > 1) FL_ISSUE(1, 1);

    int stage = 0;
    for (int pp = 0; pp < np; pp++) {
        if (pp + 1 < np) CP_WAIT(1); else CP_WAIT(0);
        __syncthreads();

        if (pp + 2 < np) {
            int s2 = stage + 2; if (s2 >= 3) s2 -= 3;
            FL_ISSUE(pp + 2, s2);
        }

#pragma unroll
        for (int sub = 0; sub < 2; sub++) {
            const int kt = pp * 2 + sub;
            const char* kpl = fsm + stage * FL_PRB + sub * 2 * FL_TPL;
            const __half (*KSs)[KVS] = (const __half(*)[KVS])kpl;
            const __half (*VSs)[KVS] = (const __half(*)[KVS])(kpl + FL_TPL);
            const int k0 = kt * 64;

            float p[8][4];
#pragma unroll
            for (int nt = 0; nt < 8; nt++)
#pragma unroll
                for (int r = 0; r < 4; r++) p[nt][r] = 0.0f;

#pragma unroll
            for (int ks = 0; ks < 4; ks++) {
                const int kd = ks * 16 + lc * 2;
#pragma unroll
                for (int nt = 0; nt < 8; nt++) {
                    const int j = nt * 8 + lr;
                    unsigned b0 = *(const unsigned*)&KSs[j][kd];
                    unsigned b1 = *(const unsigned*)&KSs[j][kd + 8];
                    mma_fp16(p[nt], qh[ks], b0, b1);
                }
            }

            if (kt + 2 >= nkt) {
#pragma unroll
                for (int nt = 0; nt < 8; nt++) {
                    const int c = k0 + nt * 8 + lc * 2;
                    if (c     > grow_a) p[nt][0] = -1e30f;
                    if (c + 1 > grow_a) p[nt][1] = -1e30f;
                    if (c     > grow_b) p[nt][2] = -1e30f;
                    if (c + 1 > grow_b) p[nt][3] = -1e30f;
                }
            }

            float ma = -1e30f, mb2 = -1e30f;
#pragma unroll
            for (int nt = 0; nt < 8; nt++) {
                ma  = fmaxf(ma,  fmaxf(p[nt][0], p[nt][1]));
                mb2 = fmaxf(mb2, fmaxf(p[nt][2], p[nt][3]));
            }
            ma  = fmaxf(ma,  __shfl_xor_sync(0xffffffffu, ma, 1));
            ma  = fmaxf(ma,  __shfl_xor_sync(0xffffffffu, ma, 2));
            mb2 = fmaxf(mb2, __shfl_xor_sync(0xffffffffu, mb2, 1));
            mb2 = fmaxf(mb2, __shfl_xor_sync(0xffffffffu, mb2, 2));

            const float mna = fmaxf(m_a, ma);
            const float mnb = fmaxf(m_b, mb2);
            const float ca  = exp2f(m_a - mna);
            const float cbx = exp2f(m_b - mnb);

            float sa = 0.0f, sb2 = 0.0f;
#pragma unroll
            for (int nt = 0; nt < 8; nt++) {
                p[nt][0] = exp2f(p[nt][0] - mna);
                p[nt][1] = exp2f(p[nt][1] - mna);
                p[nt][2] = exp2f(p[nt][2] - mnb);
                p[nt][3] = exp2f(p[nt][3] - mnb);
                sa  += p[nt][0] + p[nt][1];
                sb2 += p[nt][2] + p[nt][3];
            }
            sa  += __shfl_xor_sync(0xffffffffu, sa, 1);
            sa  += __shfl_xor_sync(0xffffffffu, sa, 2);
            sb2 += __shfl_xor_sync(0xffffffffu, sb2, 1);
            sb2 += __shfl_xor_sync(0xffffffffu, sb2, 2);
            l_a = l_a * ca + sa;    m_a = mna;
            l_b = l_b * cbx + sb2;  m_b = mnb;

#pragma unroll
            for (int nt = 0; nt < 8; nt++) {
                o[nt][0] *= ca;  o[nt][1] *= ca;
                o[nt][2] *= cbx; o[nt][3] *= cbx;
            }

            unsigned pa[4][4];
#pragma unroll
            for (int g = 0; g < 4; g++) {
                pa[g][0] = pkh2f(p[2*g][0],   p[2*g][1]);
                pa[g][1] = pkh2f(p[2*g][2],   p[2*g][3]);
                pa[g][2] = pkh2f(p[2*g+1][0], p[2*g+1][1]);
                pa[g][3] = pkh2f(p[2*g+1][2], p[2*g+1][3]);
            }

#pragma unroll
            for (int g = 0; g < 4; g++) {
                const int j0 = g * 16 + lc * 2;
#pragma unroll
                for (int nt = 0; nt < 8; nt++) {
                    const int dcol = nt * 8 + lr;
                    unsigned b0 = *(const unsigned*)&VSs[dcol][j0];
                    unsigned b1 = *(const unsigned*)&VSs[dcol][j0 + 8];
                    mma_fp16(o[nt], pa[g], b0, b1);
                }
            }
        }
        if (++stage == 3) stage = 0;
    }
#undef FL_ISSUE

    const float rla = 1.0f / l_a;
    const float rlb = 1.0f / l_b;
    const int b = bh >> 4;
    const int h = bh & 15;
    size_t oa = ((size_t)b * TT + grow_a) * CEMB + h * HS;
    size_t ob = ((size_t)b * TT + grow_b) * CEMB + h * HS;
#pragma unroll
    for (int nt = 0; nt < 8; nt++) {
        const int col = nt * 8 + lc * 2;
        *(unsigned*)(g_att + oa + col) = pkh2f(o[nt][0] * rla, o[nt][1] * rla);
        *(unsigned*)(g_att + ob + col) = pkh2f(o[nt][2] * rlb, o[nt][3] * rlb);
    }
}

// ---------------------------------------------------------------------------
extern "C" void kernel_launch(void* const* d_in, const int* in_sizes, int n_in,
                              void* d_out, int out_size)
{
    (void)in_sizes; (void)n_in; (void)out_size;
    const float* x  = (const float*)d_in[0];
    const float* Wq = (const float*)d_in[1];
    const float* Wk = (const float*)d_in[2];
    const float* Wv = (const float*)d_in[3];
    const float* Wp = (const float*)d_in[4];
    const float* bp = (const float*)d_in[5];
    float* out = (float*)d_out;

    cudaFuncSetAttribute(qkv_gemm,
        cudaFuncAttributeMaxDynamicSharedMemorySize, GM1_SMEM);
    cudaFuncSetAttribute(proj_gemm,
        cudaFuncAttributeMaxDynamicSharedMemorySize, GM1_SMEM);
    cudaFuncSetAttribute(flash_fp16,
        cudaFuncAttributeMaxDynamicSharedMemorySize, FL_SMEM);

    prep_all<<<12544, 256>>>(x, Wq, Wk, Wv, Wp);

    qkv_gemm<<<dim3(CEMB / 128, MTOT / 128, 3), 256, GM1_SMEM>>>();

    flash_fp16<<<dim3(TT / 128, BB * NHEAD), 256, FL_SMEM>>>();

    proj_gemm<<<dim3(CEMB / 128, MTOT / 128), 256, GM1_SMEM>>>(bp, out);
}

// round 16
// speedup vs baseline: 2.7646x; 1.0218x over previous
#include <cuda_runtime.h>
#include <cuda_bf16.h>
#include <cuda_fp16.h>
#include <math.h>
#include <stdint.h>

#define NHEAD 16
#define HS    64
#define CEMB  1024
#define BB    4
#define TT    2048
#define MTOT  (BB*TT)          // 8192

// ---------------- device scratch (module-load allocated) -------------------
__device__ __align__(16) float2 g_rope[(size_t)TT*32];
__device__ __align__(16) __half g_qh[(size_t)BB*NHEAD*TT*HS];   // Q fp16 (scaled*log2e)
__device__ __align__(16) __half g_kh[(size_t)BB*NHEAD*TT*HS];   // K fp16 [bh][t][d]
__device__ __align__(16) __half g_vt[(size_t)BB*NHEAD*TT*HS];   // V fp16 [bh][d][t]
__device__ __align__(16) __half g_xh[(size_t)MTOT*CEMB];        // x fp16
__device__ __align__(16) __half g_wt[(size_t)4*CEMB*CEMB];      // [mat][n][k]
__device__ __align__(16) __half g_att[(size_t)MTOT*CEMB];       // att fp16

// ---------------- helpers ---------------------------------------------------
__device__ __forceinline__ void mma_fp16(float c[4], const unsigned a[4],
                                         unsigned b0, unsigned b1) {
    asm volatile(
        "mma.sync.aligned.m16n8k16.row.col.f32.f16.f16.f32 "
        "{%0,%1,%2,%3}, {%4,%5,%6,%7}, {%8,%9}, {%0,%1,%2,%3};\n"
        : "+f"(c[0]), "+f"(c[1]), "+f"(c[2]), "+f"(c[3])
        : "r"(a[0]), "r"(a[1]), "r"(a[2]), "r"(a[3]),
          "r"(b0), "r"(b1));
}

__device__ __forceinline__ void ldsm4(unsigned r[4], uint32_t addr) {
    asm volatile(
        "ldmatrix.sync.aligned.m8n8.x4.shared.b16 {%0,%1,%2,%3}, [%4];"
        : "=r"(r[0]), "=r"(r[1]), "=r"(r[2]), "=r"(r[3]) : "r"(addr));
}

__device__ __forceinline__ unsigned pkh(__half x, __half y) {
    unsigned short a = *(unsigned short*)&x, b = *(unsigned short*)&y;
    return (unsigned)a | ((unsigned)b << 16);
}
__device__ __forceinline__ unsigned pkh2f(float a, float b) {
    return pkh(__float2half_rn(a), __float2half_rn(b));
}

__device__ __forceinline__ uint32_t smem_u32(const void* p) {
    uint32_t a;
    asm("{ .reg .u64 t; cvta.to.shared.u64 t, %1; cvt.u32.u64 %0, t; }"
        : "=r"(a) : "l"(p));
    return a;
}
__device__ __forceinline__ void cpa16(uint32_t dst, const void* src) {
    asm volatile("cp.async.cg.shared.global [%0], [%1], 16;\n"
                 :: "r"(dst), "l"(src));
}
#define CP_COMMIT() asm volatile("cp.async.commit_group;\n" ::: "memory")
#define CP_WAIT(n)  asm volatile("cp.async.wait_group %0;\n" :: "n"(n) : "memory")

// ---------------------------------------------------------------------------
// Fused prep: blocks [0,8192) round x; [8192,12288) transpose+round W;
// [12288,12544) RoPE table.
// ---------------------------------------------------------------------------
__global__ void __launch_bounds__(256) prep_all(
    const float* __restrict__ x,
    const float* __restrict__ Wq, const float* __restrict__ Wk,
    const float* __restrict__ Wv, const float* __restrict__ Wp)
{
    __shared__ float tile[32][33];
    const int bid = blockIdx.x;
    const int tid = threadIdx.x;

    if (bid < 8192) {
        int i = bid * 256 + tid;
        float4 v = ((const float4*)x)[i];
        ((uint2*)g_xh)[i] = make_uint2(pkh2f(v.x, v.y), pkh2f(v.z, v.w));
    } else if (bid < 12288) {
        const int b2 = bid - 8192;
        const int z = b2 >> 10;
        const int rem = b2 & 1023;
        const int by = rem >> 5;
        const int bx = rem & 31;
        const float* W = (z == 0) ? Wq : ((z == 1) ? Wk : ((z == 2) ? Wv : Wp));
        __half* outh = g_wt + (size_t)z * CEMB * CEMB;
        const int tx = tid & 31;
        const int ty = tid >> 5;
        const int k0 = by * 32;
        const int nn0 = bx * 32;
#pragma unroll
        for (int j = 0; j < 4; j++)
            tile[ty + 8 * j][tx] =
                W[(size_t)(k0 + ty + 8 * j) * CEMB + nn0 + tx];
        __syncthreads();
#pragma unroll
        for (int j = 0; j < 4; j++) {
            float v = tile[tx][ty + 8 * j];
            outh[(size_t)(nn0 + ty + 8 * j) * CEMB + k0 + tx] =
                __float2half_rn(v);
        }
    } else {
        int idx = (bid - 12288) * 256 + tid;
        int t = idx >> 5, p = idx & 31;
        const float L2T = 13.287712379549449f / 64.0f;
        float inv = exp2f(-(float)(2 * p) * L2T);
        float sv, cv;
        sincosf((float)t * inv, &sv, &cv);
        g_rope[idx] = make_float2(cv, sv);
    }
}

// ---------------------------------------------------------------------------
// fp16 x1 LDSM GEMM, BK=64, 3-stage cp.async, one barrier per chunk (r14).
// ---------------------------------------------------------------------------
#define PL_B    18432
#define STG1_B  36864
#define GM1_SMEM (3 * STG1_B)  // 110592

__device__ __forceinline__ void gemm_main_x1(
    const __half* __restrict__ Ag, const __half* __restrict__ Bg,
    int m0, int n0, char* smp, float acc[2][8][4])
{
    const int tid  = threadIdx.x;
    const int warp = tid >> 5;
    const int lane = tid & 31;
    const int wm = warp >> 1;
    const int wn = warp & 1;
    const uint32_t sb = smem_u32(smp);

#pragma unroll
    for (int mt = 0; mt < 2; mt++)
#pragma unroll
        for (int nt = 0; nt < 8; nt++)
#pragma unroll
            for (int r = 0; r < 4; r++) acc[mt][nt][r] = 0.0f;

    const __half* sp[8];
    uint32_t doff[8];
#pragma unroll
    for (int i = 0; i < 8; i++) {
        int g = i * 256 + tid;
        int pl = g >> 10;
        int r  = (g >> 3) & 127;
        int sq = g & 7;
        const __half* base = pl ? Bg : Ag;
        int rbase = pl ? n0 : m0;
        sp[i]   = base + (size_t)(rbase + r) * CEMB + sq * 8;
        doff[i] = (uint32_t)(pl * PL_B + r * 144 + sq * 16);
    }

#define GM1_ISSUE(CK, S) do {                                 \
    const int kb_ = (CK) * 64;                                \
    uint32_t st_ = sb + (S) * STG1_B;                         \
    _Pragma("unroll")                                         \
    for (int i = 0; i < 8; i++)                               \
        cpa16(st_ + doff[i], sp[i] + kb_);                    \
    CP_COMMIT();                                              \
} while (0)

    GM1_ISSUE(0, 0);
    GM1_ISSUE(1, 1);

    const int a_row = lane & 15;
    const int a_kh  = lane >> 4;
    const uint32_t aoff = (uint32_t)((wm * 32 + a_row) * 144 + a_kh * 16);
    const int b_n  = ((lane >> 4) << 3) + (lane & 7);
    const int b_kh = (lane >> 3) & 1;
    const uint32_t boff = (uint32_t)(PL_B + (wn * 64 + b_n) * 144 + b_kh * 16);

    int stage = 0;
    for (int ck = 0; ck < 16; ck++) {
        if (ck + 1 < 16) CP_WAIT(1); else CP_WAIT(0);
        __syncthreads();

        if (ck + 2 < 16) {
            int s2 = stage + 2; if (s2 >= 3) s2 -= 3;
            GM1_ISSUE(ck + 2, s2);
        }

        const uint32_t st = sb + stage * STG1_B;
#pragma unroll
        for (int kk = 0; kk < 4; kk++) {
            unsigned Ah[2][4];
#pragma unroll
            for (int mt = 0; mt < 2; mt++)
                ldsm4(Ah[mt], st + aoff + mt * 2304 + kk * 32);
#pragma unroll
            for (int ntp = 0; ntp < 4; ntp++) {
                unsigned Bh[4];
                ldsm4(Bh, st + boff + ntp * 2304 + kk * 32);
#pragma unroll
                for (int mt = 0; mt < 2; mt++) {
                    mma_fp16(acc[mt][ntp * 2 + 0], Ah[mt], Bh[0], Bh[1]);
                    mma_fp16(acc[mt][ntp * 2 + 1], Ah[mt], Bh[2], Bh[3]);
                }
            }
        }
        if (++stage == 3) stage = 0;
    }
#undef GM1_ISSUE
}

// ---------------------------------------------------------------------------
// QKV (x1): mode 0=Q(+RoPE)->fp16 scaled*log2e, 1=K(+RoPE)->fp16, 2=V->trans
// ---------------------------------------------------------------------------
__global__ void __launch_bounds__(256, 2) qkv_gemm()
{
    extern __shared__ char smp[];
    const int mode = blockIdx.z;
    const int m0 = blockIdx.y * 128;
    const int n0 = blockIdx.x * 128;

    float acc[2][8][4];
    gemm_main_x1(g_xh, g_wt + (size_t)mode * CEMB * CEMB, m0, n0, smp, acc);

    const int warp = threadIdx.x >> 5;
    const int lane = threadIdx.x & 31;
    const int wm = warp >> 1;
    const int wn = warp & 1;
    const float QSCALE = 0.125f * 1.4426950408889634f;

#pragma unroll
    for (int mt = 0; mt < 2; mt++) {
        const int row_base = m0 + wm * 32 + mt * 16 + (lane >> 2);
#pragma unroll
        for (int nt = 0; nt < 8; nt++) {
            const int col = n0 + wn * 64 + nt * 8 + (lane & 3) * 2;
            const int h = col >> 6;
            const int d = col & 63;
#pragma unroll
            for (int half = 0; half < 2; half++) {
                const int row = row_base + half * 8;
                const int b = row >> 11;
                const int t = row & 2047;
                float x0 = acc[mt][nt][half * 2];
                float x1 = acc[mt][nt][half * 2 + 1];
                float o0 = x0, o1 = x1;
                if (mode < 2) {
                    float2 cs = g_rope[t * 32 + (d >> 1)];
                    o0 = x0 * cs.x - x1 * cs.y;
                    o1 = x0 * cs.y + x1 * cs.x;
                }
                const int bh = b * NHEAD + h;
                if (mode == 0) {
                    size_t base = ((size_t)bh * TT + t) * HS + d;
                    *(unsigned*)(g_qh + base) =
                        pkh2f(o0 * QSCALE, o1 * QSCALE);
                } else if (mode == 1) {
                    size_t base = ((size_t)bh * TT + t) * HS + d;
                    *(unsigned*)(g_kh + base) = pkh2f(o0, o1);
                } else {
                    size_t tb = ((size_t)bh * HS + d) * TT + t;
                    g_vt[tb]      = __float2half_rn(o0);
                    g_vt[tb + TT] = __float2half_rn(o1);
                }
            }
        }
    }
}

// ---------------------------------------------------------------------------
// Output projection (x1): att fp16 @ WpT fp16 + bias -> fp32 out
// ---------------------------------------------------------------------------
__global__ void __launch_bounds__(256, 2) proj_gemm(
    const float* __restrict__ bp, float* __restrict__ out)
{
    extern __shared__ char smp[];
    const int m0 = blockIdx.y * 128;
    const int n0 = blockIdx.x * 128;

    float acc[2][8][4];
    gemm_main_x1(g_att, g_wt + (size_t)3 * CEMB * CEMB, m0, n0, smp, acc);

    const int warp = threadIdx.x >> 5;
    const int lane = threadIdx.x & 31;
    const int wm = warp >> 1;
    const int wn = warp & 1;

#pragma unroll
    for (int mt = 0; mt < 2; mt++) {
        const int row_base = m0 + wm * 32 + mt * 16 + (lane >> 2);
#pragma unroll
        for (int nt = 0; nt < 8; nt++) {
            const int col = n0 + wn * 64 + nt * 8 + (lane & 3) * 2;
            const float b0 = bp[col];
            const float b1 = bp[col + 1];
#pragma unroll
            for (int half = 0; half < 2; half++) {
                const int row = row_base + half * 8;
                *(float2*)(out + (size_t)row * CEMB + col) =
                    make_float2(acc[mt][nt][half * 2]     + b0,
                                acc[mt][nt][half * 2 + 1] + b1);
            }
        }
    }
}

// ---------------------------------------------------------------------------
// Flash attention, fp16 x1, paired KV tiles, ldmatrix B-fragments.
// BM=128 (8 warps x m16), BN=64 per tile. exp2-domain softmax.
// KS [j][d] rows 144B (n=j, k=d); VS [d][j] rows 144B (n=d, k=j) — both are
// native m16n8k16 B layouts; ldsm addressing identical to the GEMM's.
// ---------------------------------------------------------------------------
#define KVS 72
#define KVROWB (KVS * 2)           // 144 B per row
#define FL_TPL (64 * KVROWB)       // 9216 B per tile plane (K or V)
#define FL_PRB (4 * FL_TPL)        // 36864 B per pair stage
#define FL_SMEM (3 * FL_PRB)       // 110592 B

__global__ void __launch_bounds__(256, 2) flash_fp16()
{
    extern __shared__ char fsm[];
    const uint32_t sb = smem_u32(fsm);

    const int tid  = threadIdx.x;
    const int warp = tid >> 5;
    const int lane = tid & 31;
    const int qt   = gridDim.x - 1 - blockIdx.x;   // big tiles first
    const int q0   = qt * 128;
    const int bh   = blockIdx.y;

    const __half* Q = g_qh + (size_t)bh * TT * HS;
    const __half* K = g_kh + (size_t)bh * TT * HS;
    const __half* V = g_vt + (size_t)bh * HS * TT;

    const int lr = lane >> 2;
    const int lc = lane & 3;
    const int lrow = warp * 16 + lr;
    const int grow_a = q0 + lrow;
    const int grow_b = grow_a + 8;

    // ldmatrix B lane addressing (validated in GEMM)
    const int b_n  = ((lane >> 4) << 3) + (lane & 7);
    const int b_kh = (lane >> 3) & 1;
    const uint32_t boff = (uint32_t)(b_n * KVROWB + b_kh * 16);

    unsigned qh[4][4];
#pragma unroll
    for (int ks = 0; ks < 4; ks++) {
        const int kd = ks * 16 + lc * 2;
        const __half* qa = Q + (size_t)grow_a * HS;
        const __half* qb = Q + (size_t)grow_b * HS;
        qh[ks][0] = *(const unsigned*)(qa + kd);
        qh[ks][1] = *(const unsigned*)(qb + kd);
        qh[ks][2] = *(const unsigned*)(qa + kd + 8);
        qh[ks][3] = *(const unsigned*)(qb + kd + 8);
    }

    const int sj  = tid >> 3;
    const int sdq = (tid & 7) * 8;
    const uint32_t kdst0 = (uint32_t)(sj * KVROWB + sdq * 2);
    const uint32_t kdst1 = (uint32_t)((sj + 32) * KVROWB + sdq * 2);

#define FL_ISSUE(PAIR, S) do {                                           \
    uint32_t base_ = sb + (S) * FL_PRB;                                  \
    _Pragma("unroll")                                                    \
    for (int sub_ = 0; sub_ < 2; sub_++) {                               \
        const int k0_ = ((PAIR) * 2 + sub_) * 64;                        \
        uint32_t kb_ = base_ + sub_ * 2 * FL_TPL;                        \
        uint32_t vb_ = kb_ + FL_TPL;                                     \
        cpa16(kb_ + kdst0, K + (size_t)(k0_ + sj) * HS + sdq);           \
        cpa16(kb_ + kdst1, K + (size_t)(k0_ + sj + 32) * HS + sdq);      \
        cpa16(vb_ + kdst0, V + (size_t)sj * TT + k0_ + sdq);             \
        cpa16(vb_ + kdst1, V + (size_t)(sj + 32) * TT + k0_ + sdq);      \
    }                                                                    \
    CP_COMMIT();                                                         \
} while (0)

    float o[8][4];
#pragma unroll
    for (int nt = 0; nt < 8; nt++)
#pragma unroll
        for (int r = 0; r < 4; r++) o[nt][r] = 0.0f;
    float m_a = -1e30f, m_b = -1e30f, l_a = 0.0f, l_b = 0.0f;

    const int nkt = 2 * qt + 2;       // always even
    const int np  = nkt >> 1;
    FL_ISSUE(0, 0);
    if (np > 1) FL_ISSUE(1, 1);

    int stage = 0;
    for (int pp = 0; pp < np; pp++) {
        if (pp + 1 < np) CP_WAIT(1); else CP_WAIT(0);
        __syncthreads();

        if (pp + 2 < np) {
            int s2 = stage + 2; if (s2 >= 3) s2 -= 3;
            FL_ISSUE(pp + 2, s2);
        }

#pragma unroll
        for (int sub = 0; sub < 2; sub++) {
            const int kt = pp * 2 + sub;
            const uint32_t ktile = sb + stage * FL_PRB + sub * 2 * FL_TPL;
            const uint32_t vtile = ktile + FL_TPL;
            const int k0 = kt * 64;

            // S = Q K^T via ldsm4 B-fragments
            float p[8][4];
#pragma unroll
            for (int nt = 0; nt < 8; nt++)
#pragma unroll
                for (int r = 0; r < 4; r++) p[nt][r] = 0.0f;

#pragma unroll
            for (int ks = 0; ks < 4; ks++) {
#pragma unroll
                for (int ntp = 0; ntp < 4; ntp++) {
                    unsigned Bh[4];
                    ldsm4(Bh, ktile + boff + ntp * 16 * KVROWB + ks * 32);
                    mma_fp16(p[ntp * 2 + 0], qh[ks], Bh[0], Bh[1]);
                    mma_fp16(p[ntp * 2 + 1], qh[ks], Bh[2], Bh[3]);
                }
            }

            if (kt + 2 >= nkt) {
#pragma unroll
                for (int nt = 0; nt < 8; nt++) {
                    const int c = k0 + nt * 8 + lc * 2;
                    if (c     > grow_a) p[nt][0] = -1e30f;
                    if (c + 1 > grow_a) p[nt][1] = -1e30f;
                    if (c     > grow_b) p[nt][2] = -1e30f;
                    if (c + 1 > grow_b) p[nt][3] = -1e30f;
                }
            }

            float ma = -1e30f, mb2 = -1e30f;
#pragma unroll
            for (int nt = 0; nt < 8; nt++) {
                ma  = fmaxf(ma,  fmaxf(p[nt][0], p[nt][1]));
                mb2 = fmaxf(mb2, fmaxf(p[nt][2], p[nt][3]));
            }
            ma  = fmaxf(ma,  __shfl_xor_sync(0xffffffffu, ma, 1));
            ma  = fmaxf(ma,  __shfl_xor_sync(0xffffffffu, ma, 2));
            mb2 = fmaxf(mb2, __shfl_xor_sync(0xffffffffu, mb2, 1));
            mb2 = fmaxf(mb2, __shfl_xor_sync(0xffffffffu, mb2, 2));

            const float mna = fmaxf(m_a, ma);
            const float mnb = fmaxf(m_b, mb2);
            const float ca  = exp2f(m_a - mna);
            const float cbx = exp2f(m_b - mnb);

            float sa = 0.0f, sb2 = 0.0f;
#pragma unroll
            for (int nt = 0; nt < 8; nt++) {
                p[nt][0] = exp2f(p[nt][0] - mna);
                p[nt][1] = exp2f(p[nt][1] - mna);
                p[nt][2] = exp2f(p[nt][2] - mnb);
                p[nt][3] = exp2f(p[nt][3] - mnb);
                sa  += p[nt][0] + p[nt][1];
                sb2 += p[nt][2] + p[nt][3];
            }
            sa  += __shfl_xor_sync(0xffffffffu, sa, 1);
            sa  += __shfl_xor_sync(0xffffffffu, sa, 2);
            sb2 += __shfl_xor_sync(0xffffffffu, sb2, 1);
            sb2 += __shfl_xor_sync(0xffffffffu, sb2, 2);
            l_a = l_a * ca + sa;    m_a = mna;
            l_b = l_b * cbx + sb2;  m_b = mnb;

#pragma unroll
            for (int nt = 0; nt < 8; nt++) {
                o[nt][0] *= ca;  o[nt][1] *= ca;
                o[nt][2] *= cbx; o[nt][3] *= cbx;
            }

            unsigned pa[4][4];
#pragma unroll
            for (int g = 0; g < 4; g++) {
                pa[g][0] = pkh2f(p[2*g][0],   p[2*g][1]);
                pa[g][1] = pkh2f(p[2*g][2],   p[2*g][3]);
                pa[g][2] = pkh2f(p[2*g+1][0], p[2*g+1][1]);
                pa[g][3] = pkh2f(p[2*g+1][2], p[2*g+1][3]);
            }

            // O += P V via ldsm4 B-fragments (VS rows = d, cols = j)
#pragma unroll
            for (int g = 0; g < 4; g++) {
#pragma unroll
                for (int ntp = 0; ntp < 4; ntp++) {
                    unsigned Bv[4];
                    ldsm4(Bv, vtile + boff + ntp * 16 * KVROWB + g * 32);
                    mma_fp16(o[ntp * 2 + 0], pa[g], Bv[0], Bv[1]);
                    mma_fp16(o[ntp * 2 + 1], pa[g], Bv[2], Bv[3]);
                }
            }
        }
        if (++stage == 3) stage = 0;
    }
#undef FL_ISSUE

    const float rla = 1.0f / l_a;
    const float rlb = 1.0f / l_b;
    const int b = bh >> 4;
    const int h = bh & 15;
    size_t oa = ((size_t)b * TT + grow_a) * CEMB + h * HS;
    size_t ob = ((size_t)b * TT + grow_b) * CEMB + h * HS;
#pragma unroll
    for (int nt = 0; nt < 8; nt++) {
        const int col = nt * 8 + lc * 2;
        *(unsigned*)(g_att + oa + col) = pkh2f(o[nt][0] * rla, o[nt][1] * rla);
        *(unsigned*)(g_att + ob + col) = pkh2f(o[nt][2] * rlb, o[nt][3] * rlb);
    }
}

// ---------------------------------------------------------------------------
extern "C" void kernel_launch(void* const* d_in, const int* in_sizes, int n_in,
                              void* d_out, int out_size)
{
    (void)in_sizes; (void)n_in; (void)out_size;
    const float* x  = (const float*)d_in[0];
    const float* Wq = (const float*)d_in[1];
    const float* Wk = (const float*)d_in[2];
    const float* Wv = (const float*)d_in[3];
    const float* Wp = (const float*)d_in[4];
    const float* bp = (const float*)d_in[5];
    float* out = (float*)d_out;

    cudaFuncSetAttribute(qkv_gemm,
        cudaFuncAttributeMaxDynamicSharedMemorySize, GM1_SMEM);
    cudaFuncSetAttribute(proj_gemm,
        cudaFuncAttributeMaxDynamicSharedMemorySize, GM1_SMEM);
    cudaFuncSetAttribute(flash_fp16,
        cudaFuncAttributeMaxDynamicSharedMemorySize, FL_SMEM);

    prep_all<<<12544, 256>>>(x, Wq, Wk, Wv, Wp);

    qkv_gemm<<<dim3(CEMB / 128, MTOT / 128, 3), 256, GM1_SMEM>>>();

    flash_fp16<<<dim3(TT / 128, BB * NHEAD), 256, FL_SMEM>>>();

    proj_gemm<<<dim3(CEMB / 128, MTOT / 128), 256, GM1_SMEM>>>(bp, out);
}

// round 17
// speedup vs baseline: 2.9711x; 1.0747x over previous
#include <cuda_runtime.h>
#include <cuda_bf16.h>
#include <cuda_fp16.h>
#include <math.h>
#include <stdint.h>

#define NHEAD 16
#define HS    64
#define CEMB  1024
#define BB    4
#define TT    2048
#define MTOT  (BB*TT)          // 8192

// ---------------- device scratch (module-load allocated) -------------------
__device__ __align__(16) float2 g_rope[(size_t)TT*32];
__device__ __align__(16) __half g_qh[(size_t)BB*NHEAD*TT*HS];   // Q fp16 (scaled*log2e)
__device__ __align__(16) __half g_kh[(size_t)BB*NHEAD*TT*HS];   // K fp16 [bh][t][d]
__device__ __align__(16) __half g_vt[(size_t)BB*NHEAD*TT*HS];   // V fp16 [bh][d][t]
__device__ __align__(16) __half g_xh[(size_t)MTOT*CEMB];        // x fp16
__device__ __align__(16) __half g_wt[(size_t)4*CEMB*CEMB];      // [mat][n][k]
__device__ __align__(16) __half g_att[(size_t)MTOT*CEMB];       // att fp16

// ---------------- helpers ---------------------------------------------------
__device__ __forceinline__ void mma_fp16(float c[4], const unsigned a[4],
                                         unsigned b0, unsigned b1) {
    asm volatile(
        "mma.sync.aligned.m16n8k16.row.col.f32.f16.f16.f32 "
        "{%0,%1,%2,%3}, {%4,%5,%6,%7}, {%8,%9}, {%0,%1,%2,%3};\n"
        : "+f"(c[0]), "+f"(c[1]), "+f"(c[2]), "+f"(c[3])
        : "r"(a[0]), "r"(a[1]), "r"(a[2]), "r"(a[3]),
          "r"(b0), "r"(b1));
}

__device__ __forceinline__ void ldsm4(unsigned r[4], uint32_t addr) {
    asm volatile(
        "ldmatrix.sync.aligned.m8n8.x4.shared.b16 {%0,%1,%2,%3}, [%4];"
        : "=r"(r[0]), "=r"(r[1]), "=r"(r[2]), "=r"(r[3]) : "r"(addr));
}

__device__ __forceinline__ unsigned pkh(__half x, __half y) {
    unsigned short a = *(unsigned short*)&x, b = *(unsigned short*)&y;
    return (unsigned)a | ((unsigned)b << 16);
}
__device__ __forceinline__ unsigned pkh2f(float a, float b) {
    return pkh(__float2half_rn(a), __float2half_rn(b));
}

__device__ __forceinline__ uint32_t smem_u32(const void* p) {
    uint32_t a;
    asm("{ .reg .u64 t; cvta.to.shared.u64 t, %1; cvt.u32.u64 %0, t; }"
        : "=r"(a) : "l"(p));
    return a;
}
__device__ __forceinline__ void cpa16(uint32_t dst, const void* src) {
    asm volatile("cp.async.cg.shared.global [%0], [%1], 16;\n"
                 :: "r"(dst), "l"(src));
}
#define CP_COMMIT() asm volatile("cp.async.commit_group;\n" ::: "memory")
#define CP_WAIT(n)  asm volatile("cp.async.wait_group %0;\n" :: "n"(n) : "memory")

// ---------------------------------------------------------------------------
// Fused prep: blocks [0,8192) round x; [8192,12288) transpose+round W;
// [12288,12544) RoPE table.
// ---------------------------------------------------------------------------
__global__ void __launch_bounds__(256) prep_all(
    const float* __restrict__ x,
    const float* __restrict__ Wq, const float* __restrict__ Wk,
    const float* __restrict__ Wv, const float* __restrict__ Wp)
{
    __shared__ float tile[32][33];
    const int bid = blockIdx.x;
    const int tid = threadIdx.x;

    if (bid < 8192) {
        int i = bid * 256 + tid;
        float4 v = ((const float4*)x)[i];
        ((uint2*)g_xh)[i] = make_uint2(pkh2f(v.x, v.y), pkh2f(v.z, v.w));
    } else if (bid < 12288) {
        const int b2 = bid - 8192;
        const int z = b2 >> 10;
        const int rem = b2 & 1023;
        const int by = rem >> 5;
        const int bx = rem & 31;
        const float* W = (z == 0) ? Wq : ((z == 1) ? Wk : ((z == 2) ? Wv : Wp));
        __half* outh = g_wt + (size_t)z * CEMB * CEMB;
        const int tx = tid & 31;
        const int ty = tid >> 5;
        const int k0 = by * 32;
        const int nn0 = bx * 32;
#pragma unroll
        for (int j = 0; j < 4; j++)
            tile[ty + 8 * j][tx] =
                W[(size_t)(k0 + ty + 8 * j) * CEMB + nn0 + tx];
        __syncthreads();
#pragma unroll
        for (int j = 0; j < 4; j++) {
            float v = tile[tx][ty + 8 * j];
            outh[(size_t)(nn0 + ty + 8 * j) * CEMB + k0 + tx] =
                __float2half_rn(v);
        }
    } else {
        int idx = (bid - 12288) * 256 + tid;
        int t = idx >> 5, p = idx & 31;
        const float L2T = 13.287712379549449f / 64.0f;
        float inv = exp2f(-(float)(2 * p) * L2T);
        float sv, cv;
        sincosf((float)t * inv, &sv, &cv);
        g_rope[idx] = make_float2(cv, sv);
    }
}

// ---------------------------------------------------------------------------
// fp16 x1 LDSM GEMM, BK=64, 3-stage cp.async, one barrier per chunk (r14).
// ---------------------------------------------------------------------------
#define PL_B    18432
#define STG1_B  36864
#define GM1_SMEM (3 * STG1_B)  // 110592

__device__ __forceinline__ void gemm_main_x1(
    const __half* __restrict__ Ag, const __half* __restrict__ Bg,
    int m0, int n0, char* smp, float acc[2][8][4])
{
    const int tid  = threadIdx.x;
    const int warp = tid >> 5;
    const int lane = tid & 31;
    const int wm = warp >> 1;
    const int wn = warp & 1;
    const uint32_t sb = smem_u32(smp);

#pragma unroll
    for (int mt = 0; mt < 2; mt++)
#pragma unroll
        for (int nt = 0; nt < 8; nt++)
#pragma unroll
            for (int r = 0; r < 4; r++) acc[mt][nt][r] = 0.0f;

    const __half* sp[8];
    uint32_t doff[8];
#pragma unroll
    for (int i = 0; i < 8; i++) {
        int g = i * 256 + tid;
        int pl = g >> 10;
        int r  = (g >> 3) & 127;
        int sq = g & 7;
        const __half* base = pl ? Bg : Ag;
        int rbase = pl ? n0 : m0;
        sp[i]   = base + (size_t)(rbase + r) * CEMB + sq * 8;
        doff[i] = (uint32_t)(pl * PL_B + r * 144 + sq * 16);
    }

#define GM1_ISSUE(CK, S) do {                                 \
    const int kb_ = (CK) * 64;                                \
    uint32_t st_ = sb + (S) * STG1_B;                         \
    _Pragma("unroll")                                         \
    for (int i = 0; i < 8; i++)                               \
        cpa16(st_ + doff[i], sp[i] + kb_);                    \
    CP_COMMIT();                                              \
} while (0)

    GM1_ISSUE(0, 0);
    GM1_ISSUE(1, 1);

    const int a_row = lane & 15;
    const int a_kh  = lane >> 4;
    const uint32_t aoff = (uint32_t)((wm * 32 + a_row) * 144 + a_kh * 16);
    const int b_n  = ((lane >> 4) << 3) + (lane & 7);
    const int b_kh = (lane >> 3) & 1;
    const uint32_t boff = (uint32_t)(PL_B + (wn * 64 + b_n) * 144 + b_kh * 16);

    int stage = 0;
    for (int ck = 0; ck < 16; ck++) {
        if (ck + 1 < 16) CP_WAIT(1); else CP_WAIT(0);
        __syncthreads();

        if (ck + 2 < 16) {
            int s2 = stage + 2; if (s2 >= 3) s2 -= 3;
            GM1_ISSUE(ck + 2, s2);
        }

        const uint32_t st = sb + stage * STG1_B;
#pragma unroll
        for (int kk = 0; kk < 4; kk++) {
            unsigned Ah[2][4];
#pragma unroll
            for (int mt = 0; mt < 2; mt++)
                ldsm4(Ah[mt], st + aoff + mt * 2304 + kk * 32);
#pragma unroll
            for (int ntp = 0; ntp < 4; ntp++) {
                unsigned Bh[4];
                ldsm4(Bh, st + boff + ntp * 2304 + kk * 32);
#pragma unroll
                for (int mt = 0; mt < 2; mt++) {
                    mma_fp16(acc[mt][ntp * 2 + 0], Ah[mt], Bh[0], Bh[1]);
                    mma_fp16(acc[mt][ntp * 2 + 1], Ah[mt], Bh[2], Bh[3]);
                }
            }
        }
        if (++stage == 3) stage = 0;
    }
#undef GM1_ISSUE
}

// ---------------------------------------------------------------------------
// QKV (x1): mode 0=Q(+RoPE)->fp16 scaled*log2e, 1=K(+RoPE)->fp16, 2=V->trans
// ---------------------------------------------------------------------------
__global__ void __launch_bounds__(256, 2) qkv_gemm()
{
    extern __shared__ char smp[];
    const int mode = blockIdx.z;
    const int m0 = blockIdx.y * 128;
    const int n0 = blockIdx.x * 128;

    float acc[2][8][4];
    gemm_main_x1(g_xh, g_wt + (size_t)mode * CEMB * CEMB, m0, n0, smp, acc);

    const int warp = threadIdx.x >> 5;
    const int lane = threadIdx.x & 31;
    const int wm = warp >> 1;
    const int wn = warp & 1;
    const float QSCALE = 0.125f * 1.4426950408889634f;

#pragma unroll
    for (int mt = 0; mt < 2; mt++) {
        const int row_base = m0 + wm * 32 + mt * 16 + (lane >> 2);
#pragma unroll
        for (int nt = 0; nt < 8; nt++) {
            const int col = n0 + wn * 64 + nt * 8 + (lane & 3) * 2;
            const int h = col >> 6;
            const int d = col & 63;
#pragma unroll
            for (int half = 0; half < 2; half++) {
                const int row = row_base + half * 8;
                const int b = row >> 11;
                const int t = row & 2047;
                float x0 = acc[mt][nt][half * 2];
                float x1 = acc[mt][nt][half * 2 + 1];
                float o0 = x0, o1 = x1;
                if (mode < 2) {
                    float2 cs = g_rope[t * 32 + (d >> 1)];
                    o0 = x0 * cs.x - x1 * cs.y;
                    o1 = x0 * cs.y + x1 * cs.x;
                }
                const int bh = b * NHEAD + h;
                if (mode == 0) {
                    size_t base = ((size_t)bh * TT + t) * HS + d;
                    *(unsigned*)(g_qh + base) =
                        pkh2f(o0 * QSCALE, o1 * QSCALE);
                } else if (mode == 1) {
                    size_t base = ((size_t)bh * TT + t) * HS + d;
                    *(unsigned*)(g_kh + base) = pkh2f(o0, o1);
                } else {
                    size_t tb = ((size_t)bh * HS + d) * TT + t;
                    g_vt[tb]      = __float2half_rn(o0);
                    g_vt[tb + TT] = __float2half_rn(o1);
                }
            }
        }
    }
}

// ---------------------------------------------------------------------------
// Output projection (x1): att fp16 @ WpT fp16 + bias -> fp32 out
// ---------------------------------------------------------------------------
__global__ void __launch_bounds__(256, 2) proj_gemm(
    const float* __restrict__ bp, float* __restrict__ out)
{
    extern __shared__ char smp[];
    const int m0 = blockIdx.y * 128;
    const int n0 = blockIdx.x * 128;

    float acc[2][8][4];
    gemm_main_x1(g_att, g_wt + (size_t)3 * CEMB * CEMB, m0, n0, smp, acc);

    const int warp = threadIdx.x >> 5;
    const int lane = threadIdx.x & 31;
    const int wm = warp >> 1;
    const int wn = warp & 1;

#pragma unroll
    for (int mt = 0; mt < 2; mt++) {
        const int row_base = m0 + wm * 32 + mt * 16 + (lane >> 2);
#pragma unroll
        for (int nt = 0; nt < 8; nt++) {
            const int col = n0 + wn * 64 + nt * 8 + (lane & 3) * 2;
            const float b0 = bp[col];
            const float b1 = bp[col + 1];
#pragma unroll
            for (int half = 0; half < 2; half++) {
                const int row = row_base + half * 8;
                *(float2*)(out + (size_t)row * CEMB + col) =
                    make_float2(acc[mt][nt][half * 2]     + b0,
                                acc[mt][nt][half * 2 + 1] + b1);
            }
        }
    }
}

// ---------------------------------------------------------------------------
// Flash attention, fp16 x1, paired KV tiles, ldmatrix B-fragments.
// Grid (bh, qtile): qtile on Y reversed -> all big tiles launch first
// globally (greedy wave balance). BM=128, BN=64/tile, exp2-domain softmax.
// ---------------------------------------------------------------------------
#define KVS 72
#define KVROWB (KVS * 2)           // 144 B per row
#define FL_TPL (64 * KVROWB)       // 9216 B per tile plane (K or V)
#define FL_PRB (4 * FL_TPL)        // 36864 B per pair stage
#define FL_SMEM (3 * FL_PRB)       // 110592 B

__global__ void __launch_bounds__(256, 2) flash_fp16()
{
    extern __shared__ char fsm[];
    const uint32_t sb = smem_u32(fsm);

    const int tid  = threadIdx.x;
    const int warp = tid >> 5;
    const int lane = tid & 31;
    const int qt   = gridDim.y - 1 - blockIdx.y;   // big tiles first (global)
    const int q0   = qt * 128;
    const int bh   = blockIdx.x;

    const __half* Q = g_qh + (size_t)bh * TT * HS;
    const __half* K = g_kh + (size_t)bh * TT * HS;
    const __half* V = g_vt + (size_t)bh * HS * TT;

    const int lr = lane >> 2;
    const int lc = lane & 3;
    const int lrow = warp * 16 + lr;
    const int grow_a = q0 + lrow;
    const int grow_b = grow_a + 8;

    const int b_n  = ((lane >> 4) << 3) + (lane & 7);
    const int b_kh = (lane >> 3) & 1;
    const uint32_t boff = (uint32_t)(b_n * KVROWB + b_kh * 16);

    unsigned qh[4][4];
#pragma unroll
    for (int ks = 0; ks < 4; ks++) {
        const int kd = ks * 16 + lc * 2;
        const __half* qa = Q + (size_t)grow_a * HS;
        const __half* qb = Q + (size_t)grow_b * HS;
        qh[ks][0] = *(const unsigned*)(qa + kd);
        qh[ks][1] = *(const unsigned*)(qb + kd);
        qh[ks][2] = *(const unsigned*)(qa + kd + 8);
        qh[ks][3] = *(const unsigned*)(qb + kd + 8);
    }

    const int sj  = tid >> 3;
    const int sdq = (tid & 7) * 8;
    const uint32_t kdst0 = (uint32_t)(sj * KVROWB + sdq * 2);
    const uint32_t kdst1 = (uint32_t)((sj + 32) * KVROWB + sdq * 2);

#define FL_ISSUE(PAIR, S) do {                                           \
    uint32_t base_ = sb + (S) * FL_PRB;                                  \
    _Pragma("unroll")                                                    \
    for (int sub_ = 0; sub_ < 2; sub_++) {                               \
        const int k0_ = ((PAIR) * 2 + sub_) * 64;                        \
        uint32_t kb_ = base_ + sub_ * 2 * FL_TPL;                        \
        uint32_t vb_ = kb_ + FL_TPL;                                     \
        cpa16(kb_ + kdst0, K + (size_t)(k0_ + sj) * HS + sdq);           \
        cpa16(kb_ + kdst1, K + (size_t)(k0_ + sj + 32) * HS + sdq);      \
        cpa16(vb_ + kdst0, V + (size_t)sj * TT + k0_ + sdq);             \
        cpa16(vb_ + kdst1, V + (size_t)(sj + 32) * TT + k0_ + sdq);      \
    }                                                                    \
    CP_COMMIT();                                                         \
} while (0)

    float o[8][4];
#pragma unroll
    for (int nt = 0; nt < 8; nt++)
#pragma unroll
        for (int r = 0; r < 4; r++) o[nt][r] = 0.0f;
    float m_a = -1e30f, m_b = -1e30f, l_a = 0.0f, l_b = 0.0f;

    const int nkt = 2 * qt + 2;       // always even
    const int np  = nkt >> 1;
    FL_ISSUE(0, 0);
    if (np > 1) FL_ISSUE(1, 1);

    int stage = 0;
    for (int pp = 0; pp < np; pp++) {
        if (pp + 1 < np) CP_WAIT(1); else CP_WAIT(0);
        __syncthreads();

        if (pp + 2 < np) {
            int s2 = stage + 2; if (s2 >= 3) s2 -= 3;
            FL_ISSUE(pp + 2, s2);
        }

#pragma unroll
        for (int sub = 0; sub < 2; sub++) {
            const int kt = pp * 2 + sub;
            const uint32_t ktile = sb + stage * FL_PRB + sub * 2 * FL_TPL;
            const uint32_t vtile = ktile + FL_TPL;
            const int k0 = kt * 64;

            float p[8][4];
#pragma unroll
            for (int nt = 0; nt < 8; nt++)
#pragma unroll
                for (int r = 0; r < 4; r++) p[nt][r] = 0.0f;

#pragma unroll
            for (int ks = 0; ks < 4; ks++) {
#pragma unroll
                for (int ntp = 0; ntp < 4; ntp++) {
                    unsigned Bh[4];
                    ldsm4(Bh, ktile + boff + ntp * 16 * KVROWB + ks * 32);
                    mma_fp16(p[ntp * 2 + 0], qh[ks], Bh[0], Bh[1]);
                    mma_fp16(p[ntp * 2 + 1], qh[ks], Bh[2], Bh[3]);
                }
            }

            if (kt + 2 >= nkt) {
#pragma unroll
                for (int nt = 0; nt < 8; nt++) {
                    const int c = k0 + nt * 8 + lc * 2;
                    if (c     > grow_a) p[nt][0] = -1e30f;
                    if (c + 1 > grow_a) p[nt][1] = -1e30f;
                    if (c     > grow_b) p[nt][2] = -1e30f;
                    if (c + 1 > grow_b) p[nt][3] = -1e30f;
                }
            }

            float ma = -1e30f, mb2 = -1e30f;
#pragma unroll
            for (int nt = 0; nt < 8; nt++) {
                ma  = fmaxf(ma,  fmaxf(p[nt][0], p[nt][1]));
                mb2 = fmaxf(mb2, fmaxf(p[nt][2], p[nt][3]));
            }
            ma  = fmaxf(ma,  __shfl_xor_sync(0xffffffffu, ma, 1));
            ma  = fmaxf(ma,  __shfl_xor_sync(0xffffffffu, ma, 2));
            mb2 = fmaxf(mb2, __shfl_xor_sync(0xffffffffu, mb2, 1));
            mb2 = fmaxf(mb2, __shfl_xor_sync(0xffffffffu, mb2, 2));

            const float mna = fmaxf(m_a, ma);
            const float mnb = fmaxf(m_b, mb2);
            const float ca  = exp2f(m_a - mna);
            const float cbx = exp2f(m_b - mnb);

            float sa = 0.0f, sb2 = 0.0f;
#pragma unroll
            for (int nt = 0; nt < 8; nt++) {
                p[nt][0] = exp2f(p[nt][0] - mna);
                p[nt][1] = exp2f(p[nt][1] - mna);
                p[nt][2] = exp2f(p[nt][2] - mnb);
                p[nt][3] = exp2f(p[nt][3] - mnb);
                sa  += p[nt][0] + p[nt][1];
                sb2 += p[nt][2] + p[nt][3];
            }
            sa  += __shfl_xor_sync(0xffffffffu, sa, 1);
            sa  += __shfl_xor_sync(0xffffffffu, sa, 2);
            sb2 += __shfl_xor_sync(0xffffffffu, sb2, 1);
            sb2 += __shfl_xor_sync(0xffffffffu, sb2, 2);
            l_a = l_a * ca + sa;    m_a = mna;
            l_b = l_b * cbx + sb2;  m_b = mnb;

#pragma unroll
            for (int nt = 0; nt < 8; nt++) {
                o[nt][0] *= ca;  o[nt][1] *= ca;
                o[nt][2] *= cbx; o[nt][3] *= cbx;
            }

            unsigned pa[4][4];
#pragma unroll
            for (int g = 0; g < 4; g++) {
                pa[g][0] = pkh2f(p[2*g][0],   p[2*g][1]);
                pa[g][1] = pkh2f(p[2*g][2],   p[2*g][3]);
                pa[g][2] = pkh2f(p[2*g+1][0], p[2*g+1][1]);
                pa[g][3] = pkh2f(p[2*g+1][2], p[2*g+1][3]);
            }

#pragma unroll
            for (int g = 0; g < 4; g++) {
#pragma unroll
                for (int ntp = 0; ntp < 4; ntp++) {
                    unsigned Bv[4];
                    ldsm4(Bv, vtile + boff + ntp * 16 * KVROWB + g * 32);
                    mma_fp16(o[ntp * 2 + 0], pa[g], Bv[0], Bv[1]);
                    mma_fp16(o[ntp * 2 + 1], pa[g], Bv[2], Bv[3]);
                }
            }
        }
        if (++stage == 3) stage = 0;
    }
#undef FL_ISSUE

    const float rla = __fdividef(1.0f, l_a);
    const float rlb = __fdividef(1.0f, l_b);
    const int b = bh >> 4;
    const int h = bh & 15;
    size_t oa = ((size_t)b * TT + grow_a) * CEMB + h * HS;
    size_t ob = ((size_t)b * TT + grow_b) * CEMB + h * HS;
#pragma unroll
    for (int nt = 0; nt < 8; nt++) {
        const int col = nt * 8 + lc * 2;
        *(unsigned*)(g_att + oa + col) = pkh2f(o[nt][0] * rla, o[nt][1] * rla);
        *(unsigned*)(g_att + ob + col) = pkh2f(o[nt][2] * rlb, o[nt][3] * rlb);
    }
}

// ---------------------------------------------------------------------------
extern "C" void kernel_launch(void* const* d_in, const int* in_sizes, int n_in,
                              void* d_out, int out_size)
{
    (void)in_sizes; (void)n_in; (void)out_size;
    const float* x  = (const float*)d_in[0];
    const float* Wq = (const float*)d_in[1];
    const float* Wk = (const float*)d_in[2];
    const float* Wv = (const float*)d_in[3];
    const float* Wp = (const float*)d_in[4];
    const float* bp = (const float*)d_in[5];
    float* out = (float*)d_out;

    cudaFuncSetAttribute(qkv_gemm,
        cudaFuncAttributeMaxDynamicSharedMemorySize, GM1_SMEM);
    cudaFuncSetAttribute(proj_gemm,
        cudaFuncAttributeMaxDynamicSharedMemorySize, GM1_SMEM);
    cudaFuncSetAttribute(flash_fp16,
        cudaFuncAttributeMaxDynamicSharedMemorySize, FL_SMEM);

    prep_all<<<12544, 256>>>(x, Wq, Wk, Wv, Wp);

    qkv_gemm<<<dim3(CEMB / 128, MTOT / 128, 3), 256, GM1_SMEM>>>();

    flash_fp16<<<dim3(BB * NHEAD, TT / 128), 256, FL_SMEM>>>();

    proj_gemm<<<dim3(CEMB / 128, MTOT / 128), 256, GM1_SMEM>>>(bp, out);
}